// round 5
// baseline (speedup 1.0000x reference)
#include <cuda_runtime.h>
#include <math.h>

#define MTOT 8192      // n * T = 4 * 2048
#define DIM 1024
#define FFD 4096
#define TT 2048
#define NBATCH 4
#define NHEAD 16
#define HDIM 64

// ---------------- scratch (no allocs allowed) ----------------
__device__ float g_X [MTOT * DIM];   // concat(kq, v), tf32-rounded
__device__ float g_K [MTOT * DIM];
__device__ float g_Q [MTOT * DIM];
__device__ float g_V [MTOT * DIM];
__device__ float g_AO[MTOT * DIM];   // attention output
__device__ float g_H [MTOT * DIM];   // after LN1 (tf32-rounded)
__device__ float g_G [MTOT * FFD];   // gelu(h W1^T + b1) (tf32-rounded)
__device__ float g_F [MTOT * DIM];   // ffn output
__device__ float g_Wc[3 * DIM * DIM + 2 * FFD * DIM];  // tf32-rounded weights

// ---------------- helpers ----------------
__device__ __forceinline__ unsigned cvt_tf32(float f) {
    unsigned r;
    asm("cvt.rna.tf32.f32 %0, %1;" : "=r"(r) : "f"(f));
    return r;
}
__device__ __forceinline__ float tf32f(float f) { return __uint_as_float(cvt_tf32(f)); }

__device__ __forceinline__ void mma8(float* c, const unsigned* a, const unsigned* b) {
    asm volatile(
        "mma.sync.aligned.m16n8k8.row.col.f32.tf32.tf32.f32 "
        "{%0,%1,%2,%3}, {%4,%5,%6,%7}, {%8,%9}, {%0,%1,%2,%3};\n"
        : "+f"(c[0]), "+f"(c[1]), "+f"(c[2]), "+f"(c[3])
        : "r"(a[0]), "r"(a[1]), "r"(a[2]), "r"(a[3]), "r"(b[0]), "r"(b[1]));
}

// ---------------- concat (writes tf32-rounded) ----------------
__global__ void concat_kernel(const float* __restrict__ kq, const float* __restrict__ v) {
    int i = blockIdx.x * blockDim.x + threadIdx.x;
    int m = i >> 10;
    int j = i & 1023;
    float x = (j < 512) ? kq[m * 512 + j] : v[m * 512 + (j - 512)];
    g_X[i] = tf32f(x);
}

// ---------------- weight rounding ----------------
__global__ void cvt_kernel(const float* __restrict__ src, float* __restrict__ dst, int n) {
    int i = blockIdx.x * blockDim.x + threadIdx.x;
    if (i < n) dst[i] = tf32f(src[i]);
}

// ---------------- tf32 tensor-core GEMM ----------------
// C[M,N] = A[M,K]*B[N,K]^T + bias (+GELU, +ROUND). Inputs must be tf32-representable.
// Block tile 128x128x16, 4 warps (2x2), warp tile 64x64, 2 CTAs/SM.
// Quad-packed smem: float4 per fragment = {(r+g,tg),(r+g,tg+4),(r+8+g,tg),(r+8+g,tg+4)},
// slot = (g + 2*tg) & 7 -> conflict-free LDS.128 / STS.64.
// Stage: A 512 float4 (2ks x 4tg x 8mb x 8) + B 512 float4 = 1024 float4 = 16KB; 2 stages.
#define GSMEM 32768

template<int GELU, int ROUND>
__global__ void __launch_bounds__(128, 2) gemm_mma(
    const float* __restrict__ A, const float* __restrict__ B,
    const float* __restrict__ bias, float* __restrict__ C,
    int N, int K)
{
    extern __shared__ float4 s4[];   // [2][1024]

    const int tid  = threadIdx.x;
    const int lane = tid & 31;
    const int warp = tid >> 5;
    const int g    = lane >> 2;
    const int tg   = lane & 3;
    const int wm   = (warp & 1) * 64;
    const int wn   = (warp >> 1) * 64;
    const int bm   = blockIdx.y * 128;
    const int bn   = blockIdx.x * 128;
    const int sgc  = (g + 2 * tg) & 7;

    // producer: thread t loads A row t and B row t (16 k's each)
    const int row = tid;
    const float* Ap = A + (size_t)(bm + row) * K;
    const float* Bp = B + (size_t)(bn + row) * K;
    const int mbs = row >> 4, rg = row & 7, half = (row >> 3) & 1;

    float acc[4][8][4];
#pragma unroll
    for (int i = 0; i < 4; i++)
#pragma unroll
        for (int j = 0; j < 8; j++)
#pragma unroll
            for (int q = 0; q < 4; q++) acc[i][j][q] = 0.f;

    float ra[16], rb[16];
#pragma unroll
    for (int c = 0; c < 4; c++) {
        *(float4*)&ra[c * 4] = *(const float4*)(Ap + c * 4);
        *(float4*)&rb[c * 4] = *(const float4*)(Bp + c * 4);
    }

    // store stage 0 (pure copy — inputs already tf32-rounded)
    {
        float2* s2 = (float2*)s4;
#pragma unroll
        for (int ks = 0; ks < 2; ks++)
#pragma unroll
            for (int p = 0; p < 4; p++) {
                int slot = (rg + 2 * p) & 7;
                int ai = ks * 256 + p * 64 + mbs * 8 + slot;
                s2[ai * 2 + half] = make_float2(ra[ks * 8 + p], ra[ks * 8 + p + 4]);
                s2[(512 + ai) * 2 + half] = make_float2(rb[ks * 8 + p], rb[ks * 8 + p + 4]);
            }
    }
    __syncthreads();

    int buf = 0;
    for (int k0 = 0; k0 < K; k0 += 16) {
        const bool more = (k0 + 16 < K);
        if (more) {
#pragma unroll
            for (int c = 0; c < 4; c++) {
                *(float4*)&ra[c * 4] = *(const float4*)(Ap + k0 + 16 + c * 4);
                *(float4*)&rb[c * 4] = *(const float4*)(Bp + k0 + 16 + c * 4);
            }
        }

        const float4* sa = s4 + buf * 1024;
        const float4* sb = sa + 512;
#pragma unroll
        for (int ks = 0; ks < 2; ks++) {
            unsigned af[4][4], bf[8][2];
#pragma unroll
            for (int mi = 0; mi < 4; mi++) {
                float4 a4 = sa[ks * 256 + tg * 64 + ((wm >> 4) + mi) * 8 + sgc];
                af[mi][0] = __float_as_uint(a4.x);
                af[mi][1] = __float_as_uint(a4.z);
                af[mi][2] = __float_as_uint(a4.y);
                af[mi][3] = __float_as_uint(a4.w);
            }
#pragma unroll
            for (int j = 0; j < 4; j++) {
                float4 b4 = sb[ks * 256 + tg * 64 + ((wn >> 4) + j) * 8 + sgc];
                bf[2 * j][0]     = __float_as_uint(b4.x);
                bf[2 * j][1]     = __float_as_uint(b4.y);
                bf[2 * j + 1][0] = __float_as_uint(b4.z);
                bf[2 * j + 1][1] = __float_as_uint(b4.w);
            }
#pragma unroll
            for (int mi = 0; mi < 4; mi++)
#pragma unroll
                for (int ni = 0; ni < 8; ni++)
                    mma8(acc[mi][ni], af[mi], bf[ni]);
        }

        if (more) {
            float2* s2 = (float2*)(s4 + (buf ^ 1) * 1024);
#pragma unroll
            for (int ks = 0; ks < 2; ks++)
#pragma unroll
                for (int p = 0; p < 4; p++) {
                    int slot = (rg + 2 * p) & 7;
                    int ai = ks * 256 + p * 64 + mbs * 8 + slot;
                    s2[ai * 2 + half] = make_float2(ra[ks * 8 + p], ra[ks * 8 + p + 4]);
                    s2[(512 + ai) * 2 + half] = make_float2(rb[ks * 8 + p], rb[ks * 8 + p + 4]);
                }
        }
        __syncthreads();
        buf ^= 1;
    }

    // epilogue
#pragma unroll
    for (int ni = 0; ni < 8; ni++) {
        int n = bn + wn + ni * 8 + tg * 2;
        float b0 = bias[n], b1 = bias[n + 1];
#pragma unroll
        for (int mi = 0; mi < 4; mi++) {
            int m = bm + wm + mi * 16 + g;
            float v00 = acc[mi][ni][0] + b0;
            float v01 = acc[mi][ni][1] + b1;
            float v10 = acc[mi][ni][2] + b0;
            float v11 = acc[mi][ni][3] + b1;
            if (GELU) {
                v00 = 0.5f * v00 * (1.f + erff(v00 * 0.7071067811865476f));
                v01 = 0.5f * v01 * (1.f + erff(v01 * 0.7071067811865476f));
                v10 = 0.5f * v10 * (1.f + erff(v10 * 0.7071067811865476f));
                v11 = 0.5f * v11 * (1.f + erff(v11 * 0.7071067811865476f));
            }
            if (ROUND) {
                v00 = tf32f(v00); v01 = tf32f(v01);
                v10 = tf32f(v10); v11 = tf32f(v11);
            }
            *(float2*)&C[(size_t)m * N + n] = make_float2(v00, v01);
            *(float2*)&C[(size_t)(m + 8) * N + n] = make_float2(v10, v11);
        }
    }
}

// ---------------- attention: tf32 mma flash, causal, no scale ----------------
#define QPLN 68           // float2 per plane row (64 + 4 pad)
#define PSTR 72           // P row stride in floats
#define SMEM_ATTN (13312 * 4)

__global__ void __launch_bounds__(128, 3) attn_mma(
    const float* __restrict__ Qg, const float* __restrict__ Kg,
    const float* __restrict__ Vg, float* __restrict__ AO)
{
    extern __shared__ float sm[];
    float2* Kp  = (float2*)sm;
    float*  Vf  = sm + 4352;
    float2* Vp  = (float2*)Vf;
    float2* Qp2 = (float2*)(sm + 8704);
    float*  Ps  = sm + 8704;

    const int qb = blockIdx.x, h = blockIdx.y, b = blockIdx.z;
    const int tid = threadIdx.x;
    const int warp = tid >> 5, lane = tid & 31;
    const int g = lane >> 2, tg = lane & 3;
    const int qw0 = warp * 16;
    const size_t base = ((size_t)b * TT) * DIM + (size_t)h * HDIM;
    const int q0 = qb * 64;

    for (int t = tid; t < 512; t += 128) {
        int row = t & 63, ks = t >> 6;
        const float* src = Qg + base + (size_t)(q0 + row) * DIM + ks * 8;
        float4 v0 = *(const float4*)src, v1 = *(const float4*)(src + 4);
        float a[8] = {v0.x, v0.y, v0.z, v0.w, v1.x, v1.y, v1.z, v1.w};
#pragma unroll
        for (int p = 0; p < 4; p++)
            Qp2[(ks * 4 + p) * QPLN + row] = make_float2(tf32f(a[p]), tf32f(a[p + 4]));
    }
    __syncthreads();

    unsigned qf[8][4];
#pragma unroll
    for (int ks = 0; ks < 8; ks++) {
        float2 lo = Qp2[(ks * 4 + tg) * QPLN + qw0 + g];
        float2 hi = Qp2[(ks * 4 + tg) * QPLN + qw0 + g + 8];
        qf[ks][0] = __float_as_uint(lo.x);
        qf[ks][1] = __float_as_uint(hi.x);
        qf[ks][2] = __float_as_uint(lo.y);
        qf[ks][3] = __float_as_uint(hi.y);
    }

    float o[8][4];
#pragma unroll
    for (int ni = 0; ni < 8; ni++)
#pragma unroll
        for (int q = 0; q < 4; q++) o[ni][q] = 0.f;
    float m0 = -INFINITY, m1 = -INFINITY, l0 = 0.f, l1 = 0.f;

    for (int jb = 0; jb <= qb; jb++) {
        __syncthreads();
        const int k0 = jb * 64;
        for (int t = tid; t < 512; t += 128) {
            int row = t & 63, ks = t >> 6;
            const float* src = Kg + base + (size_t)(k0 + row) * DIM + ks * 8;
            float4 v0 = *(const float4*)src, v1 = *(const float4*)(src + 4);
            float a[8] = {v0.x, v0.y, v0.z, v0.w, v1.x, v1.y, v1.z, v1.w};
#pragma unroll
            for (int p = 0; p < 4; p++)
                Kp[(ks * 4 + p) * QPLN + row] = make_float2(tf32f(a[p]), tf32f(a[p + 4]));
        }
        for (int t = tid; t < 512; t += 128) {
            int row = t & 63, ch = t >> 6;
            const float* src = Vg + base + (size_t)(k0 + row) * DIM + ch * 8;
            float4 v0 = *(const float4*)src, v1 = *(const float4*)(src + 4);
            float a[8] = {v0.x, v0.y, v0.z, v0.w, v1.x, v1.y, v1.z, v1.w};
            int plane = (row >> 3) * 4 + (row & 3);
            int slot = (row & 4) >> 2;
            float* dst = Vf + plane * 136 + slot;
#pragma unroll
            for (int e = 0; e < 8; e++)
                dst[(ch * 8 + e) * 2] = tf32f(a[e]);
        }
        __syncthreads();

        float s[8][4];
#pragma unroll
        for (int ni = 0; ni < 8; ni++)
#pragma unroll
            for (int q = 0; q < 4; q++) s[ni][q] = 0.f;
#pragma unroll
        for (int ks = 0; ks < 8; ks++) {
#pragma unroll
            for (int ni = 0; ni < 8; ni++) {
                float2 kb = Kp[(ks * 4 + tg) * QPLN + ni * 8 + g];
                unsigned bf[2] = {__float_as_uint(kb.x), __float_as_uint(kb.y)};
                mma8(s[ni], qf[ks], bf);
            }
        }

        if (jb == qb) {
#pragma unroll
            for (int ni = 0; ni < 8; ni++) {
                int c = ni * 8 + 2 * tg;
                if (c     > qw0 + g)     s[ni][0] = -INFINITY;
                if (c + 1 > qw0 + g)     s[ni][1] = -INFINITY;
                if (c     > qw0 + g + 8) s[ni][2] = -INFINITY;
                if (c + 1 > qw0 + g + 8) s[ni][3] = -INFINITY;
            }
        }

        float rx0 = -INFINITY, rx1 = -INFINITY;
#pragma unroll
        for (int ni = 0; ni < 8; ni++) {
            rx0 = fmaxf(rx0, fmaxf(s[ni][0], s[ni][1]));
            rx1 = fmaxf(rx1, fmaxf(s[ni][2], s[ni][3]));
        }
        rx0 = fmaxf(rx0, __shfl_xor_sync(0xffffffffu, rx0, 1));
        rx0 = fmaxf(rx0, __shfl_xor_sync(0xffffffffu, rx0, 2));
        rx1 = fmaxf(rx1, __shfl_xor_sync(0xffffffffu, rx1, 1));
        rx1 = fmaxf(rx1, __shfl_xor_sync(0xffffffffu, rx1, 2));

        float mn0 = fmaxf(m0, rx0), mn1 = fmaxf(m1, rx1);
        float al0 = __expf(m0 - mn0), al1 = __expf(m1 - mn1);
        float ps0 = 0.f, ps1 = 0.f;
#pragma unroll
        for (int ni = 0; ni < 8; ni++) {
            float p0 = tf32f(__expf(s[ni][0] - mn0));
            float p1 = tf32f(__expf(s[ni][1] - mn0));
            float p2 = tf32f(__expf(s[ni][2] - mn1));
            float p3 = tf32f(__expf(s[ni][3] - mn1));
            s[ni][0] = p0; s[ni][1] = p1; s[ni][2] = p2; s[ni][3] = p3;
            ps0 += p0 + p1;
            ps1 += p2 + p3;
        }
        ps0 += __shfl_xor_sync(0xffffffffu, ps0, 1);
        ps0 += __shfl_xor_sync(0xffffffffu, ps0, 2);
        ps1 += __shfl_xor_sync(0xffffffffu, ps1, 1);
        ps1 += __shfl_xor_sync(0xffffffffu, ps1, 2);
        l0 = l0 * al0 + ps0;
        l1 = l1 * al1 + ps1;
        m0 = mn0; m1 = mn1;
#pragma unroll
        for (int ni = 0; ni < 8; ni++) {
            o[ni][0] *= al0; o[ni][1] *= al0;
            o[ni][2] *= al1; o[ni][3] *= al1;
        }

#pragma unroll
        for (int ni = 0; ni < 8; ni++) {
            *(float2*)&Ps[(qw0 + g)     * PSTR + ni * 8 + 2 * tg] = make_float2(s[ni][0], s[ni][1]);
            *(float2*)&Ps[(qw0 + g + 8) * PSTR + ni * 8 + 2 * tg] = make_float2(s[ni][2], s[ni][3]);
        }
        __syncwarp();

#pragma unroll
        for (int ks = 0; ks < 8; ks++) {
            unsigned pf[4];
            pf[0] = __float_as_uint(Ps[(qw0 + g)     * PSTR + ks * 8 + tg]);
            pf[1] = __float_as_uint(Ps[(qw0 + g + 8) * PSTR + ks * 8 + tg]);
            pf[2] = __float_as_uint(Ps[(qw0 + g)     * PSTR + ks * 8 + tg + 4]);
            pf[3] = __float_as_uint(Ps[(qw0 + g + 8) * PSTR + ks * 8 + tg + 4]);
#pragma unroll
            for (int ni = 0; ni < 8; ni++) {
                float2 vb = Vp[(ks * 4 + tg) * QPLN + ni * 8 + g];
                unsigned bf[2] = {__float_as_uint(vb.x), __float_as_uint(vb.y)};
                mma8(o[ni], pf, bf);
            }
        }
    }

    float i0 = 1.f / l0, i1 = 1.f / l1;
#pragma unroll
    for (int ni = 0; ni < 8; ni++) {
        size_t r0 = base + (size_t)(q0 + qw0 + g) * DIM + ni * 8 + 2 * tg;
        size_t r1 = base + (size_t)(q0 + qw0 + g + 8) * DIM + ni * 8 + 2 * tg;
        *(float2*)&AO[r0] = make_float2(o[ni][0] * i0, o[ni][1] * i0);
        *(float2*)&AO[r1] = make_float2(o[ni][2] * i1, o[ni][3] * i1);
    }
}

// ---------------- fused add + LayerNorm (row = 1024) ----------------
template<int ROUND>
__global__ void __launch_bounds__(256) add_ln_kernel(
    const float* __restrict__ A, const float* __restrict__ B,
    const float* __restrict__ g, const float* __restrict__ beta,
    float* __restrict__ out)
{
    const int row = blockIdx.x;
    const float* a = A + (size_t)row * DIM;
    const float* b = B + (size_t)row * DIM;
    const int tid = threadIdx.x;

    float x[4];
    float s = 0.f, s2 = 0.f;
#pragma unroll
    for (int i = 0; i < 4; i++) {
        int c = tid + i * 256;
        x[i] = a[c] + b[c];
        s += x[i];
        s2 += x[i] * x[i];
    }
#pragma unroll
    for (int off = 16; off; off >>= 1) {
        s  += __shfl_down_sync(0xffffffffu, s,  off);
        s2 += __shfl_down_sync(0xffffffffu, s2, off);
    }
    __shared__ float ss[8], ss2[8];
    __shared__ float s_mean, s_inv;
    int w = tid >> 5;
    if ((tid & 31) == 0) { ss[w] = s; ss2[w] = s2; }
    __syncthreads();
    if (tid == 0) {
        float S = 0.f, S2 = 0.f;
#pragma unroll
        for (int i = 0; i < 8; i++) { S += ss[i]; S2 += ss2[i]; }
        float mu = S * (1.f / DIM);
        float var = S2 * (1.f / DIM) - mu * mu;
        s_mean = mu;
        s_inv = rsqrtf(var + 1e-5f);
    }
    __syncthreads();
    float mu = s_mean, iv = s_inv;
#pragma unroll
    for (int i = 0; i < 4; i++) {
        int c = tid + i * 256;
        float v = (x[i] - mu) * iv * g[c] + beta[c];
        if (ROUND) v = tf32f(v);
        out[(size_t)row * DIM + c] = v;
    }
}

// ---------------- host ----------------
extern "C" void kernel_launch(void* const* d_in, const int* in_sizes, int n_in,
                              void* d_out, int out_size)
{
    const float* kq  = (const float*)d_in[0];
    const float* v   = (const float*)d_in[1];
    const float* Wk  = (const float*)d_in[2];
    const float* bk  = (const float*)d_in[3];
    const float* Wq  = (const float*)d_in[4];
    const float* bq  = (const float*)d_in[5];
    const float* Wv  = (const float*)d_in[6];
    const float* bv  = (const float*)d_in[7];
    const float* W1  = (const float*)d_in[8];
    const float* b1  = (const float*)d_in[9];
    const float* W2  = (const float*)d_in[10];
    const float* b2  = (const float*)d_in[11];
    const float* g1  = (const float*)d_in[12];
    const float* be1 = (const float*)d_in[13];
    const float* g2  = (const float*)d_in[14];
    const float* be2 = (const float*)d_in[15];
    float* out = (float*)d_out;

    float *X, *Kb, *Qb, *Vb, *AO, *Hh, *G, *F, *Wc;
    cudaGetSymbolAddress((void**)&X,  g_X);
    cudaGetSymbolAddress((void**)&Kb, g_K);
    cudaGetSymbolAddress((void**)&Qb, g_Q);
    cudaGetSymbolAddress((void**)&Vb, g_V);
    cudaGetSymbolAddress((void**)&AO, g_AO);
    cudaGetSymbolAddress((void**)&Hh, g_H);
    cudaGetSymbolAddress((void**)&G,  g_G);
    cudaGetSymbolAddress((void**)&F,  g_F);
    cudaGetSymbolAddress((void**)&Wc, g_Wc);

    float* cWk = Wc;
    float* cWq = Wc + 1 * DIM * DIM;
    float* cWv = Wc + 2 * DIM * DIM;
    float* cW1 = Wc + 3 * DIM * DIM;
    float* cW2 = Wc + 3 * DIM * DIM + FFD * DIM;

    cudaFuncSetAttribute(gemm_mma<0, 0>, cudaFuncAttributeMaxDynamicSharedMemorySize, GSMEM);
    cudaFuncSetAttribute(gemm_mma<1, 1>, cudaFuncAttributeMaxDynamicSharedMemorySize, GSMEM);
    cudaFuncSetAttribute(attn_mma, cudaFuncAttributeMaxDynamicSharedMemorySize, SMEM_ATTN);

    concat_kernel<<<(MTOT * DIM) / 256, 256>>>(kq, v);
    cvt_kernel<<<(DIM * DIM) / 256, 256>>>(Wk, cWk, DIM * DIM);
    cvt_kernel<<<(DIM * DIM) / 256, 256>>>(Wq, cWq, DIM * DIM);
    cvt_kernel<<<(DIM * DIM) / 256, 256>>>(Wv, cWv, DIM * DIM);
    cvt_kernel<<<(FFD * DIM) / 256, 256>>>(W1, cW1, FFD * DIM);
    cvt_kernel<<<(FFD * DIM) / 256, 256>>>(W2, cW2, FFD * DIM);

    dim3 gqkv(DIM / 128, MTOT / 128);
    gemm_mma<0, 0><<<gqkv, 128, GSMEM>>>(X, cWk, bk, Kb, DIM, DIM);
    gemm_mma<0, 0><<<gqkv, 128, GSMEM>>>(X, cWq, bq, Qb, DIM, DIM);
    gemm_mma<0, 0><<<gqkv, 128, GSMEM>>>(X, cWv, bv, Vb, DIM, DIM);

    attn_mma<<<dim3(TT / 64, NHEAD, NBATCH), 128, SMEM_ATTN>>>(Qb, Kb, Vb, AO);

    add_ln_kernel<1><<<MTOT, 256>>>(Vb, AO, g1, be1, Hh);

    gemm_mma<1, 1><<<dim3(FFD / 128, MTOT / 128), 128, GSMEM>>>(Hh, cW1, b1, G, FFD, DIM);
    gemm_mma<0, 0><<<dim3(DIM / 128, MTOT / 128), 128, GSMEM>>>(G, cW2, b2, F, DIM, FFD);

    add_ln_kernel<0><<<MTOT, 256>>>(Hh, F, g2, be2, out);
}

// round 8
// speedup vs baseline: 1.0599x; 1.0599x over previous
#include <cuda_runtime.h>
#include <math.h>

#define MTOT 8192      // n * T = 4 * 2048
#define DIM 1024
#define FFD 4096
#define TT 2048
#define NBATCH 4
#define NHEAD 16
#define HDIM 64

// ---------------- scratch (no allocs allowed) ----------------
__device__ float g_X [MTOT * DIM];   // concat(kq, v), tf32-rounded
__device__ float g_K [MTOT * DIM];
__device__ float g_Q [MTOT * DIM];
__device__ float g_V [MTOT * DIM];
__device__ float g_AO[MTOT * DIM];   // attention output
__device__ float g_H [MTOT * DIM];   // after LN1 (tf32-rounded)
__device__ float g_G [MTOT * FFD];   // gelu(h W1^T + b1) (tf32-rounded)
__device__ float g_F [MTOT * DIM];   // ffn output
__device__ float g_Wc[3 * DIM * DIM + 2 * FFD * DIM];  // tf32-rounded weights

// ---------------- helpers ----------------
__device__ __forceinline__ unsigned cvt_tf32(float f) {
    unsigned r;
    asm("cvt.rna.tf32.f32 %0, %1;" : "=r"(r) : "f"(f));
    return r;
}
__device__ __forceinline__ float tf32f(float f) { return __uint_as_float(cvt_tf32(f)); }

__device__ __forceinline__ void mma8(float* c, const unsigned* a, const unsigned* b) {
    asm volatile(
        "mma.sync.aligned.m16n8k8.row.col.f32.tf32.tf32.f32 "
        "{%0,%1,%2,%3}, {%4,%5,%6,%7}, {%8,%9}, {%0,%1,%2,%3};\n"
        : "+f"(c[0]), "+f"(c[1]), "+f"(c[2]), "+f"(c[3])
        : "r"(a[0]), "r"(a[1]), "r"(a[2]), "r"(a[3]), "r"(b[0]), "r"(b[1]));
}

// ---------------- concat (writes tf32-rounded) ----------------
__global__ void concat_kernel(const float* __restrict__ kq, const float* __restrict__ v) {
    int i = blockIdx.x * blockDim.x + threadIdx.x;
    int m = i >> 10;
    int j = i & 1023;
    float x = (j < 512) ? kq[m * 512 + j] : v[m * 512 + (j - 512)];
    g_X[i] = tf32f(x);
}

// ---------------- weight rounding ----------------
__global__ void cvt_kernel(const float* __restrict__ src, float* __restrict__ dst, int n) {
    int i = blockIdx.x * blockDim.x + threadIdx.x;
    if (i < n) dst[i] = tf32f(src[i]);
}

// ---------------- tf32 tensor-core GEMM ----------------
// C[M,N] = A[M,K]*B[N,K]^T + bias (+GELU, +ROUND). Inputs must be tf32-representable.
// Block tile 256x128x16, 8 warps (4 M x 2 N), warp tile 64x64, mma.m16n8k8.tf32.
// Quad-packed smem: one float4 per fragment = {(r+g,tg),(r+g,tg+4),(r+8+g,tg),(r+8+g,tg+4)}
// slot index within 8-slot group = (g + 2*tg) & 7 -> conflict-free LDS.128 and STS.64.
// A region: 1024 float4 (2ks x 4tg x 16 mblk x 8), B region: 512 float4.
#define GSTG 1536      // float4 per stage (A 1024 + B 512)

template<int GELU, int ROUND>
__global__ void __launch_bounds__(256, 1) gemm_mma(
    const float* __restrict__ A, const float* __restrict__ B,
    const float* __restrict__ bias, float* __restrict__ C,
    int N, int K)
{
    extern __shared__ float4 s4[];   // [2][GSTG]

    const int tid  = threadIdx.x;
    const int lane = tid & 31;
    const int warp = tid >> 5;
    const int g    = lane >> 2;
    const int tg   = lane & 3;
    const int wm   = (warp & 3) * 64;
    const int wn   = (warp >> 2) * 64;
    const int bm   = blockIdx.y * 256;
    const int bn   = blockIdx.x * 128;
    const int sgc  = (g + 2 * tg) & 7;

    // producer mapping: A row = tid (16 k's), B row = tid&127 at kstep tid>>7 (8 k's)
    const int arow = tid;
    const int brow = tid & 127;
    const int bks  = tid >> 7;
    const float* Ap = A + (size_t)(bm + arow) * K;
    const float* Bp = B + (size_t)(bn + brow) * K + bks * 8;

    const int amb = arow >> 4, ag = arow & 7, ah = (arow >> 3) & 1;
    const int bnb = brow >> 4, bg = brow & 7, bh = (brow >> 3) & 1;

    float acc[4][8][4];
#pragma unroll
    for (int i = 0; i < 4; i++)
#pragma unroll
        for (int j = 0; j < 8; j++)
#pragma unroll
            for (int q = 0; q < 4; q++) acc[i][j][q] = 0.f;

    float ra[16], rb[8];
#pragma unroll
    for (int c = 0; c < 4; c++)
        *(float4*)&ra[c * 4] = *(const float4*)(Ap + c * 4);
    *(float4*)&rb[0] = *(const float4*)(Bp);
    *(float4*)&rb[4] = *(const float4*)(Bp + 4);

    // store stage 0 (pure copy — inputs already tf32-representable)
    {
        float2* s2 = (float2*)(s4);
#pragma unroll
        for (int ks = 0; ks < 2; ks++)
#pragma unroll
            for (int p = 0; p < 4; p++) {
                int idx = ks * 512 + p * 128 + amb * 8 + ((ag + 2 * p) & 7);
                s2[idx * 2 + ah] = make_float2(ra[ks * 8 + p], ra[ks * 8 + p + 4]);
            }
#pragma unroll
        for (int p = 0; p < 4; p++) {
            int idx = 1024 + bks * 256 + p * 64 + bnb * 8 + ((bg + 2 * p) & 7);
            s2[idx * 2 + bh] = make_float2(rb[p], rb[p + 4]);
        }
    }
    __syncthreads();

    int buf = 0;
    for (int k0 = 0; k0 < K; k0 += 16) {
        const bool more = (k0 + 16 < K);
        if (more) {
            const float* ap = Ap + k0 + 16;
#pragma unroll
            for (int c = 0; c < 4; c++)
                *(float4*)&ra[c * 4] = *(const float4*)(ap + c * 4);
            *(float4*)&rb[0] = *(const float4*)(Bp + k0 + 16);
            *(float4*)&rb[4] = *(const float4*)(Bp + k0 + 20);
        }

        const float4* sa = s4 + buf * GSTG;
        const float4* sb = sa + 1024;
#pragma unroll
        for (int ks = 0; ks < 2; ks++) {
            unsigned af[4][4], bf[8][2];
#pragma unroll
            for (int mi = 0; mi < 4; mi++) {
                float4 a4 = sa[ks * 512 + tg * 128 + ((wm >> 4) + mi) * 8 + sgc];
                af[mi][0] = __float_as_uint(a4.x);
                af[mi][1] = __float_as_uint(a4.z);
                af[mi][2] = __float_as_uint(a4.y);
                af[mi][3] = __float_as_uint(a4.w);
            }
#pragma unroll
            for (int j = 0; j < 4; j++) {
                float4 b4 = sb[ks * 256 + tg * 64 + ((wn >> 4) + j) * 8 + sgc];
                bf[2 * j][0]     = __float_as_uint(b4.x);
                bf[2 * j][1]     = __float_as_uint(b4.y);
                bf[2 * j + 1][0] = __float_as_uint(b4.z);
                bf[2 * j + 1][1] = __float_as_uint(b4.w);
            }
#pragma unroll
            for (int mi = 0; mi < 4; mi++)
#pragma unroll
                for (int ni = 0; ni < 8; ni++)
                    mma8(acc[mi][ni], af[mi], bf[ni]);
        }

        if (more) {
            float2* s2 = (float2*)(s4 + (buf ^ 1) * GSTG);
#pragma unroll
            for (int ks = 0; ks < 2; ks++)
#pragma unroll
                for (int p = 0; p < 4; p++) {
                    int idx = ks * 512 + p * 128 + amb * 8 + ((ag + 2 * p) & 7);
                    s2[idx * 2 + ah] = make_float2(ra[ks * 8 + p], ra[ks * 8 + p + 4]);
                }
#pragma unroll
            for (int p = 0; p < 4; p++) {
                int idx = 1024 + bks * 256 + p * 64 + bnb * 8 + ((bg + 2 * p) & 7);
                s2[idx * 2 + bh] = make_float2(rb[p], rb[p + 4]);
            }
        }
        __syncthreads();
        buf ^= 1;
    }

    // epilogue
#pragma unroll
    for (int ni = 0; ni < 8; ni++) {
        int n = bn + wn + ni * 8 + tg * 2;
        float b0 = bias[n], b1 = bias[n + 1];
#pragma unroll
        for (int mi = 0; mi < 4; mi++) {
            int m = bm + wm + mi * 16 + g;
            float v00 = acc[mi][ni][0] + b0;
            float v01 = acc[mi][ni][1] + b1;
            float v10 = acc[mi][ni][2] + b0;
            float v11 = acc[mi][ni][3] + b1;
            if (GELU) {
                v00 = 0.5f * v00 * (1.f + erff(v00 * 0.7071067811865476f));
                v01 = 0.5f * v01 * (1.f + erff(v01 * 0.7071067811865476f));
                v10 = 0.5f * v10 * (1.f + erff(v10 * 0.7071067811865476f));
                v11 = 0.5f * v11 * (1.f + erff(v11 * 0.7071067811865476f));
            }
            if (ROUND) {
                v00 = tf32f(v00); v01 = tf32f(v01);
                v10 = tf32f(v10); v11 = tf32f(v11);
            }
            *(float2*)&C[(size_t)m * N + n] = make_float2(v00, v01);
            *(float2*)&C[(size_t)(m + 8) * N + n] = make_float2(v10, v11);
        }
    }
}

// ---------------- attention: tf32 mma flash, causal, no scale ----------------
#define QPLN 68           // float2 per plane row (64 + 4 pad)
#define PSTR 72           // P row stride in floats
#define SMEM_ATTN (13312 * 4)

__global__ void __launch_bounds__(128, 3) attn_mma(
    const float* __restrict__ Qg, const float* __restrict__ Kg,
    const float* __restrict__ Vg, float* __restrict__ AO)
{
    extern __shared__ float sm[];
    float2* Kp  = (float2*)sm;
    float*  Vf  = sm + 4352;
    float2* Vp  = (float2*)Vf;
    float2* Qp2 = (float2*)(sm + 8704);
    float*  Ps  = sm + 8704;

    const int qb = blockIdx.x, h = blockIdx.y, b = blockIdx.z;
    const int tid = threadIdx.x;
    const int warp = tid >> 5, lane = tid & 31;
    const int g = lane >> 2, tg = lane & 3;
    const int qw0 = warp * 16;
    const size_t base = ((size_t)b * TT) * DIM + (size_t)h * HDIM;
    const int q0 = qb * 64;

    for (int t = tid; t < 512; t += 128) {
        int row = t & 63, ks = t >> 6;
        const float* src = Qg + base + (size_t)(q0 + row) * DIM + ks * 8;
        float4 v0 = *(const float4*)src, v1 = *(const float4*)(src + 4);
        float a[8] = {v0.x, v0.y, v0.z, v0.w, v1.x, v1.y, v1.z, v1.w};
#pragma unroll
        for (int p = 0; p < 4; p++)
            Qp2[(ks * 4 + p) * QPLN + row] = make_float2(tf32f(a[p]), tf32f(a[p + 4]));
    }
    __syncthreads();

    unsigned qf[8][4];
#pragma unroll
    for (int ks = 0; ks < 8; ks++) {
        float2 lo = Qp2[(ks * 4 + tg) * QPLN + qw0 + g];
        float2 hi = Qp2[(ks * 4 + tg) * QPLN + qw0 + g + 8];
        qf[ks][0] = __float_as_uint(lo.x);
        qf[ks][1] = __float_as_uint(hi.x);
        qf[ks][2] = __float_as_uint(lo.y);
        qf[ks][3] = __float_as_uint(hi.y);
    }

    float o[8][4];
#pragma unroll
    for (int ni = 0; ni < 8; ni++)
#pragma unroll
        for (int q = 0; q < 4; q++) o[ni][q] = 0.f;
    float m0 = -INFINITY, m1 = -INFINITY, l0 = 0.f, l1 = 0.f;

    for (int jb = 0; jb <= qb; jb++) {
        __syncthreads();
        const int k0 = jb * 64;
        for (int t = tid; t < 512; t += 128) {
            int row = t & 63, ks = t >> 6;
            const float* src = Kg + base + (size_t)(k0 + row) * DIM + ks * 8;
            float4 v0 = *(const float4*)src, v1 = *(const float4*)(src + 4);
            float a[8] = {v0.x, v0.y, v0.z, v0.w, v1.x, v1.y, v1.z, v1.w};
#pragma unroll
            for (int p = 0; p < 4; p++)
                Kp[(ks * 4 + p) * QPLN + row] = make_float2(tf32f(a[p]), tf32f(a[p + 4]));
        }
        for (int t = tid; t < 512; t += 128) {
            int row = t & 63, ch = t >> 6;
            const float* src = Vg + base + (size_t)(k0 + row) * DIM + ch * 8;
            float4 v0 = *(const float4*)src, v1 = *(const float4*)(src + 4);
            float a[8] = {v0.x, v0.y, v0.z, v0.w, v1.x, v1.y, v1.z, v1.w};
            int plane = (row >> 3) * 4 + (row & 3);
            int slot = (row & 4) >> 2;
            float* dst = Vf + plane * 136 + slot;
#pragma unroll
            for (int e = 0; e < 8; e++)
                dst[(ch * 8 + e) * 2] = tf32f(a[e]);
        }
        __syncthreads();

        float s[8][4];
#pragma unroll
        for (int ni = 0; ni < 8; ni++)
#pragma unroll
            for (int q = 0; q < 4; q++) s[ni][q] = 0.f;
#pragma unroll
        for (int ks = 0; ks < 8; ks++) {
#pragma unroll
            for (int ni = 0; ni < 8; ni++) {
                float2 kb = Kp[(ks * 4 + tg) * QPLN + ni * 8 + g];
                unsigned bf[2] = {__float_as_uint(kb.x), __float_as_uint(kb.y)};
                mma8(s[ni], qf[ks], bf);
            }
        }

        if (jb == qb) {
#pragma unroll
            for (int ni = 0; ni < 8; ni++) {
                int c = ni * 8 + 2 * tg;
                if (c     > qw0 + g)     s[ni][0] = -INFINITY;
                if (c + 1 > qw0 + g)     s[ni][1] = -INFINITY;
                if (c     > qw0 + g + 8) s[ni][2] = -INFINITY;
                if (c + 1 > qw0 + g + 8) s[ni][3] = -INFINITY;
            }
        }

        float rx0 = -INFINITY, rx1 = -INFINITY;
#pragma unroll
        for (int ni = 0; ni < 8; ni++) {
            rx0 = fmaxf(rx0, fmaxf(s[ni][0], s[ni][1]));
            rx1 = fmaxf(rx1, fmaxf(s[ni][2], s[ni][3]));
        }
        rx0 = fmaxf(rx0, __shfl_xor_sync(0xffffffffu, rx0, 1));
        rx0 = fmaxf(rx0, __shfl_xor_sync(0xffffffffu, rx0, 2));
        rx1 = fmaxf(rx1, __shfl_xor_sync(0xffffffffu, rx1, 1));
        rx1 = fmaxf(rx1, __shfl_xor_sync(0xffffffffu, rx1, 2));

        float mn0 = fmaxf(m0, rx0), mn1 = fmaxf(m1, rx1);
        float al0 = __expf(m0 - mn0), al1 = __expf(m1 - mn1);
        float ps0 = 0.f, ps1 = 0.f;
#pragma unroll
        for (int ni = 0; ni < 8; ni++) {
            float p0 = tf32f(__expf(s[ni][0] - mn0));
            float p1 = tf32f(__expf(s[ni][1] - mn0));
            float p2 = tf32f(__expf(s[ni][2] - mn1));
            float p3 = tf32f(__expf(s[ni][3] - mn1));
            s[ni][0] = p0; s[ni][1] = p1; s[ni][2] = p2; s[ni][3] = p3;
            ps0 += p0 + p1;
            ps1 += p2 + p3;
        }
        ps0 += __shfl_xor_sync(0xffffffffu, ps0, 1);
        ps0 += __shfl_xor_sync(0xffffffffu, ps0, 2);
        ps1 += __shfl_xor_sync(0xffffffffu, ps1, 1);
        ps1 += __shfl_xor_sync(0xffffffffu, ps1, 2);
        l0 = l0 * al0 + ps0;
        l1 = l1 * al1 + ps1;
        m0 = mn0; m1 = mn1;
#pragma unroll
        for (int ni = 0; ni < 8; ni++) {
            o[ni][0] *= al0; o[ni][1] *= al0;
            o[ni][2] *= al1; o[ni][3] *= al1;
        }

#pragma unroll
        for (int ni = 0; ni < 8; ni++) {
            *(float2*)&Ps[(qw0 + g)     * PSTR + ni * 8 + 2 * tg] = make_float2(s[ni][0], s[ni][1]);
            *(float2*)&Ps[(qw0 + g + 8) * PSTR + ni * 8 + 2 * tg] = make_float2(s[ni][2], s[ni][3]);
        }
        __syncwarp();

#pragma unroll
        for (int ks = 0; ks < 8; ks++) {
            unsigned pf[4];
            pf[0] = __float_as_uint(Ps[(qw0 + g)     * PSTR + ks * 8 + tg]);
            pf[1] = __float_as_uint(Ps[(qw0 + g + 8) * PSTR + ks * 8 + tg]);
            pf[2] = __float_as_uint(Ps[(qw0 + g)     * PSTR + ks * 8 + tg + 4]);
            pf[3] = __float_as_uint(Ps[(qw0 + g + 8) * PSTR + ks * 8 + tg + 4]);
#pragma unroll
            for (int ni = 0; ni < 8; ni++) {
                float2 vb = Vp[(ks * 4 + tg) * QPLN + ni * 8 + g];
                unsigned bf[2] = {__float_as_uint(vb.x), __float_as_uint(vb.y)};
                mma8(o[ni], pf, bf);
            }
        }
    }

    float i0 = 1.f / l0, i1 = 1.f / l1;
#pragma unroll
    for (int ni = 0; ni < 8; ni++) {
        size_t r0 = base + (size_t)(q0 + qw0 + g) * DIM + ni * 8 + 2 * tg;
        size_t r1 = base + (size_t)(q0 + qw0 + g + 8) * DIM + ni * 8 + 2 * tg;
        *(float2*)&AO[r0] = make_float2(o[ni][0] * i0, o[ni][1] * i0);
        *(float2*)&AO[r1] = make_float2(o[ni][2] * i1, o[ni][3] * i1);
    }
}

// ---------------- fused add + LayerNorm (row = 1024) ----------------
template<int ROUND>
__global__ void __launch_bounds__(256) add_ln_kernel(
    const float* __restrict__ A, const float* __restrict__ B,
    const float* __restrict__ g, const float* __restrict__ beta,
    float* __restrict__ out)
{
    const int row = blockIdx.x;
    const float* a = A + (size_t)row * DIM;
    const float* b = B + (size_t)row * DIM;
    const int tid = threadIdx.x;

    float x[4];
    float s = 0.f, s2 = 0.f;
#pragma unroll
    for (int i = 0; i < 4; i++) {
        int c = tid + i * 256;
        x[i] = a[c] + b[c];
        s += x[i];
        s2 += x[i] * x[i];
    }
#pragma unroll
    for (int off = 16; off; off >>= 1) {
        s  += __shfl_down_sync(0xffffffffu, s,  off);
        s2 += __shfl_down_sync(0xffffffffu, s2, off);
    }
    __shared__ float ss[8], ss2[8];
    __shared__ float s_mean, s_inv;
    int w = tid >> 5;
    if ((tid & 31) == 0) { ss[w] = s; ss2[w] = s2; }
    __syncthreads();
    if (tid == 0) {
        float S = 0.f, S2 = 0.f;
#pragma unroll
        for (int i = 0; i < 8; i++) { S += ss[i]; S2 += ss2[i]; }
        float mu = S * (1.f / DIM);
        float var = S2 * (1.f / DIM) - mu * mu;
        s_mean = mu;
        s_inv = rsqrtf(var + 1e-5f);
    }
    __syncthreads();
    float mu = s_mean, iv = s_inv;
#pragma unroll
    for (int i = 0; i < 4; i++) {
        int c = tid + i * 256;
        float v = (x[i] - mu) * iv * g[c] + beta[c];
        if (ROUND) v = tf32f(v);
        out[(size_t)row * DIM + c] = v;
    }
}

// ---------------- host ----------------
extern "C" void kernel_launch(void* const* d_in, const int* in_sizes, int n_in,
                              void* d_out, int out_size)
{
    const float* kq  = (const float*)d_in[0];
    const float* v   = (const float*)d_in[1];
    const float* Wk  = (const float*)d_in[2];
    const float* bk  = (const float*)d_in[3];
    const float* Wq  = (const float*)d_in[4];
    const float* bq  = (const float*)d_in[5];
    const float* Wv  = (const float*)d_in[6];
    const float* bv  = (const float*)d_in[7];
    const float* W1  = (const float*)d_in[8];
    const float* b1  = (const float*)d_in[9];
    const float* W2  = (const float*)d_in[10];
    const float* b2  = (const float*)d_in[11];
    const float* g1  = (const float*)d_in[12];
    const float* be1 = (const float*)d_in[13];
    const float* g2  = (const float*)d_in[14];
    const float* be2 = (const float*)d_in[15];
    float* out = (float*)d_out;

    float *X, *Kb, *Qb, *Vb, *AO, *Hh, *G, *F, *Wc;
    cudaGetSymbolAddress((void**)&X,  g_X);
    cudaGetSymbolAddress((void**)&Kb, g_K);
    cudaGetSymbolAddress((void**)&Qb, g_Q);
    cudaGetSymbolAddress((void**)&Vb, g_V);
    cudaGetSymbolAddress((void**)&AO, g_AO);
    cudaGetSymbolAddress((void**)&Hh, g_H);
    cudaGetSymbolAddress((void**)&G,  g_G);
    cudaGetSymbolAddress((void**)&F,  g_F);
    cudaGetSymbolAddress((void**)&Wc, g_Wc);

    float* cWk = Wc;
    float* cWq = Wc + 1 * DIM * DIM;
    float* cWv = Wc + 2 * DIM * DIM;
    float* cW1 = Wc + 3 * DIM * DIM;
    float* cW2 = Wc + 3 * DIM * DIM + FFD * DIM;

    const int GSMEM = 2 * GSTG * 16;   // 49152 bytes
    cudaFuncSetAttribute(gemm_mma<0, 0>, cudaFuncAttributeMaxDynamicSharedMemorySize, GSMEM);
    cudaFuncSetAttribute(gemm_mma<1, 1>, cudaFuncAttributeMaxDynamicSharedMemorySize, GSMEM);
    cudaFuncSetAttribute(attn_mma, cudaFuncAttributeMaxDynamicSharedMemorySize, SMEM_ATTN);

    concat_kernel<<<(MTOT * DIM) / 256, 256>>>(kq, v);
    cvt_kernel<<<(DIM * DIM) / 256, 256>>>(Wk, cWk, DIM * DIM);
    cvt_kernel<<<(DIM * DIM) / 256, 256>>>(Wq, cWq, DIM * DIM);
    cvt_kernel<<<(DIM * DIM) / 256, 256>>>(Wv, cWv, DIM * DIM);
    cvt_kernel<<<(FFD * DIM) / 256, 256>>>(W1, cW1, FFD * DIM);
    cvt_kernel<<<(FFD * DIM) / 256, 256>>>(W2, cW2, FFD * DIM);

    dim3 gqkv(DIM / 128, MTOT / 256);
    gemm_mma<0, 0><<<gqkv, 256, GSMEM>>>(X, cWk, bk, Kb, DIM, DIM);
    gemm_mma<0, 0><<<gqkv, 256, GSMEM>>>(X, cWq, bq, Qb, DIM, DIM);
    gemm_mma<0, 0><<<gqkv, 256, GSMEM>>>(X, cWv, bv, Vb, DIM, DIM);

    attn_mma<<<dim3(TT / 64, NHEAD, NBATCH), 128, SMEM_ATTN>>>(Qb, Kb, Vb, AO);

    add_ln_kernel<1><<<MTOT, 256>>>(Vb, AO, g1, be1, Hh);

    gemm_mma<1, 1><<<dim3(FFD / 128, MTOT / 256), 256, GSMEM>>>(Hh, cW1, b1, G, FFD, DIM);
    gemm_mma<0, 0><<<dim3(DIM / 128, MTOT / 256), 256, GSMEM>>>(G, cW2, b2, F, DIM, FFD);

    add_ln_kernel<0><<<MTOT, 256>>>(Hh, F, g2, be2, out);
}

// round 9
// speedup vs baseline: 1.3609x; 1.2839x over previous
#include <cuda_runtime.h>
#include <math.h>
#include <stdint.h>

#define MTOT 8192      // n * T = 4 * 2048
#define DIM 1024
#define FFD 4096
#define TT 2048
#define NBATCH 4
#define NHEAD 16
#define HDIM 64

// ---------------- scratch (no allocs allowed) ----------------
__device__ float g_Xp[MTOT * DIM];   // packed concat(kq,v), tf32-rounded (A layout)
__device__ float g_K [MTOT * DIM];
__device__ float g_Q [MTOT * DIM];
__device__ float g_V [MTOT * DIM];
__device__ float g_AO[MTOT * DIM];
__device__ float g_H [MTOT * DIM];   // after LN1 (rounded, normal layout)
__device__ float g_Hp[MTOT * DIM];   // packed H (A layout)
__device__ float g_G [MTOT * FFD];   // gelu out (rounded, normal layout)
__device__ float g_Gp[MTOT * FFD];   // packed G (A layout)
__device__ float g_F [MTOT * DIM];
__device__ float g_Wp[3 * DIM * DIM + 2 * FFD * DIM];  // packed+rounded weights (B layout)

// ---------------- helpers ----------------
__device__ __forceinline__ unsigned cvt_tf32(float f) {
    unsigned r;
    asm("cvt.rna.tf32.f32 %0, %1;" : "=r"(r) : "f"(f));
    return r;
}
__device__ __forceinline__ float tf32f(float f) { return __uint_as_float(cvt_tf32(f)); }

__device__ __forceinline__ void mma8(float* c, const unsigned* a, const unsigned* b) {
    asm volatile(
        "mma.sync.aligned.m16n8k8.row.col.f32.tf32.tf32.f32 "
        "{%0,%1,%2,%3}, {%4,%5,%6,%7}, {%8,%9}, {%0,%1,%2,%3};\n"
        : "+f"(c[0]), "+f"(c[1]), "+f"(c[2]), "+f"(c[3])
        : "r"(a[0]), "r"(a[1]), "r"(a[2]), "r"(a[3]), "r"(b[0]), "r"(b[1]));
}

__device__ __forceinline__ uint32_t smem_u32(const void* p) {
    uint32_t a;
    asm("{ .reg .u64 t; cvta.to.shared.u64 t, %1; cvt.u32.u64 %0, t; }" : "=r"(a) : "l"(p));
    return a;
}
__device__ __forceinline__ void cp16(uint32_t dst, const void* src) {
    asm volatile("cp.async.cg.shared.global [%0], [%1], 16;" :: "r"(dst), "l"(src));
}

// ---------------- pack kernels ----------------
// A layout (256-row tiles): per (mt,kt) tile of 1024 float4:
//   float2 index = idx*2 + ah, idx = ks*512 + p*128 + amb*8 + ((ag+2p)&7)
//   holds (A[m][k], A[m][k+4]); m = mt*256 + amb*16 + ah*8 + ag; k = kt*16 + ks*8 + p.
template<int ROUND>
__global__ void packA_k(const float* __restrict__ src, float* __restrict__ dst, int K) {
    __shared__ float tile[256 * 16];
    const int kt = blockIdx.x, mt = blockIdx.y, tid = threadIdx.x;
    const int NKt = K >> 4;
#pragma unroll
    for (int i = 0; i < 4; i++) {
        int idx = tid + 256 * i;
        int row = idx >> 2, q = idx & 3;
        float4 v = ((const float4*)(src + (size_t)(mt * 256 + row) * K + kt * 16))[q];
        ((float4*)tile)[row * 4 + q] = v;
    }
    __syncthreads();
    float2* d2 = (float2*)dst + (size_t)(mt * NKt + kt) * 2048;
#pragma unroll
    for (int j = 0; j < 8; j++) {
        int d = tid + 256 * j;
        int ah = d & 1, idx = d >> 1;
        int ks = idx >> 9, p = (idx >> 7) & 3, amb = (idx >> 3) & 15, slot = idx & 7;
        int ag = (slot - 2 * p) & 7;
        int arow = amb * 16 + ah * 8 + ag;
        int kk = ks * 8 + p;
        float a = tile[arow * 16 + kk], b = tile[arow * 16 + kk + 4];
        if (ROUND) { a = tf32f(a); b = tf32f(b); }
        d2[d] = make_float2(a, b);
    }
}

// concat + round + pack (K=1024; kt<32 -> kq, else v; both have row stride 512)
__global__ void packA_concat(const float* __restrict__ kq, const float* __restrict__ vv,
                             float* __restrict__ dst) {
    __shared__ float tile[256 * 16];
    const int kt = blockIdx.x, mt = blockIdx.y, tid = threadIdx.x;
    const float* src = (kt < 32) ? kq : vv;
    const int kof = (kt < 32) ? kt * 16 : (kt - 32) * 16;
#pragma unroll
    for (int i = 0; i < 4; i++) {
        int idx = tid + 256 * i;
        int row = idx >> 2, q = idx & 3;
        float4 v = ((const float4*)(src + (size_t)(mt * 256 + row) * 512 + kof))[q];
        ((float4*)tile)[row * 4 + q] = v;
    }
    __syncthreads();
    float2* d2 = (float2*)dst + (size_t)(mt * 64 + kt) * 2048;
#pragma unroll
    for (int j = 0; j < 8; j++) {
        int d = tid + 256 * j;
        int ah = d & 1, idx = d >> 1;
        int ks = idx >> 9, p = (idx >> 7) & 3, amb = (idx >> 3) & 15, slot = idx & 7;
        int ag = (slot - 2 * p) & 7;
        int arow = amb * 16 + ah * 8 + ag;
        int kk = ks * 8 + p;
        d2[d] = make_float2(tf32f(tile[arow * 16 + kk]), tf32f(tile[arow * 16 + kk + 4]));
    }
}

// B layout (128-row tiles): per (nt,kt) tile of 512 float4:
//   idx = ks*256 + p*64 + bnb*8 + ((bg+2p)&7); n = nt*128 + bnb*16 + ah*8 + bg.
__global__ void packB_k(const float* __restrict__ src, float* __restrict__ dst, int K) {
    __shared__ float tile[128 * 16];
    const int kt = blockIdx.x, nt = blockIdx.y, tid = threadIdx.x;
    const int NKt = K >> 4;
#pragma unroll
    for (int i = 0; i < 2; i++) {
        int idx = tid + 256 * i;
        int row = idx >> 2, q = idx & 3;
        float4 v = ((const float4*)(src + (size_t)(nt * 128 + row) * K + kt * 16))[q];
        ((float4*)tile)[row * 4 + q] = v;
    }
    __syncthreads();
    float2* d2 = (float2*)dst + (size_t)(nt * NKt + kt) * 1024;
#pragma unroll
    for (int j = 0; j < 4; j++) {
        int d = tid + 256 * j;
        int ah = d & 1, idx = d >> 1;
        int ks = idx >> 8, p = (idx >> 6) & 3, bnb = (idx >> 3) & 7, slot = idx & 7;
        int bg = (slot - 2 * p) & 7;
        int brow = bnb * 16 + ah * 8 + bg;
        int kk = ks * 8 + p;
        d2[d] = make_float2(tf32f(tile[brow * 16 + kk]), tf32f(tile[brow * 16 + kk + 4]));
    }
}

// ---------------- packed-operand tf32 GEMM, cp.async 4-stage pipeline ----------------
// C[M,N] = A*B^T + bias (+GELU,+ROUND). A packed (256-row tiles), B packed (128-row).
// Block 256x128x16, 8 warps 64x64. Stage = A 1024 + B 512 float4 = 24KB; 4 stages = 96KB.
#define STGB 24576
#define GPSMEM (4 * STGB)

template<int GELU, int ROUND>
__global__ void __launch_bounds__(256, 1) gemm_pk(
    const float4* __restrict__ Apk, const float4* __restrict__ Bpk,
    const float* __restrict__ bias, float* __restrict__ C,
    int N, int K)
{
    extern __shared__ float4 s4[];
    const int tid  = threadIdx.x;
    const int lane = tid & 31;
    const int warp = tid >> 5;
    const int g    = lane >> 2;
    const int tg   = lane & 3;
    const int wm   = (warp & 3) * 64;
    const int wn   = (warp >> 2) * 64;
    const int mt   = blockIdx.y;
    const int nt   = blockIdx.x;
    const int sgc  = (g + 2 * tg) & 7;
    const int NKt  = K >> 4;
    const uint32_t sbase = smem_u32(s4);

    float acc[4][8][4];
#pragma unroll
    for (int i = 0; i < 4; i++)
#pragma unroll
        for (int j = 0; j < 8; j++)
#pragma unroll
            for (int q = 0; q < 4; q++) acc[i][j][q] = 0.f;

#define FILLP(s, c) do { \
    const float4* As_ = Apk + ((size_t)mt * NKt + (c)) * 1024 + tid * 4; \
    const float4* Bs_ = Bpk + ((size_t)nt * NKt + (c)) * 512 + tid * 2; \
    uint32_t da_ = sbase + (s) * STGB + tid * 64; \
    uint32_t db_ = sbase + (s) * STGB + 16384 + tid * 32; \
    cp16(da_,      As_);     cp16(da_ + 16, As_ + 1); \
    cp16(da_ + 32, As_ + 2); cp16(da_ + 48, As_ + 3); \
    cp16(db_,      Bs_);     cp16(db_ + 16, Bs_ + 1); \
} while (0)

    FILLP(0, 0); asm volatile("cp.async.commit_group;" ::: "memory");
    FILLP(1, 1); asm volatile("cp.async.commit_group;" ::: "memory");
    FILLP(2, 2); asm volatile("cp.async.commit_group;" ::: "memory");

    for (int c = 0; c < NKt; c++) {
        asm volatile("cp.async.wait_group 2;" ::: "memory");
        __syncthreads();

        const float4* sa = s4 + (c & 3) * 1536;
        const float4* sb = sa + 1024;
#pragma unroll
        for (int ks = 0; ks < 2; ks++) {
            unsigned af[4][4], bf[8][2];
#pragma unroll
            for (int mi = 0; mi < 4; mi++) {
                float4 a4 = sa[ks * 512 + tg * 128 + ((wm >> 4) + mi) * 8 + sgc];
                af[mi][0] = __float_as_uint(a4.x);
                af[mi][1] = __float_as_uint(a4.z);
                af[mi][2] = __float_as_uint(a4.y);
                af[mi][3] = __float_as_uint(a4.w);
            }
#pragma unroll
            for (int j = 0; j < 4; j++) {
                float4 b4 = sb[ks * 256 + tg * 64 + ((wn >> 4) + j) * 8 + sgc];
                bf[2 * j][0]     = __float_as_uint(b4.x);
                bf[2 * j][1]     = __float_as_uint(b4.y);
                bf[2 * j + 1][0] = __float_as_uint(b4.z);
                bf[2 * j + 1][1] = __float_as_uint(b4.w);
            }
#pragma unroll
            for (int mi = 0; mi < 4; mi++)
#pragma unroll
                for (int ni = 0; ni < 8; ni++)
                    mma8(acc[mi][ni], af[mi], bf[ni]);
        }

        if (c + 3 < NKt) FILLP((c + 3) & 3, c + 3);
        asm volatile("cp.async.commit_group;" ::: "memory");
    }
#undef FILLP

    const int bm = mt * 256, bn = nt * 128;
#pragma unroll
    for (int ni = 0; ni < 8; ni++) {
        int n = bn + wn + ni * 8 + tg * 2;
        float b0 = bias[n], b1 = bias[n + 1];
#pragma unroll
        for (int mi = 0; mi < 4; mi++) {
            int m = bm + wm + mi * 16 + g;
            float v00 = acc[mi][ni][0] + b0;
            float v01 = acc[mi][ni][1] + b1;
            float v10 = acc[mi][ni][2] + b0;
            float v11 = acc[mi][ni][3] + b1;
            if (GELU) {
                v00 = 0.5f * v00 * (1.f + erff(v00 * 0.7071067811865476f));
                v01 = 0.5f * v01 * (1.f + erff(v01 * 0.7071067811865476f));
                v10 = 0.5f * v10 * (1.f + erff(v10 * 0.7071067811865476f));
                v11 = 0.5f * v11 * (1.f + erff(v11 * 0.7071067811865476f));
            }
            if (ROUND) {
                v00 = tf32f(v00); v01 = tf32f(v01);
                v10 = tf32f(v10); v11 = tf32f(v11);
            }
            *(float2*)&C[(size_t)m * N + n] = make_float2(v00, v01);
            *(float2*)&C[(size_t)(m + 8) * N + n] = make_float2(v10, v11);
        }
    }
}

// ---------------- attention: tf32 mma flash, causal, no scale ----------------
#define QPLN 68
#define PSTR 72
#define SMEM_ATTN (13312 * 4)

__global__ void __launch_bounds__(128, 3) attn_mma(
    const float* __restrict__ Qg, const float* __restrict__ Kg,
    const float* __restrict__ Vg, float* __restrict__ AO)
{
    extern __shared__ float sm[];
    float2* Kp  = (float2*)sm;
    float*  Vf  = sm + 4352;
    float2* Vp  = (float2*)Vf;
    float2* Qp2 = (float2*)(sm + 8704);
    float*  Ps  = sm + 8704;

    const int qb = blockIdx.x, h = blockIdx.y, b = blockIdx.z;
    const int tid = threadIdx.x;
    const int warp = tid >> 5, lane = tid & 31;
    const int g = lane >> 2, tg = lane & 3;
    const int qw0 = warp * 16;
    const size_t base = ((size_t)b * TT) * DIM + (size_t)h * HDIM;
    const int q0 = qb * 64;

    for (int t = tid; t < 512; t += 128) {
        int row = t & 63, ks = t >> 6;
        const float* src = Qg + base + (size_t)(q0 + row) * DIM + ks * 8;
        float4 v0 = *(const float4*)src, v1 = *(const float4*)(src + 4);
        float a[8] = {v0.x, v0.y, v0.z, v0.w, v1.x, v1.y, v1.z, v1.w};
#pragma unroll
        for (int p = 0; p < 4; p++)
            Qp2[(ks * 4 + p) * QPLN + row] = make_float2(tf32f(a[p]), tf32f(a[p + 4]));
    }
    __syncthreads();

    unsigned qf[8][4];
#pragma unroll
    for (int ks = 0; ks < 8; ks++) {
        float2 lo = Qp2[(ks * 4 + tg) * QPLN + qw0 + g];
        float2 hi = Qp2[(ks * 4 + tg) * QPLN + qw0 + g + 8];
        qf[ks][0] = __float_as_uint(lo.x);
        qf[ks][1] = __float_as_uint(hi.x);
        qf[ks][2] = __float_as_uint(lo.y);
        qf[ks][3] = __float_as_uint(hi.y);
    }

    float o[8][4];
#pragma unroll
    for (int ni = 0; ni < 8; ni++)
#pragma unroll
        for (int q = 0; q < 4; q++) o[ni][q] = 0.f;
    float m0 = -INFINITY, m1 = -INFINITY, l0 = 0.f, l1 = 0.f;

    for (int jb = 0; jb <= qb; jb++) {
        __syncthreads();
        const int k0 = jb * 64;
        for (int t = tid; t < 512; t += 128) {
            int row = t & 63, ks = t >> 6;
            const float* src = Kg + base + (size_t)(k0 + row) * DIM + ks * 8;
            float4 v0 = *(const float4*)src, v1 = *(const float4*)(src + 4);
            float a[8] = {v0.x, v0.y, v0.z, v0.w, v1.x, v1.y, v1.z, v1.w};
#pragma unroll
            for (int p = 0; p < 4; p++)
                Kp[(ks * 4 + p) * QPLN + row] = make_float2(tf32f(a[p]), tf32f(a[p + 4]));
        }
        for (int t = tid; t < 512; t += 128) {
            int row = t & 63, ch = t >> 6;
            const float* src = Vg + base + (size_t)(k0 + row) * DIM + ch * 8;
            float4 v0 = *(const float4*)src, v1 = *(const float4*)(src + 4);
            float a[8] = {v0.x, v0.y, v0.z, v0.w, v1.x, v1.y, v1.z, v1.w};
            int plane = (row >> 3) * 4 + (row & 3);
            int slot = (row & 4) >> 2;
            float* dst = Vf + plane * 136 + slot;
#pragma unroll
            for (int e = 0; e < 8; e++)
                dst[(ch * 8 + e) * 2] = tf32f(a[e]);
        }
        __syncthreads();

        float s[8][4];
#pragma unroll
        for (int ni = 0; ni < 8; ni++)
#pragma unroll
            for (int q = 0; q < 4; q++) s[ni][q] = 0.f;
#pragma unroll
        for (int ks = 0; ks < 8; ks++) {
#pragma unroll
            for (int ni = 0; ni < 8; ni++) {
                float2 kb = Kp[(ks * 4 + tg) * QPLN + ni * 8 + g];
                unsigned bf[2] = {__float_as_uint(kb.x), __float_as_uint(kb.y)};
                mma8(s[ni], qf[ks], bf);
            }
        }

        if (jb == qb) {
#pragma unroll
            for (int ni = 0; ni < 8; ni++) {
                int c = ni * 8 + 2 * tg;
                if (c     > qw0 + g)     s[ni][0] = -INFINITY;
                if (c + 1 > qw0 + g)     s[ni][1] = -INFINITY;
                if (c     > qw0 + g + 8) s[ni][2] = -INFINITY;
                if (c + 1 > qw0 + g + 8) s[ni][3] = -INFINITY;
            }
        }

        float rx0 = -INFINITY, rx1 = -INFINITY;
#pragma unroll
        for (int ni = 0; ni < 8; ni++) {
            rx0 = fmaxf(rx0, fmaxf(s[ni][0], s[ni][1]));
            rx1 = fmaxf(rx1, fmaxf(s[ni][2], s[ni][3]));
        }
        rx0 = fmaxf(rx0, __shfl_xor_sync(0xffffffffu, rx0, 1));
        rx0 = fmaxf(rx0, __shfl_xor_sync(0xffffffffu, rx0, 2));
        rx1 = fmaxf(rx1, __shfl_xor_sync(0xffffffffu, rx1, 1));
        rx1 = fmaxf(rx1, __shfl_xor_sync(0xffffffffu, rx1, 2));

        float mn0 = fmaxf(m0, rx0), mn1 = fmaxf(m1, rx1);
        float al0 = __expf(m0 - mn0), al1 = __expf(m1 - mn1);
        float ps0 = 0.f, ps1 = 0.f;
#pragma unroll
        for (int ni = 0; ni < 8; ni++) {
            float p0 = tf32f(__expf(s[ni][0] - mn0));
            float p1 = tf32f(__expf(s[ni][1] - mn0));
            float p2 = tf32f(__expf(s[ni][2] - mn1));
            float p3 = tf32f(__expf(s[ni][3] - mn1));
            s[ni][0] = p0; s[ni][1] = p1; s[ni][2] = p2; s[ni][3] = p3;
            ps0 += p0 + p1;
            ps1 += p2 + p3;
        }
        ps0 += __shfl_xor_sync(0xffffffffu, ps0, 1);
        ps0 += __shfl_xor_sync(0xffffffffu, ps0, 2);
        ps1 += __shfl_xor_sync(0xffffffffu, ps1, 1);
        ps1 += __shfl_xor_sync(0xffffffffu, ps1, 2);
        l0 = l0 * al0 + ps0;
        l1 = l1 * al1 + ps1;
        m0 = mn0; m1 = mn1;
#pragma unroll
        for (int ni = 0; ni < 8; ni++) {
            o[ni][0] *= al0; o[ni][1] *= al0;
            o[ni][2] *= al1; o[ni][3] *= al1;
        }

#pragma unroll
        for (int ni = 0; ni < 8; ni++) {
            *(float2*)&Ps[(qw0 + g)     * PSTR + ni * 8 + 2 * tg] = make_float2(s[ni][0], s[ni][1]);
            *(float2*)&Ps[(qw0 + g + 8) * PSTR + ni * 8 + 2 * tg] = make_float2(s[ni][2], s[ni][3]);
        }
        __syncwarp();

#pragma unroll
        for (int ks = 0; ks < 8; ks++) {
            unsigned pf[4];
            pf[0] = __float_as_uint(Ps[(qw0 + g)     * PSTR + ks * 8 + tg]);
            pf[1] = __float_as_uint(Ps[(qw0 + g + 8) * PSTR + ks * 8 + tg]);
            pf[2] = __float_as_uint(Ps[(qw0 + g)     * PSTR + ks * 8 + tg + 4]);
            pf[3] = __float_as_uint(Ps[(qw0 + g + 8) * PSTR + ks * 8 + tg + 4]);
#pragma unroll
            for (int ni = 0; ni < 8; ni++) {
                float2 vb = Vp[(ks * 4 + tg) * QPLN + ni * 8 + g];
                unsigned bf[2] = {__float_as_uint(vb.x), __float_as_uint(vb.y)};
                mma8(o[ni], pf, bf);
            }
        }
    }

    float i0 = 1.f / l0, i1 = 1.f / l1;
#pragma unroll
    for (int ni = 0; ni < 8; ni++) {
        size_t r0 = base + (size_t)(q0 + qw0 + g) * DIM + ni * 8 + 2 * tg;
        size_t r1 = base + (size_t)(q0 + qw0 + g + 8) * DIM + ni * 8 + 2 * tg;
        *(float2*)&AO[r0] = make_float2(o[ni][0] * i0, o[ni][1] * i0);
        *(float2*)&AO[r1] = make_float2(o[ni][2] * i1, o[ni][3] * i1);
    }
}

// ---------------- fused add + LayerNorm (row = 1024) ----------------
template<int ROUND>
__global__ void __launch_bounds__(256) add_ln_kernel(
    const float* __restrict__ A, const float* __restrict__ B,
    const float* __restrict__ g, const float* __restrict__ beta,
    float* __restrict__ out)
{
    const int row = blockIdx.x;
    const float* a = A + (size_t)row * DIM;
    const float* b = B + (size_t)row * DIM;
    const int tid = threadIdx.x;

    float x[4];
    float s = 0.f, s2 = 0.f;
#pragma unroll
    for (int i = 0; i < 4; i++) {
        int c = tid + i * 256;
        x[i] = a[c] + b[c];
        s += x[i];
        s2 += x[i] * x[i];
    }
#pragma unroll
    for (int off = 16; off; off >>= 1) {
        s  += __shfl_down_sync(0xffffffffu, s,  off);
        s2 += __shfl_down_sync(0xffffffffu, s2, off);
    }
    __shared__ float ss[8], ss2[8];
    __shared__ float s_mean, s_inv;
    int w = tid >> 5;
    if ((tid & 31) == 0) { ss[w] = s; ss2[w] = s2; }
    __syncthreads();
    if (tid == 0) {
        float S = 0.f, S2 = 0.f;
#pragma unroll
        for (int i = 0; i < 8; i++) { S += ss[i]; S2 += ss2[i]; }
        float mu = S * (1.f / DIM);
        float var = S2 * (1.f / DIM) - mu * mu;
        s_mean = mu;
        s_inv = rsqrtf(var + 1e-5f);
    }
    __syncthreads();
    float mu = s_mean, iv = s_inv;
#pragma unroll
    for (int i = 0; i < 4; i++) {
        int c = tid + i * 256;
        float v = (x[i] - mu) * iv * g[c] + beta[c];
        if (ROUND) v = tf32f(v);
        out[(size_t)row * DIM + c] = v;
    }
}

// ---------------- host ----------------
extern "C" void kernel_launch(void* const* d_in, const int* in_sizes, int n_in,
                              void* d_out, int out_size)
{
    const float* kq  = (const float*)d_in[0];
    const float* v   = (const float*)d_in[1];
    const float* Wk  = (const float*)d_in[2];
    const float* bk  = (const float*)d_in[3];
    const float* Wq  = (const float*)d_in[4];
    const float* bq  = (const float*)d_in[5];
    const float* Wv  = (const float*)d_in[6];
    const float* bv  = (const float*)d_in[7];
    const float* W1  = (const float*)d_in[8];
    const float* b1  = (const float*)d_in[9];
    const float* W2  = (const float*)d_in[10];
    const float* b2  = (const float*)d_in[11];
    const float* g1  = (const float*)d_in[12];
    const float* be1 = (const float*)d_in[13];
    const float* g2  = (const float*)d_in[14];
    const float* be2 = (const float*)d_in[15];
    float* out = (float*)d_out;

    float *Xp, *Kb, *Qb, *Vb, *AO, *Hh, *Hp, *G, *Gp, *F, *Wp;
    cudaGetSymbolAddress((void**)&Xp, g_Xp);
    cudaGetSymbolAddress((void**)&Kb, g_K);
    cudaGetSymbolAddress((void**)&Qb, g_Q);
    cudaGetSymbolAddress((void**)&Vb, g_V);
    cudaGetSymbolAddress((void**)&AO, g_AO);
    cudaGetSymbolAddress((void**)&Hh, g_H);
    cudaGetSymbolAddress((void**)&Hp, g_Hp);
    cudaGetSymbolAddress((void**)&G,  g_G);
    cudaGetSymbolAddress((void**)&Gp, g_Gp);
    cudaGetSymbolAddress((void**)&F,  g_F);
    cudaGetSymbolAddress((void**)&Wp, g_Wp);

    float* pWk = Wp;
    float* pWq = Wp + 1 * DIM * DIM;
    float* pWv = Wp + 2 * DIM * DIM;
    float* pW1 = Wp + 3 * DIM * DIM;
    float* pW2 = Wp + 3 * DIM * DIM + FFD * DIM;

    cudaFuncSetAttribute(gemm_pk<0, 0>, cudaFuncAttributeMaxDynamicSharedMemorySize, GPSMEM);
    cudaFuncSetAttribute(gemm_pk<1, 1>, cudaFuncAttributeMaxDynamicSharedMemorySize, GPSMEM);
    cudaFuncSetAttribute(attn_mma, cudaFuncAttributeMaxDynamicSharedMemorySize, SMEM_ATTN);

    // pack inputs
    packA_concat<<<dim3(DIM / 16, MTOT / 256), 256>>>(kq, v, Xp);
    packB_k<<<dim3(DIM / 16, DIM / 128), 256>>>(Wk, pWk, DIM);
    packB_k<<<dim3(DIM / 16, DIM / 128), 256>>>(Wq, pWq, DIM);
    packB_k<<<dim3(DIM / 16, DIM / 128), 256>>>(Wv, pWv, DIM);
    packB_k<<<dim3(DIM / 16, FFD / 128), 256>>>(W1, pW1, DIM);
    packB_k<<<dim3(FFD / 16, DIM / 128), 256>>>(W2, pW2, FFD);

    // QKV
    dim3 gqkv(DIM / 128, MTOT / 256);
    gemm_pk<0, 0><<<gqkv, 256, GPSMEM>>>((const float4*)Xp, (const float4*)pWk, bk, Kb, DIM, DIM);
    gemm_pk<0, 0><<<gqkv, 256, GPSMEM>>>((const float4*)Xp, (const float4*)pWq, bq, Qb, DIM, DIM);
    gemm_pk<0, 0><<<gqkv, 256, GPSMEM>>>((const float4*)Xp, (const float4*)pWv, bv, Vb, DIM, DIM);

    attn_mma<<<dim3(TT / 64, NHEAD, NBATCH), 128, SMEM_ATTN>>>(Qb, Kb, Vb, AO);

    add_ln_kernel<1><<<MTOT, 256>>>(Vb, AO, g1, be1, Hh);
    packA_k<0><<<dim3(DIM / 16, MTOT / 256), 256>>>(Hh, Hp, DIM);

    gemm_pk<1, 1><<<dim3(FFD / 128, MTOT / 256), 256, GPSMEM>>>((const float4*)Hp, (const float4*)pW1, b1, G, FFD, DIM);
    packA_k<0><<<dim3(FFD / 16, MTOT / 256), 256>>>(G, Gp, FFD);
    gemm_pk<0, 0><<<dim3(DIM / 128, MTOT / 256), 256, GPSMEM>>>((const float4*)Gp, (const float4*)pW2, b2, F, DIM, FFD);

    add_ln_kernel<0><<<MTOT, 256>>>(Hh, F, g2, be2, out);
}

// round 10
// speedup vs baseline: 1.3621x; 1.0009x over previous
#include <cuda_runtime.h>
#include <math.h>
#include <stdint.h>

#define MTOT 8192      // n * T = 4 * 2048
#define DIM 1024
#define FFD 4096
#define TT 2048
#define NBATCH 4
#define NHEAD 16
#define HDIM 64
#define QKVSTR 3072

// ---------------- scratch (no allocs allowed) ----------------
__device__ float g_Xp[MTOT * DIM];        // packed concat(kq,v), tf32-rounded (A layout)
__device__ float g_QKV[MTOT * QKVSTR];    // fused K|Q|V output (cols 0:K,1024:Q,2048:V)
__device__ float g_AO[MTOT * DIM];
__device__ float g_H [MTOT * DIM];        // after LN1 (rounded, normal layout)
__device__ float g_Hp[MTOT * DIM];        // packed H (A layout)
__device__ float g_Gp[MTOT * FFD];        // packed gelu out (A layout)
__device__ float g_F [MTOT * DIM];
__device__ float g_Wp[3 * DIM * DIM + 2 * FFD * DIM];  // packed+rounded weights (B layout)
__device__ float g_bqkv[QKVSTR];

// ---------------- helpers ----------------
__device__ __forceinline__ unsigned cvt_tf32(float f) {
    unsigned r;
    asm("cvt.rna.tf32.f32 %0, %1;" : "=r"(r) : "f"(f));
    return r;
}
__device__ __forceinline__ float tf32f(float f) { return __uint_as_float(cvt_tf32(f)); }

__device__ __forceinline__ void mma8(float* c, const unsigned* a, const unsigned* b) {
    asm volatile(
        "mma.sync.aligned.m16n8k8.row.col.f32.tf32.tf32.f32 "
        "{%0,%1,%2,%3}, {%4,%5,%6,%7}, {%8,%9}, {%0,%1,%2,%3};\n"
        : "+f"(c[0]), "+f"(c[1]), "+f"(c[2]), "+f"(c[3])
        : "r"(a[0]), "r"(a[1]), "r"(a[2]), "r"(a[3]), "r"(b[0]), "r"(b[1]));
}

__device__ __forceinline__ uint32_t smem_u32(const void* p) {
    uint32_t a;
    asm("{ .reg .u64 t; cvta.to.shared.u64 t, %1; cvt.u32.u64 %0, t; }" : "=r"(a) : "l"(p));
    return a;
}
__device__ __forceinline__ void cp16(uint32_t dst, const void* src) {
    asm volatile("cp.async.cg.shared.global [%0], [%1], 16;" :: "r"(dst), "l"(src));
}

// ---------------- pack kernels ----------------
// A layout (256-row tiles): per (mt,kt) tile of 1024 float4:
//   float2 index = idx*2 + ah, idx = ks*512 + p*128 + amb*8 + ((ag+2p)&7)
//   holds (A[m][k], A[m][k+4]); m = mt*256 + amb*16 + ah*8 + ag; k = kt*16 + ks*8 + p.
template<int ROUND>
__global__ void packA_k(const float* __restrict__ src, float* __restrict__ dst, int K) {
    __shared__ float tile[256 * 16];
    const int kt = blockIdx.x, mt = blockIdx.y, tid = threadIdx.x;
    const int NKt = K >> 4;
#pragma unroll
    for (int i = 0; i < 4; i++) {
        int idx = tid + 256 * i;
        int row = idx >> 2, q = idx & 3;
        float4 v = ((const float4*)(src + (size_t)(mt * 256 + row) * K + kt * 16))[q];
        ((float4*)tile)[row * 4 + q] = v;
    }
    __syncthreads();
    float2* d2 = (float2*)dst + (size_t)(mt * NKt + kt) * 2048;
#pragma unroll
    for (int j = 0; j < 8; j++) {
        int d = tid + 256 * j;
        int ah = d & 1, idx = d >> 1;
        int ks = idx >> 9, p = (idx >> 7) & 3, amb = (idx >> 3) & 15, slot = idx & 7;
        int ag = (slot - 2 * p) & 7;
        int arow = amb * 16 + ah * 8 + ag;
        int kk = ks * 8 + p;
        float a = tile[arow * 16 + kk], b = tile[arow * 16 + kk + 4];
        if (ROUND) { a = tf32f(a); b = tf32f(b); }
        d2[d] = make_float2(a, b);
    }
}

// concat + round + pack (K=1024; kt<32 -> kq, else v; both row stride 512)
__global__ void packA_concat(const float* __restrict__ kq, const float* __restrict__ vv,
                             float* __restrict__ dst) {
    __shared__ float tile[256 * 16];
    const int kt = blockIdx.x, mt = blockIdx.y, tid = threadIdx.x;
    const float* src = (kt < 32) ? kq : vv;
    const int kof = (kt < 32) ? kt * 16 : (kt - 32) * 16;
#pragma unroll
    for (int i = 0; i < 4; i++) {
        int idx = tid + 256 * i;
        int row = idx >> 2, q = idx & 3;
        float4 v = ((const float4*)(src + (size_t)(mt * 256 + row) * 512 + kof))[q];
        ((float4*)tile)[row * 4 + q] = v;
    }
    __syncthreads();
    float2* d2 = (float2*)dst + (size_t)(mt * 64 + kt) * 2048;
#pragma unroll
    for (int j = 0; j < 8; j++) {
        int d = tid + 256 * j;
        int ah = d & 1, idx = d >> 1;
        int ks = idx >> 9, p = (idx >> 7) & 3, amb = (idx >> 3) & 15, slot = idx & 7;
        int ag = (slot - 2 * p) & 7;
        int arow = amb * 16 + ah * 8 + ag;
        int kk = ks * 8 + p;
        d2[d] = make_float2(tf32f(tile[arow * 16 + kk]), tf32f(tile[arow * 16 + kk + 4]));
    }
}

// B layout (128-row tiles): per (nt,kt) tile of 512 float4.
__global__ void packB_k(const float* __restrict__ src, float* __restrict__ dst, int K) {
    __shared__ float tile[128 * 16];
    const int kt = blockIdx.x, nt = blockIdx.y, tid = threadIdx.x;
    const int NKt = K >> 4;
#pragma unroll
    for (int i = 0; i < 2; i++) {
        int idx = tid + 256 * i;
        int row = idx >> 2, q = idx & 3;
        float4 v = ((const float4*)(src + (size_t)(nt * 128 + row) * K + kt * 16))[q];
        ((float4*)tile)[row * 4 + q] = v;
    }
    __syncthreads();
    float2* d2 = (float2*)dst + (size_t)(nt * NKt + kt) * 1024;
#pragma unroll
    for (int j = 0; j < 4; j++) {
        int d = tid + 256 * j;
        int ah = d & 1, idx = d >> 1;
        int ks = idx >> 8, p = (idx >> 6) & 3, bnb = (idx >> 3) & 7, slot = idx & 7;
        int bg = (slot - 2 * p) & 7;
        int brow = bnb * 16 + ah * 8 + bg;
        int kk = ks * 8 + p;
        d2[d] = make_float2(tf32f(tile[brow * 16 + kk]), tf32f(tile[brow * 16 + kk + 4]));
    }
}

__global__ void biascat(const float* __restrict__ bk, const float* __restrict__ bq,
                        const float* __restrict__ bv, float* __restrict__ dst) {
    int i = blockIdx.x * 256 + threadIdx.x;
    dst[i] = (i < 1024) ? bk[i] : (i < 2048 ? bq[i - 1024] : bv[i - 2048]);
}

// ---------------- packed-operand tf32 GEMM, cp.async 4-stage pipeline ----------------
// Block 256x128x16, 8 warps 64x64. Stage = A 1024 + B 512 float4 = 24KB; 4 stages.
// PACKOUT=1: write output in packed A layout (via smem staging) instead of row-major.
#define STGB 24576
#define GPSMEM (4 * STGB)

template<int GELU, int ROUND, int PACKOUT>
__global__ void __launch_bounds__(256, 1) gemm_pk(
    const float4* __restrict__ Apk, const float4* __restrict__ Bpk,
    const float* __restrict__ bias, float* __restrict__ C,
    int N, int K)
{
    extern __shared__ float4 s4[];
    const int tid  = threadIdx.x;
    const int lane = tid & 31;
    const int warp = tid >> 5;
    const int g    = lane >> 2;
    const int tg   = lane & 3;
    const int wm   = (warp & 3) * 64;
    const int wn   = (warp >> 2) * 64;
    const int mt   = blockIdx.y;
    const int nt   = blockIdx.x;
    const int sgc  = (g + 2 * tg) & 7;
    const int NKt  = K >> 4;
    const uint32_t sbase = smem_u32(s4);

    float acc[4][8][4];
#pragma unroll
    for (int i = 0; i < 4; i++)
#pragma unroll
        for (int j = 0; j < 8; j++)
#pragma unroll
            for (int q = 0; q < 4; q++) acc[i][j][q] = 0.f;

#define FILLP(s, c) do { \
    const float4* As_ = Apk + ((size_t)mt * NKt + (c)) * 1024 + tid * 4; \
    const float4* Bs_ = Bpk + ((size_t)nt * NKt + (c)) * 512 + tid * 2; \
    uint32_t da_ = sbase + (s) * STGB + tid * 64; \
    uint32_t db_ = sbase + (s) * STGB + 16384 + tid * 32; \
    cp16(da_,      As_);     cp16(da_ + 16, As_ + 1); \
    cp16(da_ + 32, As_ + 2); cp16(da_ + 48, As_ + 3); \
    cp16(db_,      Bs_);     cp16(db_ + 16, Bs_ + 1); \
} while (0)

    FILLP(0, 0); asm volatile("cp.async.commit_group;" ::: "memory");
    FILLP(1, 1); asm volatile("cp.async.commit_group;" ::: "memory");
    FILLP(2, 2); asm volatile("cp.async.commit_group;" ::: "memory");

    for (int c = 0; c < NKt; c++) {
        asm volatile("cp.async.wait_group 2;" ::: "memory");
        __syncthreads();

        const float4* sa = s4 + (c & 3) * 1536;
        const float4* sb = sa + 1024;
#pragma unroll
        for (int ks = 0; ks < 2; ks++) {
            unsigned af[4][4], bf[8][2];
#pragma unroll
            for (int mi = 0; mi < 4; mi++) {
                float4 a4 = sa[ks * 512 + tg * 128 + ((wm >> 4) + mi) * 8 + sgc];
                af[mi][0] = __float_as_uint(a4.x);
                af[mi][1] = __float_as_uint(a4.z);
                af[mi][2] = __float_as_uint(a4.y);
                af[mi][3] = __float_as_uint(a4.w);
            }
#pragma unroll
            for (int j = 0; j < 4; j++) {
                float4 b4 = sb[ks * 256 + tg * 64 + ((wn >> 4) + j) * 8 + sgc];
                bf[2 * j][0]     = __float_as_uint(b4.x);
                bf[2 * j][1]     = __float_as_uint(b4.y);
                bf[2 * j + 1][0] = __float_as_uint(b4.z);
                bf[2 * j + 1][1] = __float_as_uint(b4.w);
            }
#pragma unroll
            for (int mi = 0; mi < 4; mi++)
#pragma unroll
                for (int ni = 0; ni < 8; ni++)
                    mma8(acc[mi][ni], af[mi], bf[ni]);
        }

        if (c + 3 < NKt) FILLP((c + 3) & 3, c + 3);
        asm volatile("cp.async.commit_group;" ::: "memory");
    }
#undef FILLP

    const int bm = mt * 256, bn = nt * 128;

    if (!PACKOUT) {
#pragma unroll
        for (int ni = 0; ni < 8; ni++) {
            int n = bn + wn + ni * 8 + tg * 2;
            float b0 = bias[n], b1 = bias[n + 1];
#pragma unroll
            for (int mi = 0; mi < 4; mi++) {
                int m = bm + wm + mi * 16 + g;
                float v00 = acc[mi][ni][0] + b0;
                float v01 = acc[mi][ni][1] + b1;
                float v10 = acc[mi][ni][2] + b0;
                float v11 = acc[mi][ni][3] + b1;
                if (GELU) {
                    v00 = 0.5f * v00 * (1.f + erff(v00 * 0.7071067811865476f));
                    v01 = 0.5f * v01 * (1.f + erff(v01 * 0.7071067811865476f));
                    v10 = 0.5f * v10 * (1.f + erff(v10 * 0.7071067811865476f));
                    v11 = 0.5f * v11 * (1.f + erff(v11 * 0.7071067811865476f));
                }
                if (ROUND) {
                    v00 = tf32f(v00); v01 = tf32f(v01);
                    v10 = tf32f(v10); v11 = tf32f(v11);
                }
                *(float2*)&C[(size_t)m * N + n] = make_float2(v00, v01);
                *(float2*)&C[(size_t)(m + 8) * N + n] = make_float2(v10, v11);
            }
        }
    } else {
        // stage 256x64 halves in smem, write packed A-layout tiles (16-col kt tiles)
        float* Cs = (float*)s4;     // 256 x 65 floats = 66560 B (< 96KB; cp.async drained)
        const int NKo = N >> 4;
        float2* d2 = (float2*)C;
        for (int half = 0; half < 2; half++) {
            __syncthreads();
            if ((warp >> 2) == half) {
#pragma unroll
                for (int ni = 0; ni < 8; ni++) {
                    int ncol = ni * 8 + tg * 2;          // 0..63 within half
                    int n = bn + half * 64 + ncol;
                    float b0 = bias[n], b1 = bias[n + 1];
#pragma unroll
                    for (int mi = 0; mi < 4; mi++) {
                        int mr = wm + mi * 16 + g;
                        float v00 = acc[mi][ni][0] + b0;
                        float v01 = acc[mi][ni][1] + b1;
                        float v10 = acc[mi][ni][2] + b0;
                        float v11 = acc[mi][ni][3] + b1;
                        if (GELU) {
                            v00 = 0.5f * v00 * (1.f + erff(v00 * 0.7071067811865476f));
                            v01 = 0.5f * v01 * (1.f + erff(v01 * 0.7071067811865476f));
                            v10 = 0.5f * v10 * (1.f + erff(v10 * 0.7071067811865476f));
                            v11 = 0.5f * v11 * (1.f + erff(v11 * 0.7071067811865476f));
                        }
                        if (ROUND) {
                            v00 = tf32f(v00); v01 = tf32f(v01);
                            v10 = tf32f(v10); v11 = tf32f(v11);
                        }
                        Cs[mr * 65 + ncol] = v00;
                        Cs[mr * 65 + ncol + 1] = v01;
                        Cs[(mr + 8) * 65 + ncol] = v10;
                        Cs[(mr + 8) * 65 + ncol + 1] = v11;
                    }
                }
            }
            __syncthreads();
#pragma unroll 4
            for (int t = 0; t < 32; t++) {
                int e = tid + 256 * t;            // 0..8191
                int ktl = e >> 11, r = e & 2047;  // local kt (0..3), float2 index in tile
                int ah = r & 1, idx = r >> 1;
                int ks = idx >> 9, p = (idx >> 7) & 3, amb = (idx >> 3) & 15, slot = idx & 7;
                int ag = (slot - 2 * p) & 7;
                int arow = amb * 16 + ah * 8 + ag;
                int col = ktl * 16 + ks * 8 + p;
                int ktg = ((bn + half * 64) >> 4) + ktl;
                d2[((size_t)mt * NKo + ktg) * 2048 + r] =
                    make_float2(Cs[arow * 65 + col], Cs[arow * 65 + col + 4]);
            }
        }
    }
}

// ---------------- attention: tf32 mma flash, causal, no scale ----------------
// Reads fused QKV buffer (row stride 3072: cols 0=K, 1024=Q, 2048=V).
#define QPLN 68
#define PSTR 72
#define SMEM_ATTN (13312 * 4)

__global__ void __launch_bounds__(128, 3) attn_mma(
    const float* __restrict__ QKV, float* __restrict__ AO)
{
    extern __shared__ float sm[];
    float2* Kp  = (float2*)sm;
    float*  Vf  = sm + 4352;
    float2* Vp  = (float2*)Vf;
    float2* Qp2 = (float2*)(sm + 8704);
    float*  Ps  = sm + 8704;

    const int qb = blockIdx.x, h = blockIdx.y, b = blockIdx.z;
    const int tid = threadIdx.x;
    const int warp = tid >> 5, lane = tid & 31;
    const int g = lane >> 2, tg = lane & 3;
    const int qw0 = warp * 16;
    const size_t ib = ((size_t)b * TT) * QKVSTR + (size_t)h * HDIM;
    const size_t ob = ((size_t)b * TT) * DIM + (size_t)h * HDIM;
    const int q0 = qb * 64;

    for (int t = tid; t < 512; t += 128) {
        int row = t & 63, ks = t >> 6;
        const float* src = QKV + 1024 + ib + (size_t)(q0 + row) * QKVSTR + ks * 8;
        float4 v0 = *(const float4*)src, v1 = *(const float4*)(src + 4);
        float a[8] = {v0.x, v0.y, v0.z, v0.w, v1.x, v1.y, v1.z, v1.w};
#pragma unroll
        for (int p = 0; p < 4; p++)
            Qp2[(ks * 4 + p) * QPLN + row] = make_float2(tf32f(a[p]), tf32f(a[p + 4]));
    }
    __syncthreads();

    unsigned qf[8][4];
#pragma unroll
    for (int ks = 0; ks < 8; ks++) {
        float2 lo = Qp2[(ks * 4 + tg) * QPLN + qw0 + g];
        float2 hi = Qp2[(ks * 4 + tg) * QPLN + qw0 + g + 8];
        qf[ks][0] = __float_as_uint(lo.x);
        qf[ks][1] = __float_as_uint(hi.x);
        qf[ks][2] = __float_as_uint(lo.y);
        qf[ks][3] = __float_as_uint(hi.y);
    }

    float o[8][4];
#pragma unroll
    for (int ni = 0; ni < 8; ni++)
#pragma unroll
        for (int q = 0; q < 4; q++) o[ni][q] = 0.f;
    float m0 = -INFINITY, m1 = -INFINITY, l0 = 0.f, l1 = 0.f;

    for (int jb = 0; jb <= qb; jb++) {
        __syncthreads();
        const int k0 = jb * 64;
        for (int t = tid; t < 512; t += 128) {
            int row = t & 63, ks = t >> 6;
            const float* src = QKV + ib + (size_t)(k0 + row) * QKVSTR + ks * 8;
            float4 v0 = *(const float4*)src, v1 = *(const float4*)(src + 4);
            float a[8] = {v0.x, v0.y, v0.z, v0.w, v1.x, v1.y, v1.z, v1.w};
#pragma unroll
            for (int p = 0; p < 4; p++)
                Kp[(ks * 4 + p) * QPLN + row] = make_float2(tf32f(a[p]), tf32f(a[p + 4]));
        }
        for (int t = tid; t < 512; t += 128) {
            int row = t & 63, ch = t >> 6;
            const float* src = QKV + 2048 + ib + (size_t)(k0 + row) * QKVSTR + ch * 8;
            float4 v0 = *(const float4*)src, v1 = *(const float4*)(src + 4);
            float a[8] = {v0.x, v0.y, v0.z, v0.w, v1.x, v1.y, v1.z, v1.w};
            int plane = (row >> 3) * 4 + (row & 3);
            int slot = (row & 4) >> 2;
            float* dst = Vf + plane * 136 + slot;
#pragma unroll
            for (int e = 0; e < 8; e++)
                dst[(ch * 8 + e) * 2] = tf32f(a[e]);
        }
        __syncthreads();

        float s[8][4];
#pragma unroll
        for (int ni = 0; ni < 8; ni++)
#pragma unroll
            for (int q = 0; q < 4; q++) s[ni][q] = 0.f;
#pragma unroll
        for (int ks = 0; ks < 8; ks++) {
#pragma unroll
            for (int ni = 0; ni < 8; ni++) {
                float2 kb = Kp[(ks * 4 + tg) * QPLN + ni * 8 + g];
                unsigned bf[2] = {__float_as_uint(kb.x), __float_as_uint(kb.y)};
                mma8(s[ni], qf[ks], bf);
            }
        }

        if (jb == qb) {
#pragma unroll
            for (int ni = 0; ni < 8; ni++) {
                int c = ni * 8 + 2 * tg;
                if (c     > qw0 + g)     s[ni][0] = -INFINITY;
                if (c + 1 > qw0 + g)     s[ni][1] = -INFINITY;
                if (c     > qw0 + g + 8) s[ni][2] = -INFINITY;
                if (c + 1 > qw0 + g + 8) s[ni][3] = -INFINITY;
            }
        }

        float rx0 = -INFINITY, rx1 = -INFINITY;
#pragma unroll
        for (int ni = 0; ni < 8; ni++) {
            rx0 = fmaxf(rx0, fmaxf(s[ni][0], s[ni][1]));
            rx1 = fmaxf(rx1, fmaxf(s[ni][2], s[ni][3]));
        }
        rx0 = fmaxf(rx0, __shfl_xor_sync(0xffffffffu, rx0, 1));
        rx0 = fmaxf(rx0, __shfl_xor_sync(0xffffffffu, rx0, 2));
        rx1 = fmaxf(rx1, __shfl_xor_sync(0xffffffffu, rx1, 1));
        rx1 = fmaxf(rx1, __shfl_xor_sync(0xffffffffu, rx1, 2));

        float mn0 = fmaxf(m0, rx0), mn1 = fmaxf(m1, rx1);
        float al0 = __expf(m0 - mn0), al1 = __expf(m1 - mn1);
        float ps0 = 0.f, ps1 = 0.f;
#pragma unroll
        for (int ni = 0; ni < 8; ni++) {
            float p0 = tf32f(__expf(s[ni][0] - mn0));
            float p1 = tf32f(__expf(s[ni][1] - mn0));
            float p2 = tf32f(__expf(s[ni][2] - mn1));
            float p3 = tf32f(__expf(s[ni][3] - mn1));
            s[ni][0] = p0; s[ni][1] = p1; s[ni][2] = p2; s[ni][3] = p3;
            ps0 += p0 + p1;
            ps1 += p2 + p3;
        }
        ps0 += __shfl_xor_sync(0xffffffffu, ps0, 1);
        ps0 += __shfl_xor_sync(0xffffffffu, ps0, 2);
        ps1 += __shfl_xor_sync(0xffffffffu, ps1, 1);
        ps1 += __shfl_xor_sync(0xffffffffu, ps1, 2);
        l0 = l0 * al0 + ps0;
        l1 = l1 * al1 + ps1;
        m0 = mn0; m1 = mn1;
#pragma unroll
        for (int ni = 0; ni < 8; ni++) {
            o[ni][0] *= al0; o[ni][1] *= al0;
            o[ni][2] *= al1; o[ni][3] *= al1;
        }

#pragma unroll
        for (int ni = 0; ni < 8; ni++) {
            *(float2*)&Ps[(qw0 + g)     * PSTR + ni * 8 + 2 * tg] = make_float2(s[ni][0], s[ni][1]);
            *(float2*)&Ps[(qw0 + g + 8) * PSTR + ni * 8 + 2 * tg] = make_float2(s[ni][2], s[ni][3]);
        }
        __syncwarp();

#pragma unroll
        for (int ks = 0; ks < 8; ks++) {
            unsigned pf[4];
            pf[0] = __float_as_uint(Ps[(qw0 + g)     * PSTR + ks * 8 + tg]);
            pf[1] = __float_as_uint(Ps[(qw0 + g + 8) * PSTR + ks * 8 + tg]);
            pf[2] = __float_as_uint(Ps[(qw0 + g)     * PSTR + ks * 8 + tg + 4]);
            pf[3] = __float_as_uint(Ps[(qw0 + g + 8) * PSTR + ks * 8 + tg + 4]);
#pragma unroll
            for (int ni = 0; ni < 8; ni++) {
                float2 vb = Vp[(ks * 4 + tg) * QPLN + ni * 8 + g];
                unsigned bf[2] = {__float_as_uint(vb.x), __float_as_uint(vb.y)};
                mma8(o[ni], pf, bf);
            }
        }
    }

    float i0 = 1.f / l0, i1 = 1.f / l1;
#pragma unroll
    for (int ni = 0; ni < 8; ni++) {
        size_t r0 = ob + (size_t)(q0 + qw0 + g) * DIM + ni * 8 + 2 * tg;
        size_t r1 = ob + (size_t)(q0 + qw0 + g + 8) * DIM + ni * 8 + 2 * tg;
        *(float2*)&AO[r0] = make_float2(o[ni][0] * i0, o[ni][1] * i0);
        *(float2*)&AO[r1] = make_float2(o[ni][2] * i1, o[ni][3] * i1);
    }
}

// ---------------- fused add + LayerNorm (row = 1024; A has stride strideA) ---------
template<int ROUND>
__global__ void __launch_bounds__(256) add_ln_kernel(
    const float* __restrict__ A, int strideA, const float* __restrict__ B,
    const float* __restrict__ g, const float* __restrict__ beta,
    float* __restrict__ out)
{
    const int row = blockIdx.x;
    const float* a = A + (size_t)row * strideA;
    const float* b = B + (size_t)row * DIM;
    const int tid = threadIdx.x;

    float x[4];
    float s = 0.f, s2 = 0.f;
#pragma unroll
    for (int i = 0; i < 4; i++) {
        int c = tid + i * 256;
        x[i] = a[c] + b[c];
        s += x[i];
        s2 += x[i] * x[i];
    }
#pragma unroll
    for (int off = 16; off; off >>= 1) {
        s  += __shfl_down_sync(0xffffffffu, s,  off);
        s2 += __shfl_down_sync(0xffffffffu, s2, off);
    }
    __shared__ float ss[8], ss2[8];
    __shared__ float s_mean, s_inv;
    int w = tid >> 5;
    if ((tid & 31) == 0) { ss[w] = s; ss2[w] = s2; }
    __syncthreads();
    if (tid == 0) {
        float S = 0.f, S2 = 0.f;
#pragma unroll
        for (int i = 0; i < 8; i++) { S += ss[i]; S2 += ss2[i]; }
        float mu = S * (1.f / DIM);
        float var = S2 * (1.f / DIM) - mu * mu;
        s_mean = mu;
        s_inv = rsqrtf(var + 1e-5f);
    }
    __syncthreads();
    float mu = s_mean, iv = s_inv;
#pragma unroll
    for (int i = 0; i < 4; i++) {
        int c = tid + i * 256;
        float v = (x[i] - mu) * iv * g[c] + beta[c];
        if (ROUND) v = tf32f(v);
        out[(size_t)row * DIM + c] = v;
    }
}

// ---------------- host ----------------
extern "C" void kernel_launch(void* const* d_in, const int* in_sizes, int n_in,
                              void* d_out, int out_size)
{
    const float* kq  = (const float*)d_in[0];
    const float* v   = (const float*)d_in[1];
    const float* Wk  = (const float*)d_in[2];
    const float* bk  = (const float*)d_in[3];
    const float* Wq  = (const float*)d_in[4];
    const float* bq  = (const float*)d_in[5];
    const float* Wv  = (const float*)d_in[6];
    const float* bv  = (const float*)d_in[7];
    const float* W1  = (const float*)d_in[8];
    const float* b1  = (const float*)d_in[9];
    const float* W2  = (const float*)d_in[10];
    const float* b2  = (const float*)d_in[11];
    const float* g1  = (const float*)d_in[12];
    const float* be1 = (const float*)d_in[13];
    const float* g2  = (const float*)d_in[14];
    const float* be2 = (const float*)d_in[15];
    float* out = (float*)d_out;

    float *Xp, *QKV, *AO, *Hh, *Hp, *Gp, *F, *Wp, *bqkv;
    cudaGetSymbolAddress((void**)&Xp,  g_Xp);
    cudaGetSymbolAddress((void**)&QKV, g_QKV);
    cudaGetSymbolAddress((void**)&AO,  g_AO);
    cudaGetSymbolAddress((void**)&Hh,  g_H);
    cudaGetSymbolAddress((void**)&Hp,  g_Hp);
    cudaGetSymbolAddress((void**)&Gp,  g_Gp);
    cudaGetSymbolAddress((void**)&F,   g_F);
    cudaGetSymbolAddress((void**)&Wp,  g_Wp);
    cudaGetSymbolAddress((void**)&bqkv, g_bqkv);

    float* pWk = Wp;                              // nt 0..7 of fused B
    float* pWq = Wp + 1 * DIM * DIM;              // nt 8..15
    float* pWv = Wp + 2 * DIM * DIM;              // nt 16..23
    float* pW1 = Wp + 3 * DIM * DIM;
    float* pW2 = Wp + 3 * DIM * DIM + FFD * DIM;

    cudaFuncSetAttribute(gemm_pk<0, 0, 0>, cudaFuncAttributeMaxDynamicSharedMemorySize, GPSMEM);
    cudaFuncSetAttribute(gemm_pk<1, 1, 1>, cudaFuncAttributeMaxDynamicSharedMemorySize, GPSMEM);
    cudaFuncSetAttribute(attn_mma, cudaFuncAttributeMaxDynamicSharedMemorySize, SMEM_ATTN);

    // pack inputs
    packA_concat<<<dim3(DIM / 16, MTOT / 256), 256>>>(kq, v, Xp);
    packB_k<<<dim3(DIM / 16, DIM / 128), 256>>>(Wk, pWk, DIM);
    packB_k<<<dim3(DIM / 16, DIM / 128), 256>>>(Wq, pWq, DIM);
    packB_k<<<dim3(DIM / 16, DIM / 128), 256>>>(Wv, pWv, DIM);
    packB_k<<<dim3(DIM / 16, FFD / 128), 256>>>(W1, pW1, DIM);
    packB_k<<<dim3(FFD / 16, DIM / 128), 256>>>(W2, pW2, FFD);
    biascat<<<QKVSTR / 256, 256>>>(bk, bq, bv, bqkv);

    // fused QKV GEMM: [8192,1024] x [3072,1024]^T -> [8192,3072]
    gemm_pk<0, 0, 0><<<dim3(QKVSTR / 128, MTOT / 256), 256, GPSMEM>>>(
        (const float4*)Xp, (const float4*)Wp, bqkv, QKV, QKVSTR, DIM);

    attn_mma<<<dim3(TT / 64, NHEAD, NBATCH), 128, SMEM_ATTN>>>(QKV, AO);

    add_ln_kernel<1><<<MTOT, 256>>>(QKV + 2048, QKVSTR, AO, g1, be1, Hh);
    packA_k<0><<<dim3(DIM / 16, MTOT / 256), 256>>>(Hh, Hp, DIM);

    // FFN1: writes packed Gp directly
    gemm_pk<1, 1, 1><<<dim3(FFD / 128, MTOT / 256), 256, GPSMEM>>>(
        (const float4*)Hp, (const float4*)pW1, b1, (float*)Gp, FFD, DIM);
    // FFN2
    gemm_pk<0, 0, 0><<<dim3(DIM / 128, MTOT / 256), 256, GPSMEM>>>(
        (const float4*)Gp, (const float4*)pW2, b2, F, DIM, FFD);

    add_ln_kernel<0><<<MTOT, 256>>>(Hh, DIM, F, g2, be2, out);
}

// round 12
// speedup vs baseline: 2.0648x; 1.5159x over previous
#include <cuda_runtime.h>
#include <cuda_fp16.h>
#include <math.h>
#include <stdint.h>

#define MTOT 8192      // n * T = 4 * 2048
#define DIM 1024
#define FFD 4096
#define TT 2048
#define NBATCH 4
#define NHEAD 16
#define HDIM 64
#define QKVSTR 3072

// ---------------- scratch (no allocs allowed) ----------------
__device__ __half g_Xp[MTOT * DIM];        // packed concat(kq,v), fp16 (A layout)
__device__ float  g_QKV[MTOT * QKVSTR];    // fused K|Q|V output (cols 0:K,1024:Q,2048:V)
__device__ float  g_AO[MTOT * DIM];
__device__ float  g_H [MTOT * DIM];        // after LN1 (fp32, normal layout)
__device__ __half g_Hp[MTOT * DIM];        // packed H (A layout, fp16)
__device__ __half g_Gp[MTOT * FFD];        // packed gelu out (A layout, fp16)
__device__ float  g_F [MTOT * DIM];
__device__ __half g_Wp[3 * DIM * DIM + 2 * FFD * DIM];  // packed weights (B layout, fp16)
__device__ float  g_bqkv[QKVSTR];

// ---------------- helpers ----------------
__device__ __forceinline__ unsigned cvt_tf32(float f) {
    unsigned r;
    asm("cvt.rna.tf32.f32 %0, %1;" : "=r"(r) : "f"(f));
    return r;
}
__device__ __forceinline__ float tf32f(float f) { return __uint_as_float(cvt_tf32(f)); }

// fp16 m16n8k16 mma (fp32 accum)
__device__ __forceinline__ void mma16(float* c, const unsigned* a, const unsigned* b) {
    asm volatile(
        "mma.sync.aligned.m16n8k16.row.col.f32.f16.f16.f32 "
        "{%0,%1,%2,%3}, {%4,%5,%6,%7}, {%8,%9}, {%0,%1,%2,%3};\n"
        : "+f"(c[0]), "+f"(c[1]), "+f"(c[2]), "+f"(c[3])
        : "r"(a[0]), "r"(a[1]), "r"(a[2]), "r"(a[3]), "r"(b[0]), "r"(b[1]));
}

// tf32 m16n8k8 mma (attention)
__device__ __forceinline__ void mma8(float* c, const unsigned* a, const unsigned* b) {
    asm volatile(
        "mma.sync.aligned.m16n8k8.row.col.f32.tf32.tf32.f32 "
        "{%0,%1,%2,%3}, {%4,%5,%6,%7}, {%8,%9}, {%0,%1,%2,%3};\n"
        : "+f"(c[0]), "+f"(c[1]), "+f"(c[2]), "+f"(c[3])
        : "r"(a[0]), "r"(a[1]), "r"(a[2]), "r"(a[3]), "r"(b[0]), "r"(b[1]));
}

__device__ __forceinline__ float h2f(float a, float b) {
    __half2 h = __floats2half2_rn(a, b);
    return __uint_as_float(*reinterpret_cast<unsigned*>(&h));
}

__device__ __forceinline__ uint32_t smem_u32(const void* p) {
    uint32_t a;
    asm("{ .reg .u64 t; cvta.to.shared.u64 t, %1; cvt.u32.u64 %0, t; }" : "=r"(a) : "l"(p));
    return a;
}
__device__ __forceinline__ void cp16(uint32_t dst, const void* src) {
    asm volatile("cp.async.cg.shared.global [%0], [%1], 16;" :: "r"(dst), "l"(src));
}

// ---------------- pack kernels (fp16 quad layout) ----------------
// A layout, 256-row x 32-col tiles of 1024 float4.
// d = ks*512 + tg*128 + mblk*8 + slot; g' = (slot-2tg)&7; m = mblk*16+g'; k = ks*16+2tg.
// float4 = { h2(A[m][k],A[m][k+1]), h2(A[m+8][k],A[m+8][k+1]),
//            h2(A[m][k+8],A[m][k+9]), h2(A[m+8][k+8],A[m+8][k+9]) }
#define TSTR 36

__global__ void packA_h(const float* __restrict__ src, __half* __restrict__ dst, int K) {
    __shared__ float T[256 * TSTR];
    const int kt = blockIdx.x, mt = blockIdx.y, tid = threadIdx.x;
    const int NKt = K >> 5;
#pragma unroll
    for (int i = 0; i < 8; i++) {
        int idx = tid + 256 * i;            // 2048 float4 loads of 256x32
        int row = idx >> 3, q = idx & 7;
        float4 v = ((const float4*)(src + (size_t)(mt * 256 + row) * K + kt * 32))[q];
        *(float4*)&T[row * TSTR + q * 4] = v;
    }
    __syncthreads();
    float4* d4 = (float4*)dst + (size_t)(mt * NKt + kt) * 1024;
#pragma unroll
    for (int j = 0; j < 4; j++) {
        int d = tid + 256 * j;
        int slot = d & 7, mblk = (d >> 3) & 15, tg = (d >> 7) & 3, ks = d >> 9;
        int gp = (slot - 2 * tg) & 7;
        int m = mblk * 16 + gp, k = ks * 16 + 2 * tg;
        float4 o;
        o.x = h2f(T[m * TSTR + k],           T[m * TSTR + k + 1]);
        o.y = h2f(T[(m + 8) * TSTR + k],     T[(m + 8) * TSTR + k + 1]);
        o.z = h2f(T[m * TSTR + k + 8],       T[m * TSTR + k + 9]);
        o.w = h2f(T[(m + 8) * TSTR + k + 8], T[(m + 8) * TSTR + k + 9]);
        d4[d] = o;
    }
}

// concat variant: K=1024 (32 kt tiles of 32); kt<16 -> kq else v (row stride 512)
__global__ void packA_concat_h(const float* __restrict__ kq, const float* __restrict__ vv,
                               __half* __restrict__ dst) {
    __shared__ float T[256 * TSTR];
    const int kt = blockIdx.x, mt = blockIdx.y, tid = threadIdx.x;
    const float* src = (kt < 16) ? kq : vv;
    const int kof = (kt < 16) ? kt * 32 : (kt - 16) * 32;
#pragma unroll
    for (int i = 0; i < 8; i++) {
        int idx = tid + 256 * i;
        int row = idx >> 3, q = idx & 7;
        float4 v = ((const float4*)(src + (size_t)(mt * 256 + row) * 512 + kof))[q];
        *(float4*)&T[row * TSTR + q * 4] = v;
    }
    __syncthreads();
    float4* d4 = (float4*)dst + (size_t)(mt * 32 + kt) * 1024;
#pragma unroll
    for (int j = 0; j < 4; j++) {
        int d = tid + 256 * j;
        int slot = d & 7, mblk = (d >> 3) & 15, tg = (d >> 7) & 3, ks = d >> 9;
        int gp = (slot - 2 * tg) & 7;
        int m = mblk * 16 + gp, k = ks * 16 + 2 * tg;
        float4 o;
        o.x = h2f(T[m * TSTR + k],           T[m * TSTR + k + 1]);
        o.y = h2f(T[(m + 8) * TSTR + k],     T[(m + 8) * TSTR + k + 1]);
        o.z = h2f(T[m * TSTR + k + 8],       T[m * TSTR + k + 9]);
        o.w = h2f(T[(m + 8) * TSTR + k + 8], T[(m + 8) * TSTR + k + 9]);
        d4[d] = o;
    }
}

// B layout, 128-row x 32-col tiles of 512 float4.
// d = ks*256 + tg*64 + nblk*8 + slot; g'=(slot-2tg)&7; n=nblk*16+g'; k=ks*16+2tg.
// float4 = { h2(W[n][k],W[n][k+1]), h2(W[n][k+8],W[n][k+9]),
//            h2(W[n+8][k],W[n+8][k+1]), h2(W[n+8][k+8],W[n+8][k+9]) }
__global__ void packB_h(const float* __restrict__ src, __half* __restrict__ dst, int K) {
    __shared__ float T[128 * TSTR];
    const int kt = blockIdx.x, nt = blockIdx.y, tid = threadIdx.x;
    const int NKt = K >> 5;
#pragma unroll
    for (int i = 0; i < 4; i++) {
        int idx = tid + 256 * i;            // 1024 float4 loads of 128x32
        int row = idx >> 3, q = idx & 7;
        float4 v = ((const float4*)(src + (size_t)(nt * 128 + row) * K + kt * 32))[q];
        *(float4*)&T[row * TSTR + q * 4] = v;
    }
    __syncthreads();
    float4* d4 = (float4*)dst + (size_t)(nt * NKt + kt) * 512;
#pragma unroll
    for (int j = 0; j < 2; j++) {
        int d = tid + 256 * j;
        int slot = d & 7, nblk = (d >> 3) & 7, tg = (d >> 6) & 3, ks = d >> 8;
        int gp = (slot - 2 * tg) & 7;
        int n = nblk * 16 + gp, k = ks * 16 + 2 * tg;
        float4 o;
        o.x = h2f(T[n * TSTR + k],           T[n * TSTR + k + 1]);
        o.y = h2f(T[n * TSTR + k + 8],       T[n * TSTR + k + 9]);
        o.z = h2f(T[(n + 8) * TSTR + k],     T[(n + 8) * TSTR + k + 1]);
        o.w = h2f(T[(n + 8) * TSTR + k + 8], T[(n + 8) * TSTR + k + 9]);
        d4[d] = o;
    }
}

__global__ void biascat(const float* __restrict__ bk, const float* __restrict__ bq,
                        const float* __restrict__ bv, float* __restrict__ dst) {
    int i = blockIdx.x * 256 + threadIdx.x;
    dst[i] = (i < 1024) ? bk[i] : (i < 2048 ? bq[i - 1024] : bv[i - 2048]);
}

// ---------------- packed fp16 GEMM, cp.async 4-stage pipeline ----------------
// Block 256x128x32, 8 warps 64x64, m16n8k16. Stage = A 1024 + B 512 float4 = 24KB.
// PACKOUT=1: write output as packed fp16 A layout (32-col kt tiles).
#define STGB 24576
#define GPSMEM (4 * STGB)

template<int GELU, int PACKOUT>
__global__ void __launch_bounds__(256, 1) gemm_pk(
    const float4* __restrict__ Apk, const float4* __restrict__ Bpk,
    const float* __restrict__ bias, float* __restrict__ C,
    int N, int K)
{
    extern __shared__ float4 s4[];
    const int tid  = threadIdx.x;
    const int lane = tid & 31;
    const int warp = tid >> 5;
    const int g    = lane >> 2;
    const int tg   = lane & 3;
    const int wm   = (warp & 3) * 64;
    const int wn   = (warp >> 2) * 64;
    const int mt   = blockIdx.y;
    const int nt   = blockIdx.x;
    const int sgc  = (g + 2 * tg) & 7;
    const int NKt  = K >> 5;
    const uint32_t sbase = smem_u32(s4);

    float acc[4][8][4];
#pragma unroll
    for (int i = 0; i < 4; i++)
#pragma unroll
        for (int j = 0; j < 8; j++)
#pragma unroll
            for (int q = 0; q < 4; q++) acc[i][j][q] = 0.f;

#define FILLP(s, c) do { \
    const float4* As_ = Apk + ((size_t)mt * NKt + (c)) * 1024 + tid * 4; \
    const float4* Bs_ = Bpk + ((size_t)nt * NKt + (c)) * 512 + tid * 2; \
    uint32_t da_ = sbase + (s) * STGB + tid * 64; \
    uint32_t db_ = sbase + (s) * STGB + 16384 + tid * 32; \
    cp16(da_,      As_);     cp16(da_ + 16, As_ + 1); \
    cp16(da_ + 32, As_ + 2); cp16(da_ + 48, As_ + 3); \
    cp16(db_,      Bs_);     cp16(db_ + 16, Bs_ + 1); \
} while (0)

    FILLP(0, 0); asm volatile("cp.async.commit_group;" ::: "memory");
    FILLP(1, 1); asm volatile("cp.async.commit_group;" ::: "memory");
    FILLP(2, 2); asm volatile("cp.async.commit_group;" ::: "memory");

    for (int c = 0; c < NKt; c++) {
        asm volatile("cp.async.wait_group 2;" ::: "memory");
        __syncthreads();

        const float4* sa = s4 + (c & 3) * 1536;
        const float4* sb = sa + 1024;
#pragma unroll
        for (int ks = 0; ks < 2; ks++) {
            unsigned af[4][4], bf[8][2];
#pragma unroll
            for (int mi = 0; mi < 4; mi++) {
                float4 a4 = sa[ks * 512 + tg * 128 + ((wm >> 4) + mi) * 8 + sgc];
                af[mi][0] = __float_as_uint(a4.x);
                af[mi][1] = __float_as_uint(a4.y);
                af[mi][2] = __float_as_uint(a4.z);
                af[mi][3] = __float_as_uint(a4.w);
            }
#pragma unroll
            for (int j = 0; j < 4; j++) {
                float4 b4 = sb[ks * 256 + tg * 64 + ((wn >> 4) + j) * 8 + sgc];
                bf[2 * j][0]     = __float_as_uint(b4.x);
                bf[2 * j][1]     = __float_as_uint(b4.y);
                bf[2 * j + 1][0] = __float_as_uint(b4.z);
                bf[2 * j + 1][1] = __float_as_uint(b4.w);
            }
#pragma unroll
            for (int mi = 0; mi < 4; mi++)
#pragma unroll
                for (int ni = 0; ni < 8; ni++)
                    mma16(acc[mi][ni], af[mi], bf[ni]);
        }

        if (c + 3 < NKt) FILLP((c + 3) & 3, c + 3);
        asm volatile("cp.async.commit_group;" ::: "memory");
    }
#undef FILLP

    const int bm = mt * 256, bn = nt * 128;

    if (!PACKOUT) {
#pragma unroll
        for (int ni = 0; ni < 8; ni++) {
            int n = bn + wn + ni * 8 + tg * 2;
            float b0 = bias[n], b1 = bias[n + 1];
#pragma unroll
            for (int mi = 0; mi < 4; mi++) {
                int m = bm + wm + mi * 16 + g;
                float v00 = acc[mi][ni][0] + b0;
                float v01 = acc[mi][ni][1] + b1;
                float v10 = acc[mi][ni][2] + b0;
                float v11 = acc[mi][ni][3] + b1;
                if (GELU) {
                    v00 = 0.5f * v00 * (1.f + erff(v00 * 0.7071067811865476f));
                    v01 = 0.5f * v01 * (1.f + erff(v01 * 0.7071067811865476f));
                    v10 = 0.5f * v10 * (1.f + erff(v10 * 0.7071067811865476f));
                    v11 = 0.5f * v11 * (1.f + erff(v11 * 0.7071067811865476f));
                }
                *(float2*)&C[(size_t)m * N + n] = make_float2(v00, v01);
                *(float2*)&C[(size_t)(m + 8) * N + n] = make_float2(v10, v11);
            }
        }
    } else {
        // stage 256x64 halves, emit packed fp16 A-layout tiles (32-col kt tiles)
        asm volatile("cp.async.wait_group 0;" ::: "memory");
        float* Cs = (float*)s4;     // 256 x 65 floats
        const int NKo = N >> 5;
        float4* d4 = (float4*)C;
        for (int hf = 0; hf < 2; hf++) {
            __syncthreads();
            if ((warp >> 2) == hf) {
#pragma unroll
                for (int ni = 0; ni < 8; ni++) {
                    int ncol = ni * 8 + tg * 2;
                    int n = bn + hf * 64 + ncol;
                    float b0 = bias[n], b1 = bias[n + 1];
#pragma unroll
                    for (int mi = 0; mi < 4; mi++) {
                        int mr = wm + mi * 16 + g;
                        float v00 = acc[mi][ni][0] + b0;
                        float v01 = acc[mi][ni][1] + b1;
                        float v10 = acc[mi][ni][2] + b0;
                        float v11 = acc[mi][ni][3] + b1;
                        if (GELU) {
                            v00 = 0.5f * v00 * (1.f + erff(v00 * 0.7071067811865476f));
                            v01 = 0.5f * v01 * (1.f + erff(v01 * 0.7071067811865476f));
                            v10 = 0.5f * v10 * (1.f + erff(v10 * 0.7071067811865476f));
                            v11 = 0.5f * v11 * (1.f + erff(v11 * 0.7071067811865476f));
                        }
                        Cs[mr * 65 + ncol] = v00;
                        Cs[mr * 65 + ncol + 1] = v01;
                        Cs[(mr + 8) * 65 + ncol] = v10;
                        Cs[(mr + 8) * 65 + ncol + 1] = v11;
                    }
                }
            }
            __syncthreads();
#pragma unroll
            for (int t = 0; t < 8; t++) {
                int e = tid + 256 * t;             // 0..2047 (2 tiles x 1024)
                int ktl = e >> 10, d = e & 1023;
                int slot = d & 7, mblk = (d >> 3) & 15, tgg = (d >> 7) & 3, ks = d >> 9;
                int gp = (slot - 2 * tgg) & 7;
                int m = mblk * 16 + gp;
                int col = ktl * 32 + ks * 16 + 2 * tgg;
                int ktg = ((bn + hf * 64) >> 5) + ktl;
                float4 o;
                o.x = h2f(Cs[m * 65 + col],           Cs[m * 65 + col + 1]);
                o.y = h2f(Cs[(m + 8) * 65 + col],     Cs[(m + 8) * 65 + col + 1]);
                o.z = h2f(Cs[m * 65 + col + 8],       Cs[m * 65 + col + 9]);
                o.w = h2f(Cs[(m + 8) * 65 + col + 8], Cs[(m + 8) * 65 + col + 9]);
                d4[((size_t)mt * NKo + ktg) * 1024 + d] = o;
            }
        }
    }
}

// ---------------- attention: tf32 mma flash, causal, no scale ----------------
#define QPLN 68
#define PSTR 72
#define SMEM_ATTN (13312 * 4)

__global__ void __launch_bounds__(128, 3) attn_mma(
    const float* __restrict__ QKV, float* __restrict__ AO)
{
    extern __shared__ float sm[];
    float2* Kp  = (float2*)sm;
    float*  Vf  = sm + 4352;
    float2* Vp  = (float2*)Vf;
    float2* Qp2 = (float2*)(sm + 8704);
    float*  Ps  = sm + 8704;

    const int qb = blockIdx.x, h = blockIdx.y, b = blockIdx.z;
    const int tid = threadIdx.x;
    const int warp = tid >> 5, lane = tid & 31;
    const int g = lane >> 2, tg = lane & 3;
    const int qw0 = warp * 16;
    const size_t ib = ((size_t)b * TT) * QKVSTR + (size_t)h * HDIM;
    const size_t ob = ((size_t)b * TT) * DIM + (size_t)h * HDIM;
    const int q0 = qb * 64;

    for (int t = tid; t < 512; t += 128) {
        int row = t & 63, ks = t >> 6;
        const float* src = QKV + 1024 + ib + (size_t)(q0 + row) * QKVSTR + ks * 8;
        float4 v0 = *(const float4*)src, v1 = *(const float4*)(src + 4);
        float a[8] = {v0.x, v0.y, v0.z, v0.w, v1.x, v1.y, v1.z, v1.w};
#pragma unroll
        for (int p = 0; p < 4; p++)
            Qp2[(ks * 4 + p) * QPLN + row] = make_float2(tf32f(a[p]), tf32f(a[p + 4]));
    }
    __syncthreads();

    unsigned qf[8][4];
#pragma unroll
    for (int ks = 0; ks < 8; ks++) {
        float2 lo = Qp2[(ks * 4 + tg) * QPLN + qw0 + g];
        float2 hi = Qp2[(ks * 4 + tg) * QPLN + qw0 + g + 8];
        qf[ks][0] = __float_as_uint(lo.x);
        qf[ks][1] = __float_as_uint(hi.x);
        qf[ks][2] = __float_as_uint(lo.y);
        qf[ks][3] = __float_as_uint(hi.y);
    }

    float o[8][4];
#pragma unroll
    for (int ni = 0; ni < 8; ni++)
#pragma unroll
        for (int q = 0; q < 4; q++) o[ni][q] = 0.f;
    float m0 = -INFINITY, m1 = -INFINITY, l0 = 0.f, l1 = 0.f;

    for (int jb = 0; jb <= qb; jb++) {
        __syncthreads();
        const int k0 = jb * 64;
        for (int t = tid; t < 512; t += 128) {
            int row = t & 63, ks = t >> 6;
            const float* src = QKV + ib + (size_t)(k0 + row) * QKVSTR + ks * 8;
            float4 v0 = *(const float4*)src, v1 = *(const float4*)(src + 4);
            float a[8] = {v0.x, v0.y, v0.z, v0.w, v1.x, v1.y, v1.z, v1.w};
#pragma unroll
            for (int p = 0; p < 4; p++)
                Kp[(ks * 4 + p) * QPLN + row] = make_float2(tf32f(a[p]), tf32f(a[p + 4]));
        }
        for (int t = tid; t < 512; t += 128) {
            int row = t & 63, ch = t >> 6;
            const float* src = QKV + 2048 + ib + (size_t)(k0 + row) * QKVSTR + ch * 8;
            float4 v0 = *(const float4*)src, v1 = *(const float4*)(src + 4);
            float a[8] = {v0.x, v0.y, v0.z, v0.w, v1.x, v1.y, v1.z, v1.w};
            int plane = (row >> 3) * 4 + (row & 3);
            int slot = (row & 4) >> 2;
            float* dst = Vf + plane * 136 + slot;
#pragma unroll
            for (int e = 0; e < 8; e++)
                dst[(ch * 8 + e) * 2] = tf32f(a[e]);
        }
        __syncthreads();

        float s[8][4];
#pragma unroll
        for (int ni = 0; ni < 8; ni++)
#pragma unroll
            for (int q = 0; q < 4; q++) s[ni][q] = 0.f;
#pragma unroll
        for (int ks = 0; ks < 8; ks++) {
#pragma unroll
            for (int ni = 0; ni < 8; ni++) {
                float2 kb = Kp[(ks * 4 + tg) * QPLN + ni * 8 + g];
                unsigned bf[2] = {__float_as_uint(kb.x), __float_as_uint(kb.y)};
                mma8(s[ni], qf[ks], bf);
            }
        }

        if (jb == qb) {
#pragma unroll
            for (int ni = 0; ni < 8; ni++) {
                int c = ni * 8 + 2 * tg;
                if (c     > qw0 + g)     s[ni][0] = -INFINITY;
                if (c + 1 > qw0 + g)     s[ni][1] = -INFINITY;
                if (c     > qw0 + g + 8) s[ni][2] = -INFINITY;
                if (c + 1 > qw0 + g + 8) s[ni][3] = -INFINITY;
            }
        }

        float rx0 = -INFINITY, rx1 = -INFINITY;
#pragma unroll
        for (int ni = 0; ni < 8; ni++) {
            rx0 = fmaxf(rx0, fmaxf(s[ni][0], s[ni][1]));
            rx1 = fmaxf(rx1, fmaxf(s[ni][2], s[ni][3]));
        }
        rx0 = fmaxf(rx0, __shfl_xor_sync(0xffffffffu, rx0, 1));
        rx0 = fmaxf(rx0, __shfl_xor_sync(0xffffffffu, rx0, 2));
        rx1 = fmaxf(rx1, __shfl_xor_sync(0xffffffffu, rx1, 1));
        rx1 = fmaxf(rx1, __shfl_xor_sync(0xffffffffu, rx1, 2));

        float mn0 = fmaxf(m0, rx0), mn1 = fmaxf(m1, rx1);
        float al0 = __expf(m0 - mn0), al1 = __expf(m1 - mn1);
        float ps0 = 0.f, ps1 = 0.f;
#pragma unroll
        for (int ni = 0; ni < 8; ni++) {
            float p0 = tf32f(__expf(s[ni][0] - mn0));
            float p1 = tf32f(__expf(s[ni][1] - mn0));
            float p2 = tf32f(__expf(s[ni][2] - mn1));
            float p3 = tf32f(__expf(s[ni][3] - mn1));
            s[ni][0] = p0; s[ni][1] = p1; s[ni][2] = p2; s[ni][3] = p3;
            ps0 += p0 + p1;
            ps1 += p2 + p3;
        }
        ps0 += __shfl_xor_sync(0xffffffffu, ps0, 1);
        ps0 += __shfl_xor_sync(0xffffffffu, ps0, 2);
        ps1 += __shfl_xor_sync(0xffffffffu, ps1, 1);
        ps1 += __shfl_xor_sync(0xffffffffu, ps1, 2);
        l0 = l0 * al0 + ps0;
        l1 = l1 * al1 + ps1;
        m0 = mn0; m1 = mn1;
#pragma unroll
        for (int ni = 0; ni < 8; ni++) {
            o[ni][0] *= al0; o[ni][1] *= al0;
            o[ni][2] *= al1; o[ni][3] *= al1;
        }

#pragma unroll
        for (int ni = 0; ni < 8; ni++) {
            *(float2*)&Ps[(qw0 + g)     * PSTR + ni * 8 + 2 * tg] = make_float2(s[ni][0], s[ni][1]);
            *(float2*)&Ps[(qw0 + g + 8) * PSTR + ni * 8 + 2 * tg] = make_float2(s[ni][2], s[ni][3]);
        }
        __syncwarp();

#pragma unroll
        for (int ks = 0; ks < 8; ks++) {
            unsigned pf[4];
            pf[0] = __float_as_uint(Ps[(qw0 + g)     * PSTR + ks * 8 + tg]);
            pf[1] = __float_as_uint(Ps[(qw0 + g + 8) * PSTR + ks * 8 + tg]);
            pf[2] = __float_as_uint(Ps[(qw0 + g)     * PSTR + ks * 8 + tg + 4]);
            pf[3] = __float_as_uint(Ps[(qw0 + g + 8) * PSTR + ks * 8 + tg + 4]);
#pragma unroll
            for (int ni = 0; ni < 8; ni++) {
                float2 vb = Vp[(ks * 4 + tg) * QPLN + ni * 8 + g];
                unsigned bf[2] = {__float_as_uint(vb.x), __float_as_uint(vb.y)};
                mma8(o[ni], pf, bf);
            }
        }
    }

    float i0 = 1.f / l0, i1 = 1.f / l1;
#pragma unroll
    for (int ni = 0; ni < 8; ni++) {
        size_t r0 = ob + (size_t)(q0 + qw0 + g) * DIM + ni * 8 + 2 * tg;
        size_t r1 = ob + (size_t)(q0 + qw0 + g + 8) * DIM + ni * 8 + 2 * tg;
        *(float2*)&AO[r0] = make_float2(o[ni][0] * i0, o[ni][1] * i0);
        *(float2*)&AO[r1] = make_float2(o[ni][2] * i1, o[ni][3] * i1);
    }
}

// ---------------- fused add + LayerNorm (row = 1024; A has stride strideA) ---------
__global__ void __launch_bounds__(256) add_ln_kernel(
    const float* __restrict__ A, int strideA, const float* __restrict__ B,
    const float* __restrict__ g, const float* __restrict__ beta,
    float* __restrict__ out)
{
    const int row = blockIdx.x;
    const float* a = A + (size_t)row * strideA;
    const float* b = B + (size_t)row * DIM;
    const int tid = threadIdx.x;

    float x[4];
    float s = 0.f, s2 = 0.f;
#pragma unroll
    for (int i = 0; i < 4; i++) {
        int c = tid + i * 256;
        x[i] = a[c] + b[c];
        s += x[i];
        s2 += x[i] * x[i];
    }
#pragma unroll
    for (int off = 16; off; off >>= 1) {
        s  += __shfl_down_sync(0xffffffffu, s,  off);
        s2 += __shfl_down_sync(0xffffffffu, s2, off);
    }
    __shared__ float ss[8], ss2[8];
    __shared__ float s_mean, s_inv;
    int w = tid >> 5;
    if ((tid & 31) == 0) { ss[w] = s; ss2[w] = s2; }
    __syncthreads();
    if (tid == 0) {
        float S = 0.f, S2 = 0.f;
#pragma unroll
        for (int i = 0; i < 8; i++) { S += ss[i]; S2 += ss2[i]; }
        float mu = S * (1.f / DIM);
        float var = S2 * (1.f / DIM) - mu * mu;
        s_mean = mu;
        s_inv = rsqrtf(var + 1e-5f);
    }
    __syncthreads();
    float mu = s_mean, iv = s_inv;
#pragma unroll
    for (int i = 0; i < 4; i++) {
        int c = tid + i * 256;
        out[(size_t)row * DIM + c] = (x[i] - mu) * iv * g[c] + beta[c];
    }
}

// ---------------- host ----------------
extern "C" void kernel_launch(void* const* d_in, const int* in_sizes, int n_in,
                              void* d_out, int out_size)
{
    const float* kq  = (const float*)d_in[0];
    const float* v   = (const float*)d_in[1];
    const float* Wk  = (const float*)d_in[2];
    const float* bk  = (const float*)d_in[3];
    const float* Wq  = (const float*)d_in[4];
    const float* bq  = (const float*)d_in[5];
    const float* Wv  = (const float*)d_in[6];
    const float* bv  = (const float*)d_in[7];
    const float* W1  = (const float*)d_in[8];
    const float* b1  = (const float*)d_in[9];
    const float* W2  = (const float*)d_in[10];
    const float* b2  = (const float*)d_in[11];
    const float* g1  = (const float*)d_in[12];
    const float* be1 = (const float*)d_in[13];
    const float* g2  = (const float*)d_in[14];
    const float* be2 = (const float*)d_in[15];
    float* out = (float*)d_out;

    __half *Xp, *Hp, *Gp, *Wp;
    float *QKV, *AO, *Hh, *F, *bqkv;
    cudaGetSymbolAddress((void**)&Xp,  g_Xp);
    cudaGetSymbolAddress((void**)&QKV, g_QKV);
    cudaGetSymbolAddress((void**)&AO,  g_AO);
    cudaGetSymbolAddress((void**)&Hh,  g_H);
    cudaGetSymbolAddress((void**)&Hp,  g_Hp);
    cudaGetSymbolAddress((void**)&Gp,  g_Gp);
    cudaGetSymbolAddress((void**)&F,   g_F);
    cudaGetSymbolAddress((void**)&Wp,  g_Wp);
    cudaGetSymbolAddress((void**)&bqkv, g_bqkv);

    __half* pW1 = Wp + 3 * DIM * DIM;
    __half* pW2 = Wp + 3 * DIM * DIM + (size_t)FFD * DIM;

    cudaFuncSetAttribute(gemm_pk<0, 0>, cudaFuncAttributeMaxDynamicSharedMemorySize, GPSMEM);
    cudaFuncSetAttribute(gemm_pk<1, 1>, cudaFuncAttributeMaxDynamicSharedMemorySize, GPSMEM);
    cudaFuncSetAttribute(attn_mma, cudaFuncAttributeMaxDynamicSharedMemorySize, SMEM_ATTN);

    // pack inputs (fp16)
    packA_concat_h<<<dim3(DIM / 32, MTOT / 256), 256>>>(kq, v, Xp);
    packB_h<<<dim3(DIM / 32, DIM / 128), 256>>>(Wk, Wp, DIM);
    packB_h<<<dim3(DIM / 32, DIM / 128), 256>>>(Wq, Wp + DIM * DIM, DIM);
    packB_h<<<dim3(DIM / 32, DIM / 128), 256>>>(Wv, Wp + 2 * DIM * DIM, DIM);
    packB_h<<<dim3(DIM / 32, FFD / 128), 256>>>(W1, pW1, DIM);
    packB_h<<<dim3(FFD / 32, DIM / 128), 256>>>(W2, pW2, FFD);
    biascat<<<QKVSTR / 256, 256>>>(bk, bq, bv, bqkv);

    // fused QKV GEMM: [8192,1024] x [3072,1024]^T -> [8192,3072] fp32
    gemm_pk<0, 0><<<dim3(QKVSTR / 128, MTOT / 256), 256, GPSMEM>>>(
        (const float4*)Xp, (const float4*)Wp, bqkv, QKV, QKVSTR, DIM);

    attn_mma<<<dim3(TT / 64, NHEAD, NBATCH), 128, SMEM_ATTN>>>(QKV, AO);

    add_ln_kernel<<<MTOT, 256>>>(QKV + 2048, QKVSTR, AO, g1, be1, Hh);
    packA_h<<<dim3(DIM / 32, MTOT / 256), 256>>>(Hh, Hp, DIM);

    // FFN1: writes packed fp16 Gp directly
    gemm_pk<1, 1><<<dim3(FFD / 128, MTOT / 256), 256, GPSMEM>>>(
        (const float4*)Hp, (const float4*)pW1, b1, (float*)Gp, FFD, DIM);
    // FFN2
    gemm_pk<0, 0><<<dim3(DIM / 128, MTOT / 256), 256, GPSMEM>>>(
        (const float4*)Gp, (const float4*)pW2, b2, F, DIM, FFD);

    add_ln_kernel<<<MTOT, 256>>>(Hh, DIM, F, g2, be2, out);
}

// round 13
// speedup vs baseline: 2.2884x; 1.1083x over previous
#include <cuda_runtime.h>
#include <cuda_fp16.h>
#include <math.h>
#include <stdint.h>

#define MTOT 8192      // n * T = 4 * 2048
#define DIM 1024
#define FFD 4096
#define TT 2048
#define NBATCH 4
#define NHEAD 16
#define HDIM 64
#define QKVSTR 3072

// ---------------- scratch (no allocs allowed) ----------------
__device__ __half g_Xp[MTOT * DIM];        // packed concat(kq,v), fp16 (A layout)
__device__ float  g_QKV[MTOT * QKVSTR];    // fused K|Q|V output (cols 0:K,1024:Q,2048:V)
__device__ float  g_AO[MTOT * DIM];
__device__ float  g_H [MTOT * DIM];        // after LN1 (fp32, normal layout)
__device__ __half g_Hp[MTOT * DIM];        // packed H (A layout, fp16)
__device__ __half g_Gp[MTOT * FFD];        // packed gelu out (A layout, fp16)
__device__ float  g_F [MTOT * DIM];
__device__ __half g_Wp[3 * DIM * DIM + 2 * FFD * DIM];  // packed weights (B layout, fp16)
__device__ float  g_bqkv[QKVSTR];

// ---------------- helpers ----------------
// fp16 m16n8k16 mma (fp32 accum)
__device__ __forceinline__ void mma16(float* c, const unsigned* a, const unsigned* b) {
    asm volatile(
        "mma.sync.aligned.m16n8k16.row.col.f32.f16.f16.f32 "
        "{%0,%1,%2,%3}, {%4,%5,%6,%7}, {%8,%9}, {%0,%1,%2,%3};\n"
        : "+f"(c[0]), "+f"(c[1]), "+f"(c[2]), "+f"(c[3])
        : "r"(a[0]), "r"(a[1]), "r"(a[2]), "r"(a[3]), "r"(b[0]), "r"(b[1]));
}

__device__ __forceinline__ float h2f(float a, float b) {
    __half2 h = __floats2half2_rn(a, b);
    return __uint_as_float(*reinterpret_cast<unsigned*>(&h));
}
__device__ __forceinline__ unsigned h2u(float a, float b) {
    __half2 h = __floats2half2_rn(a, b);
    return *reinterpret_cast<unsigned*>(&h);
}

__device__ __forceinline__ uint32_t smem_u32(const void* p) {
    uint32_t a;
    asm("{ .reg .u64 t; cvta.to.shared.u64 t, %1; cvt.u32.u64 %0, t; }" : "=r"(a) : "l"(p));
    return a;
}
__device__ __forceinline__ void cp16(uint32_t dst, const void* src) {
    asm volatile("cp.async.cg.shared.global [%0], [%1], 16;" :: "r"(dst), "l"(src));
}

// ---------------- pack kernels (fp16 quad layout) ----------------
#define TSTR 36

__global__ void packA_h(const float* __restrict__ src, __half* __restrict__ dst, int K) {
    __shared__ float T[256 * TSTR];
    const int kt = blockIdx.x, mt = blockIdx.y, tid = threadIdx.x;
    const int NKt = K >> 5;
#pragma unroll
    for (int i = 0; i < 8; i++) {
        int idx = tid + 256 * i;
        int row = idx >> 3, q = idx & 7;
        float4 v = ((const float4*)(src + (size_t)(mt * 256 + row) * K + kt * 32))[q];
        *(float4*)&T[row * TSTR + q * 4] = v;
    }
    __syncthreads();
    float4* d4 = (float4*)dst + (size_t)(mt * NKt + kt) * 1024;
#pragma unroll
    for (int j = 0; j < 4; j++) {
        int d = tid + 256 * j;
        int slot = d & 7, mblk = (d >> 3) & 15, tg = (d >> 7) & 3, ks = d >> 9;
        int gp = (slot - 2 * tg) & 7;
        int m = mblk * 16 + gp, k = ks * 16 + 2 * tg;
        float4 o;
        o.x = h2f(T[m * TSTR + k],           T[m * TSTR + k + 1]);
        o.y = h2f(T[(m + 8) * TSTR + k],     T[(m + 8) * TSTR + k + 1]);
        o.z = h2f(T[m * TSTR + k + 8],       T[m * TSTR + k + 9]);
        o.w = h2f(T[(m + 8) * TSTR + k + 8], T[(m + 8) * TSTR + k + 9]);
        d4[d] = o;
    }
}

__global__ void packA_concat_h(const float* __restrict__ kq, const float* __restrict__ vv,
                               __half* __restrict__ dst) {
    __shared__ float T[256 * TSTR];
    const int kt = blockIdx.x, mt = blockIdx.y, tid = threadIdx.x;
    const float* src = (kt < 16) ? kq : vv;
    const int kof = (kt < 16) ? kt * 32 : (kt - 16) * 32;
#pragma unroll
    for (int i = 0; i < 8; i++) {
        int idx = tid + 256 * i;
        int row = idx >> 3, q = idx & 7;
        float4 v = ((const float4*)(src + (size_t)(mt * 256 + row) * 512 + kof))[q];
        *(float4*)&T[row * TSTR + q * 4] = v;
    }
    __syncthreads();
    float4* d4 = (float4*)dst + (size_t)(mt * 32 + kt) * 1024;
#pragma unroll
    for (int j = 0; j < 4; j++) {
        int d = tid + 256 * j;
        int slot = d & 7, mblk = (d >> 3) & 15, tg = (d >> 7) & 3, ks = d >> 9;
        int gp = (slot - 2 * tg) & 7;
        int m = mblk * 16 + gp, k = ks * 16 + 2 * tg;
        float4 o;
        o.x = h2f(T[m * TSTR + k],           T[m * TSTR + k + 1]);
        o.y = h2f(T[(m + 8) * TSTR + k],     T[(m + 8) * TSTR + k + 1]);
        o.z = h2f(T[m * TSTR + k + 8],       T[m * TSTR + k + 9]);
        o.w = h2f(T[(m + 8) * TSTR + k + 8], T[(m + 8) * TSTR + k + 9]);
        d4[d] = o;
    }
}

__global__ void packB_h(const float* __restrict__ src, __half* __restrict__ dst, int K) {
    __shared__ float T[128 * TSTR];
    const int kt = blockIdx.x, nt = blockIdx.y, tid = threadIdx.x;
    const int NKt = K >> 5;
#pragma unroll
    for (int i = 0; i < 4; i++) {
        int idx = tid + 256 * i;
        int row = idx >> 3, q = idx & 7;
        float4 v = ((const float4*)(src + (size_t)(nt * 128 + row) * K + kt * 32))[q];
        *(float4*)&T[row * TSTR + q * 4] = v;
    }
    __syncthreads();
    float4* d4 = (float4*)dst + (size_t)(nt * NKt + kt) * 512;
#pragma unroll
    for (int j = 0; j < 2; j++) {
        int d = tid + 256 * j;
        int slot = d & 7, nblk = (d >> 3) & 7, tg = (d >> 6) & 3, ks = d >> 8;
        int gp = (slot - 2 * tg) & 7;
        int n = nblk * 16 + gp, k = ks * 16 + 2 * tg;
        float4 o;
        o.x = h2f(T[n * TSTR + k],           T[n * TSTR + k + 1]);
        o.y = h2f(T[n * TSTR + k + 8],       T[n * TSTR + k + 9]);
        o.z = h2f(T[(n + 8) * TSTR + k],     T[(n + 8) * TSTR + k + 1]);
        o.w = h2f(T[(n + 8) * TSTR + k + 8], T[(n + 8) * TSTR + k + 9]);
        d4[d] = o;
    }
}

__global__ void biascat(const float* __restrict__ bk, const float* __restrict__ bq,
                        const float* __restrict__ bv, float* __restrict__ dst) {
    int i = blockIdx.x * 256 + threadIdx.x;
    dst[i] = (i < 1024) ? bk[i] : (i < 2048 ? bq[i - 1024] : bv[i - 2048]);
}

// ---------------- packed fp16 GEMM, cp.async 4-stage pipeline ----------------
#define STGB 24576
#define GPSMEM (4 * STGB)

template<int GELU, int PACKOUT>
__global__ void __launch_bounds__(256, 1) gemm_pk(
    const float4* __restrict__ Apk, const float4* __restrict__ Bpk,
    const float* __restrict__ bias, float* __restrict__ C,
    int N, int K)
{
    extern __shared__ float4 s4[];
    const int tid  = threadIdx.x;
    const int lane = tid & 31;
    const int warp = tid >> 5;
    const int g    = lane >> 2;
    const int tg   = lane & 3;
    const int wm   = (warp & 3) * 64;
    const int wn   = (warp >> 2) * 64;
    const int mt   = blockIdx.y;
    const int nt   = blockIdx.x;
    const int sgc  = (g + 2 * tg) & 7;
    const int NKt  = K >> 5;
    const uint32_t sbase = smem_u32(s4);

    float acc[4][8][4];
#pragma unroll
    for (int i = 0; i < 4; i++)
#pragma unroll
        for (int j = 0; j < 8; j++)
#pragma unroll
            for (int q = 0; q < 4; q++) acc[i][j][q] = 0.f;

#define FILLP(s, c) do { \
    const float4* As_ = Apk + ((size_t)mt * NKt + (c)) * 1024 + tid * 4; \
    const float4* Bs_ = Bpk + ((size_t)nt * NKt + (c)) * 512 + tid * 2; \
    uint32_t da_ = sbase + (s) * STGB + tid * 64; \
    uint32_t db_ = sbase + (s) * STGB + 16384 + tid * 32; \
    cp16(da_,      As_);     cp16(da_ + 16, As_ + 1); \
    cp16(da_ + 32, As_ + 2); cp16(da_ + 48, As_ + 3); \
    cp16(db_,      Bs_);     cp16(db_ + 16, Bs_ + 1); \
} while (0)

    FILLP(0, 0); asm volatile("cp.async.commit_group;" ::: "memory");
    FILLP(1, 1); asm volatile("cp.async.commit_group;" ::: "memory");
    FILLP(2, 2); asm volatile("cp.async.commit_group;" ::: "memory");

    for (int c = 0; c < NKt; c++) {
        asm volatile("cp.async.wait_group 2;" ::: "memory");
        __syncthreads();

        const float4* sa = s4 + (c & 3) * 1536;
        const float4* sb = sa + 1024;
#pragma unroll
        for (int ks = 0; ks < 2; ks++) {
            unsigned af[4][4], bf[8][2];
#pragma unroll
            for (int mi = 0; mi < 4; mi++) {
                float4 a4 = sa[ks * 512 + tg * 128 + ((wm >> 4) + mi) * 8 + sgc];
                af[mi][0] = __float_as_uint(a4.x);
                af[mi][1] = __float_as_uint(a4.y);
                af[mi][2] = __float_as_uint(a4.z);
                af[mi][3] = __float_as_uint(a4.w);
            }
#pragma unroll
            for (int j = 0; j < 4; j++) {
                float4 b4 = sb[ks * 256 + tg * 64 + ((wn >> 4) + j) * 8 + sgc];
                bf[2 * j][0]     = __float_as_uint(b4.x);
                bf[2 * j][1]     = __float_as_uint(b4.y);
                bf[2 * j + 1][0] = __float_as_uint(b4.z);
                bf[2 * j + 1][1] = __float_as_uint(b4.w);
            }
#pragma unroll
            for (int mi = 0; mi < 4; mi++)
#pragma unroll
                for (int ni = 0; ni < 8; ni++)
                    mma16(acc[mi][ni], af[mi], bf[ni]);
        }

        if (c + 3 < NKt) FILLP((c + 3) & 3, c + 3);
        asm volatile("cp.async.commit_group;" ::: "memory");
    }
#undef FILLP

    const int bm = mt * 256, bn = nt * 128;

    if (!PACKOUT) {
#pragma unroll
        for (int ni = 0; ni < 8; ni++) {
            int n = bn + wn + ni * 8 + tg * 2;
            float b0 = bias[n], b1 = bias[n + 1];
#pragma unroll
            for (int mi = 0; mi < 4; mi++) {
                int m = bm + wm + mi * 16 + g;
                float v00 = acc[mi][ni][0] + b0;
                float v01 = acc[mi][ni][1] + b1;
                float v10 = acc[mi][ni][2] + b0;
                float v11 = acc[mi][ni][3] + b1;
                if (GELU) {
                    v00 = 0.5f * v00 * (1.f + erff(v00 * 0.7071067811865476f));
                    v01 = 0.5f * v01 * (1.f + erff(v01 * 0.7071067811865476f));
                    v10 = 0.5f * v10 * (1.f + erff(v10 * 0.7071067811865476f));
                    v11 = 0.5f * v11 * (1.f + erff(v11 * 0.7071067811865476f));
                }
                *(float2*)&C[(size_t)m * N + n] = make_float2(v00, v01);
                *(float2*)&C[(size_t)(m + 8) * N + n] = make_float2(v10, v11);
            }
        }
    } else {
        asm volatile("cp.async.wait_group 0;" ::: "memory");
        float* Cs = (float*)s4;
        const int NKo = N >> 5;
        float4* d4 = (float4*)C;
        for (int hf = 0; hf < 2; hf++) {
            __syncthreads();
            if ((warp >> 2) == hf) {
#pragma unroll
                for (int ni = 0; ni < 8; ni++) {
                    int ncol = ni * 8 + tg * 2;
                    int n = bn + hf * 64 + ncol;
                    float b0 = bias[n], b1 = bias[n + 1];
#pragma unroll
                    for (int mi = 0; mi < 4; mi++) {
                        int mr = wm + mi * 16 + g;
                        float v00 = acc[mi][ni][0] + b0;
                        float v01 = acc[mi][ni][1] + b1;
                        float v10 = acc[mi][ni][2] + b0;
                        float v11 = acc[mi][ni][3] + b1;
                        if (GELU) {
                            v00 = 0.5f * v00 * (1.f + erff(v00 * 0.7071067811865476f));
                            v01 = 0.5f * v01 * (1.f + erff(v01 * 0.7071067811865476f));
                            v10 = 0.5f * v10 * (1.f + erff(v10 * 0.7071067811865476f));
                            v11 = 0.5f * v11 * (1.f + erff(v11 * 0.7071067811865476f));
                        }
                        Cs[mr * 65 + ncol] = v00;
                        Cs[mr * 65 + ncol + 1] = v01;
                        Cs[(mr + 8) * 65 + ncol] = v10;
                        Cs[(mr + 8) * 65 + ncol + 1] = v11;
                    }
                }
            }
            __syncthreads();
#pragma unroll
            for (int t = 0; t < 8; t++) {
                int e = tid + 256 * t;
                int ktl = e >> 10, d = e & 1023;
                int slot = d & 7, mblk = (d >> 3) & 15, tgg = (d >> 7) & 3, ks = d >> 9;
                int gp = (slot - 2 * tgg) & 7;
                int m = mblk * 16 + gp;
                int col = ktl * 32 + ks * 16 + 2 * tgg;
                int ktg = ((bn + hf * 64) >> 5) + ktl;
                float4 o;
                o.x = h2f(Cs[m * 65 + col],           Cs[m * 65 + col + 1]);
                o.y = h2f(Cs[(m + 8) * 65 + col],     Cs[(m + 8) * 65 + col + 1]);
                o.z = h2f(Cs[m * 65 + col + 8],       Cs[m * 65 + col + 9]);
                o.w = h2f(Cs[(m + 8) * 65 + col + 8], Cs[(m + 8) * 65 + col + 9]);
                d4[((size_t)mt * NKo + ktg) * 1024 + d] = o;
            }
        }
    }
}

// ---------------- attention: fp16 mma flash, causal, no scale ----------------
// 64 q-rows/block, 4 warps, kv tiles 64, d=64, m16n8k16.
// smem: K B-quads 8KB | V B-quads 8KB | Q A-quads 8KB | P half2 rows 9216B
#define PS2 36                       // uint stride per P row
#define SMEM_ATTN (24576 + 64 * PS2 * 4)

__global__ void __launch_bounds__(128, 3) attn_mma(
    const float* __restrict__ QKV, float* __restrict__ AO)
{
    extern __shared__ char smc[];
    float4*   Ks4 = (float4*)smc;
    __half*   Vh  = (__half*)(smc + 8192);
    float4*   Vs4 = (float4*)(smc + 8192);
    unsigned* Qu  = (unsigned*)(smc + 16384);
    float4*   Qs4 = (float4*)(smc + 16384);
    unsigned* Ku  = (unsigned*)smc;
    unsigned* Pu  = (unsigned*)(smc + 24576);

    const int qb = blockIdx.x, h = blockIdx.y, b = blockIdx.z;
    const int tid = threadIdx.x;
    const int warp = tid >> 5, lane = tid & 31;
    const int g = lane >> 2, tg = lane & 3;
    const int sgc = (g + 2 * tg) & 7;
    const int qw0 = warp * 16;
    const size_t ib = ((size_t)b * TT) * QKVSTR + (size_t)h * HDIM;
    const size_t ob = ((size_t)b * TT) * DIM + (size_t)h * HDIM;
    const int q0 = qb * 64;

    // Q producer: A-quads (m=q row, k=d)
    for (int t = tid; t < 512; t += 128) {
        int row = t & 63, ch = t >> 6;
        const float* src = QKV + 1024 + ib + (size_t)(q0 + row) * QKVSTR + ch * 8;
        float4 v0 = *(const float4*)src, v1 = *(const float4*)(src + 4);
        float a[8] = {v0.x, v0.y, v0.z, v0.w, v1.x, v1.y, v1.z, v1.w};
        int ks = ch >> 1, d8 = ch & 1;
        int mblk = row >> 4, gp = row & 7, hsel = (row >> 3) & 1;
#pragma unroll
        for (int t2 = 0; t2 < 4; t2++) {
            int quad = ks * 128 + t2 * 32 + mblk * 8 + ((gp + 2 * t2) & 7);
            Qu[quad * 4 + hsel + 2 * d8] = h2u(a[2 * t2], a[2 * t2 + 1]);
        }
    }
    __syncthreads();

    // persistent Q fragments
    unsigned qf[4][4];
#pragma unroll
    for (int ks = 0; ks < 4; ks++) {
        float4 a4 = Qs4[ks * 128 + tg * 32 + warp * 8 + sgc];
        qf[ks][0] = __float_as_uint(a4.x);
        qf[ks][1] = __float_as_uint(a4.y);
        qf[ks][2] = __float_as_uint(a4.z);
        qf[ks][3] = __float_as_uint(a4.w);
    }

    float o[8][4];
#pragma unroll
    for (int ni = 0; ni < 8; ni++)
#pragma unroll
        for (int q = 0; q < 4; q++) o[ni][q] = 0.f;
    float m0 = -INFINITY, m1 = -INFINITY, l0 = 0.f, l1 = 0.f;

    for (int jb = 0; jb <= qb; jb++) {
        __syncthreads();
        const int k0 = jb * 64;
        // K producer: B-quads (n=kv row, k=d)
        for (int t = tid; t < 512; t += 128) {
            int row = t & 63, ch = t >> 6;
            const float* src = QKV + ib + (size_t)(k0 + row) * QKVSTR + ch * 8;
            float4 v0 = *(const float4*)src, v1 = *(const float4*)(src + 4);
            float a[8] = {v0.x, v0.y, v0.z, v0.w, v1.x, v1.y, v1.z, v1.w};
            int ks = ch >> 1, d8 = ch & 1;
            int nblk = row >> 4, gp = row & 7, hsel = (row >> 3) & 1;
#pragma unroll
            for (int t2 = 0; t2 < 4; t2++) {
                int quad = ks * 128 + t2 * 32 + nblk * 8 + ((gp + 2 * t2) & 7);
                Ku[quad * 4 + d8 + 2 * hsel] = h2u(a[2 * t2], a[2 * t2 + 1]);
            }
        }
        // V producer: B-quads (n=d, k=kv row) — scalar half scatter
        for (int t = tid; t < 512; t += 128) {
            int row = t & 63, ch = t >> 6;
            const float* src = QKV + 2048 + ib + (size_t)(k0 + row) * QKVSTR + ch * 8;
            float4 v0 = *(const float4*)src, v1 = *(const float4*)(src + 4);
            float a[8] = {v0.x, v0.y, v0.z, v0.w, v1.x, v1.y, v1.z, v1.w};
            int ks = row >> 4, rr = row & 15;
            int tgv = (rr & 7) >> 1, d1 = row & 1, d8 = (rr >> 3) & 1;
            int nblk = ch >> 1, hsel = ch & 1;
            int he = d1 + 2 * d8 + 4 * hsel;
#pragma unroll
            for (int e = 0; e < 8; e++) {
                int quad = ks * 128 + tgv * 32 + nblk * 8 + ((e + 2 * tgv) & 7);
                Vh[quad * 8 + he] = __float2half(a[e]);
            }
        }
        __syncthreads();

        // S = Q K^T  (fp16 mma16: ks 0..3 x ni 0..7)
        float s[8][4];
#pragma unroll
        for (int ni = 0; ni < 8; ni++)
#pragma unroll
            for (int q = 0; q < 4; q++) s[ni][q] = 0.f;
#pragma unroll
        for (int ks = 0; ks < 4; ks++) {
#pragma unroll
            for (int j = 0; j < 4; j++) {
                float4 b4 = Ks4[ks * 128 + tg * 32 + j * 8 + sgc];
                unsigned blo[2] = {__float_as_uint(b4.x), __float_as_uint(b4.y)};
                unsigned bhi[2] = {__float_as_uint(b4.z), __float_as_uint(b4.w)};
                mma16(s[2 * j],     qf[ks], blo);
                mma16(s[2 * j + 1], qf[ks], bhi);
            }
        }

        if (jb == qb) {
#pragma unroll
            for (int ni = 0; ni < 8; ni++) {
                int c = ni * 8 + 2 * tg;
                if (c     > qw0 + g)     s[ni][0] = -INFINITY;
                if (c + 1 > qw0 + g)     s[ni][1] = -INFINITY;
                if (c     > qw0 + g + 8) s[ni][2] = -INFINITY;
                if (c + 1 > qw0 + g + 8) s[ni][3] = -INFINITY;
            }
        }

        float rx0 = -INFINITY, rx1 = -INFINITY;
#pragma unroll
        for (int ni = 0; ni < 8; ni++) {
            rx0 = fmaxf(rx0, fmaxf(s[ni][0], s[ni][1]));
            rx1 = fmaxf(rx1, fmaxf(s[ni][2], s[ni][3]));
        }
        rx0 = fmaxf(rx0, __shfl_xor_sync(0xffffffffu, rx0, 1));
        rx0 = fmaxf(rx0, __shfl_xor_sync(0xffffffffu, rx0, 2));
        rx1 = fmaxf(rx1, __shfl_xor_sync(0xffffffffu, rx1, 1));
        rx1 = fmaxf(rx1, __shfl_xor_sync(0xffffffffu, rx1, 2));

        float mn0 = fmaxf(m0, rx0), mn1 = fmaxf(m1, rx1);
        float al0 = __expf(m0 - mn0), al1 = __expf(m1 - mn1);
        float ps0 = 0.f, ps1 = 0.f;
#pragma unroll
        for (int ni = 0; ni < 8; ni++) {
            float p0 = __expf(s[ni][0] - mn0);
            float p1 = __expf(s[ni][1] - mn0);
            float p2 = __expf(s[ni][2] - mn1);
            float p3 = __expf(s[ni][3] - mn1);
            // store P as half2 (rounding applied by conversion)
            Pu[(qw0 + g) * PS2 + 4 * ni + tg]     = h2u(p0, p1);
            Pu[(qw0 + g + 8) * PS2 + 4 * ni + tg] = h2u(p2, p3);
            ps0 += __half2float(__low2half(*(__half2*)&Pu[0])) * 0.f + p0 + p1;  // keep fp32 sum of unrounded
            ps1 += p2 + p3;
        }
        // NOTE: sums above use unrounded p (fp32) — tiny mismatch vs rounded P*V is ~1e-3 relative on l? Use rounded:
        // (recompute sums from rounded halves for consistency)
        ps0 = 0.f; ps1 = 0.f;
#pragma unroll
        for (int ni = 0; ni < 8; ni++) {
            __half2 lo = *(__half2*)&Pu[(qw0 + g) * PS2 + 4 * ni + tg];
            __half2 hi = *(__half2*)&Pu[(qw0 + g + 8) * PS2 + 4 * ni + tg];
            ps0 += __half2float(__low2half(lo)) + __half2float(__high2half(lo));
            ps1 += __half2float(__low2half(hi)) + __half2float(__high2half(hi));
        }
        ps0 += __shfl_xor_sync(0xffffffffu, ps0, 1);
        ps0 += __shfl_xor_sync(0xffffffffu, ps0, 2);
        ps1 += __shfl_xor_sync(0xffffffffu, ps1, 1);
        ps1 += __shfl_xor_sync(0xffffffffu, ps1, 2);
        l0 = l0 * al0 + ps0;
        l1 = l1 * al1 + ps1;
        m0 = mn0; m1 = mn1;
#pragma unroll
        for (int ni = 0; ni < 8; ni++) {
            o[ni][0] *= al0; o[ni][1] *= al0;
            o[ni][2] *= al1; o[ni][3] *= al1;
        }
        __syncwarp();

        // O += P V  (fp16 mma16)
#pragma unroll
        for (int ks = 0; ks < 4; ks++) {
            unsigned pf[4];
            pf[0] = Pu[(qw0 + g) * PS2 + 8 * ks + tg];
            pf[1] = Pu[(qw0 + g + 8) * PS2 + 8 * ks + tg];
            pf[2] = Pu[(qw0 + g) * PS2 + 8 * ks + tg + 4];
            pf[3] = Pu[(qw0 + g + 8) * PS2 + 8 * ks + tg + 4];
#pragma unroll
            for (int j = 0; j < 4; j++) {
                float4 b4 = Vs4[ks * 128 + tg * 32 + j * 8 + sgc];
                unsigned blo[2] = {__float_as_uint(b4.x), __float_as_uint(b4.y)};
                unsigned bhi[2] = {__float_as_uint(b4.z), __float_as_uint(b4.w)};
                mma16(o[2 * j],     pf, blo);
                mma16(o[2 * j + 1], pf, bhi);
            }
        }
    }

    float i0 = 1.f / l0, i1 = 1.f / l1;
#pragma unroll
    for (int ni = 0; ni < 8; ni++) {
        size_t r0 = ob + (size_t)(q0 + qw0 + g) * DIM + ni * 8 + 2 * tg;
        size_t r1 = ob + (size_t)(q0 + qw0 + g + 8) * DIM + ni * 8 + 2 * tg;
        *(float2*)&AO[r0] = make_float2(o[ni][0] * i0, o[ni][1] * i0);
        *(float2*)&AO[r1] = make_float2(o[ni][2] * i1, o[ni][3] * i1);
    }
}

// ---------------- fused add + LayerNorm (row = 1024; A has stride strideA) ---------
__global__ void __launch_bounds__(256) add_ln_kernel(
    const float* __restrict__ A, int strideA, const float* __restrict__ B,
    const float* __restrict__ g, const float* __restrict__ beta,
    float* __restrict__ out)
{
    const int row = blockIdx.x;
    const float* a = A + (size_t)row * strideA;
    const float* b = B + (size_t)row * DIM;
    const int tid = threadIdx.x;

    float x[4];
    float s = 0.f, s2 = 0.f;
#pragma unroll
    for (int i = 0; i < 4; i++) {
        int c = tid + i * 256;
        x[i] = a[c] + b[c];
        s += x[i];
        s2 += x[i] * x[i];
    }
#pragma unroll
    for (int off = 16; off; off >>= 1) {
        s  += __shfl_down_sync(0xffffffffu, s,  off);
        s2 += __shfl_down_sync(0xffffffffu, s2, off);
    }
    __shared__ float ss[8], ss2[8];
    __shared__ float s_mean, s_inv;
    int w = tid >> 5;
    if ((tid & 31) == 0) { ss[w] = s; ss2[w] = s2; }
    __syncthreads();
    if (tid == 0) {
        float S = 0.f, S2 = 0.f;
#pragma unroll
        for (int i = 0; i < 8; i++) { S += ss[i]; S2 += ss2[i]; }
        float mu = S * (1.f / DIM);
        float var = S2 * (1.f / DIM) - mu * mu;
        s_mean = mu;
        s_inv = rsqrtf(var + 1e-5f);
    }
    __syncthreads();
    float mu = s_mean, iv = s_inv;
#pragma unroll
    for (int i = 0; i < 4; i++) {
        int c = tid + i * 256;
        out[(size_t)row * DIM + c] = (x[i] - mu) * iv * g[c] + beta[c];
    }
}

// ---------------- host ----------------
extern "C" void kernel_launch(void* const* d_in, const int* in_sizes, int n_in,
                              void* d_out, int out_size)
{
    const float* kq  = (const float*)d_in[0];
    const float* v   = (const float*)d_in[1];
    const float* Wk  = (const float*)d_in[2];
    const float* bk  = (const float*)d_in[3];
    const float* Wq  = (const float*)d_in[4];
    const float* bq  = (const float*)d_in[5];
    const float* Wv  = (const float*)d_in[6];
    const float* bv  = (const float*)d_in[7];
    const float* W1  = (const float*)d_in[8];
    const float* b1  = (const float*)d_in[9];
    const float* W2  = (const float*)d_in[10];
    const float* b2  = (const float*)d_in[11];
    const float* g1  = (const float*)d_in[12];
    const float* be1 = (const float*)d_in[13];
    const float* g2  = (const float*)d_in[14];
    const float* be2 = (const float*)d_in[15];
    float* out = (float*)d_out;

    __half *Xp, *Hp, *Gp, *Wp;
    float *QKV, *AO, *Hh, *F, *bqkv;
    cudaGetSymbolAddress((void**)&Xp,  g_Xp);
    cudaGetSymbolAddress((void**)&QKV, g_QKV);
    cudaGetSymbolAddress((void**)&AO,  g_AO);
    cudaGetSymbolAddress((void**)&Hh,  g_H);
    cudaGetSymbolAddress((void**)&Hp,  g_Hp);
    cudaGetSymbolAddress((void**)&Gp,  g_Gp);
    cudaGetSymbolAddress((void**)&F,   g_F);
    cudaGetSymbolAddress((void**)&Wp,  g_Wp);
    cudaGetSymbolAddress((void**)&bqkv, g_bqkv);

    __half* pW1 = Wp + 3 * DIM * DIM;
    __half* pW2 = Wp + 3 * DIM * DIM + (size_t)FFD * DIM;

    cudaFuncSetAttribute(gemm_pk<0, 0>, cudaFuncAttributeMaxDynamicSharedMemorySize, GPSMEM);
    cudaFuncSetAttribute(gemm_pk<1, 1>, cudaFuncAttributeMaxDynamicSharedMemorySize, GPSMEM);
    cudaFuncSetAttribute(attn_mma, cudaFuncAttributeMaxDynamicSharedMemorySize, SMEM_ATTN);

    // pack inputs (fp16)
    packA_concat_h<<<dim3(DIM / 32, MTOT / 256), 256>>>(kq, v, Xp);
    packB_h<<<dim3(DIM / 32, DIM / 128), 256>>>(Wk, Wp, DIM);
    packB_h<<<dim3(DIM / 32, DIM / 128), 256>>>(Wq, Wp + DIM * DIM, DIM);
    packB_h<<<dim3(DIM / 32, DIM / 128), 256>>>(Wv, Wp + 2 * DIM * DIM, DIM);
    packB_h<<<dim3(DIM / 32, FFD / 128), 256>>>(W1, pW1, DIM);
    packB_h<<<dim3(FFD / 32, DIM / 128), 256>>>(W2, pW2, FFD);
    biascat<<<QKVSTR / 256, 256>>>(bk, bq, bv, bqkv);

    // fused QKV GEMM
    gemm_pk<0, 0><<<dim3(QKVSTR / 128, MTOT / 256), 256, GPSMEM>>>(
        (const float4*)Xp, (const float4*)Wp, bqkv, QKV, QKVSTR, DIM);

    attn_mma<<<dim3(TT / 64, NHEAD, NBATCH), 128, SMEM_ATTN>>>(QKV, AO);

    add_ln_kernel<<<MTOT, 256>>>(QKV + 2048, QKVSTR, AO, g1, be1, Hh);
    packA_h<<<dim3(DIM / 32, MTOT / 256), 256>>>(Hh, Hp, DIM);

    gemm_pk<1, 1><<<dim3(FFD / 128, MTOT / 256), 256, GPSMEM>>>(
        (const float4*)Hp, (const float4*)pW1, b1, (float*)Gp, FFD, DIM);
    gemm_pk<0, 0><<<dim3(DIM / 128, MTOT / 256), 256, GPSMEM>>>(
        (const float4*)Gp, (const float4*)pW2, b2, F, DIM, FFD);

    add_ln_kernel<<<MTOT, 256>>>(Hh, DIM, F, g2, be2, out);
}

// round 14
// speedup vs baseline: 2.5199x; 1.1011x over previous
#include <cuda_runtime.h>
#include <cuda_fp16.h>
#include <math.h>
#include <stdint.h>

#define MTOT 8192      // n * T = 4 * 2048
#define DIM 1024
#define FFD 4096
#define TT 2048
#define NBATCH 4
#define NHEAD 16
#define HDIM 64
#define QKVSTR 3072

// ---------------- scratch (no allocs allowed) ----------------
__device__ __half g_Xp[MTOT * DIM];        // packed concat(kq,v), fp16 (A layout)
__device__ __half g_QKVh[MTOT * QKVSTR];   // fused K|Q|V output, fp16 (cols 0:K,1024:Q,2048:V)
__device__ float  g_Vres[MTOT * DIM];      // fp32 V projection (LN1 residual)
__device__ float  g_AO[MTOT * DIM];
__device__ float  g_H [MTOT * DIM];        // after LN1 (fp32, normal layout)
__device__ __half g_Hp[MTOT * DIM];        // packed H (A layout, fp16)
__device__ __half g_Gp[MTOT * FFD];        // packed gelu out (A layout, fp16)
__device__ float  g_F [MTOT * DIM];
__device__ __half g_Wp[3 * DIM * DIM + 2 * FFD * DIM];  // packed weights (B layout, fp16)
__device__ float  g_bqkv[QKVSTR];

// ---------------- helpers ----------------
__device__ __forceinline__ void mma16(float* c, const unsigned* a, const unsigned* b) {
    asm volatile(
        "mma.sync.aligned.m16n8k16.row.col.f32.f16.f16.f32 "
        "{%0,%1,%2,%3}, {%4,%5,%6,%7}, {%8,%9}, {%0,%1,%2,%3};\n"
        : "+f"(c[0]), "+f"(c[1]), "+f"(c[2]), "+f"(c[3])
        : "r"(a[0]), "r"(a[1]), "r"(a[2]), "r"(a[3]), "r"(b[0]), "r"(b[1]));
}

__device__ __forceinline__ float h2f(float a, float b) {
    __half2 h = __floats2half2_rn(a, b);
    return __uint_as_float(*reinterpret_cast<unsigned*>(&h));
}
__device__ __forceinline__ unsigned h2u(float a, float b) {
    __half2 h = __floats2half2_rn(a, b);
    return *reinterpret_cast<unsigned*>(&h);
}

__device__ __forceinline__ uint32_t smem_u32(const void* p) {
    uint32_t a;
    asm("{ .reg .u64 t; cvta.to.shared.u64 t, %1; cvt.u32.u64 %0, t; }" : "=r"(a) : "l"(p));
    return a;
}
__device__ __forceinline__ void cp16(uint32_t dst, const void* src) {
    asm volatile("cp.async.cg.shared.global [%0], [%1], 16;" :: "r"(dst), "l"(src));
}

// ---------------- pack kernels (fp16 quad layout) ----------------
#define TSTR 36

__global__ void packA_h(const float* __restrict__ src, __half* __restrict__ dst, int K) {
    __shared__ float T[256 * TSTR];
    const int kt = blockIdx.x, mt = blockIdx.y, tid = threadIdx.x;
    const int NKt = K >> 5;
#pragma unroll
    for (int i = 0; i < 8; i++) {
        int idx = tid + 256 * i;
        int row = idx >> 3, q = idx & 7;
        float4 v = ((const float4*)(src + (size_t)(mt * 256 + row) * K + kt * 32))[q];
        *(float4*)&T[row * TSTR + q * 4] = v;
    }
    __syncthreads();
    float4* d4 = (float4*)dst + (size_t)(mt * NKt + kt) * 1024;
#pragma unroll
    for (int j = 0; j < 4; j++) {
        int d = tid + 256 * j;
        int slot = d & 7, mblk = (d >> 3) & 15, tg = (d >> 7) & 3, ks = d >> 9;
        int gp = (slot - 2 * tg) & 7;
        int m = mblk * 16 + gp, k = ks * 16 + 2 * tg;
        float4 o;
        o.x = h2f(T[m * TSTR + k],           T[m * TSTR + k + 1]);
        o.y = h2f(T[(m + 8) * TSTR + k],     T[(m + 8) * TSTR + k + 1]);
        o.z = h2f(T[m * TSTR + k + 8],       T[m * TSTR + k + 9]);
        o.w = h2f(T[(m + 8) * TSTR + k + 8], T[(m + 8) * TSTR + k + 9]);
        d4[d] = o;
    }
}

__global__ void packA_concat_h(const float* __restrict__ kq, const float* __restrict__ vv,
                               __half* __restrict__ dst) {
    __shared__ float T[256 * TSTR];
    const int kt = blockIdx.x, mt = blockIdx.y, tid = threadIdx.x;
    const float* src = (kt < 16) ? kq : vv;
    const int kof = (kt < 16) ? kt * 32 : (kt - 16) * 32;
#pragma unroll
    for (int i = 0; i < 8; i++) {
        int idx = tid + 256 * i;
        int row = idx >> 3, q = idx & 7;
        float4 v = ((const float4*)(src + (size_t)(mt * 256 + row) * 512 + kof))[q];
        *(float4*)&T[row * TSTR + q * 4] = v;
    }
    __syncthreads();
    float4* d4 = (float4*)dst + (size_t)(mt * 32 + kt) * 1024;
#pragma unroll
    for (int j = 0; j < 4; j++) {
        int d = tid + 256 * j;
        int slot = d & 7, mblk = (d >> 3) & 15, tg = (d >> 7) & 3, ks = d >> 9;
        int gp = (slot - 2 * tg) & 7;
        int m = mblk * 16 + gp, k = ks * 16 + 2 * tg;
        float4 o;
        o.x = h2f(T[m * TSTR + k],           T[m * TSTR + k + 1]);
        o.y = h2f(T[(m + 8) * TSTR + k],     T[(m + 8) * TSTR + k + 1]);
        o.z = h2f(T[m * TSTR + k + 8],       T[m * TSTR + k + 9]);
        o.w = h2f(T[(m + 8) * TSTR + k + 8], T[(m + 8) * TSTR + k + 9]);
        d4[d] = o;
    }
}

__global__ void packB_h(const float* __restrict__ src, __half* __restrict__ dst, int K) {
    __shared__ float T[128 * TSTR];
    const int kt = blockIdx.x, nt = blockIdx.y, tid = threadIdx.x;
    const int NKt = K >> 5;
#pragma unroll
    for (int i = 0; i < 4; i++) {
        int idx = tid + 256 * i;
        int row = idx >> 3, q = idx & 7;
        float4 v = ((const float4*)(src + (size_t)(nt * 128 + row) * K + kt * 32))[q];
        *(float4*)&T[row * TSTR + q * 4] = v;
    }
    __syncthreads();
    float4* d4 = (float4*)dst + (size_t)(nt * NKt + kt) * 512;
#pragma unroll
    for (int j = 0; j < 2; j++) {
        int d = tid + 256 * j;
        int slot = d & 7, nblk = (d >> 3) & 7, tg = (d >> 6) & 3, ks = d >> 8;
        int gp = (slot - 2 * tg) & 7;
        int n = nblk * 16 + gp, k = ks * 16 + 2 * tg;
        float4 o;
        o.x = h2f(T[n * TSTR + k],           T[n * TSTR + k + 1]);
        o.y = h2f(T[n * TSTR + k + 8],       T[n * TSTR + k + 9]);
        o.z = h2f(T[(n + 8) * TSTR + k],     T[(n + 8) * TSTR + k + 1]);
        o.w = h2f(T[(n + 8) * TSTR + k + 8], T[(n + 8) * TSTR + k + 9]);
        d4[d] = o;
    }
}

__global__ void biascat(const float* __restrict__ bk, const float* __restrict__ bq,
                        const float* __restrict__ bv, float* __restrict__ dst) {
    int i = blockIdx.x * 256 + threadIdx.x;
    dst[i] = (i < 1024) ? bk[i] : (i < 2048 ? bq[i - 1024] : bv[i - 2048]);
}

// ---------------- packed fp16 GEMM, cp.async 4-stage pipeline ----------------
// OUTH=1: write fp16 output (half2 pairs); cols >= 2048 also copied fp32 to V32.
#define STGB 24576
#define GPSMEM (4 * STGB)

template<int GELU, int PACKOUT, int OUTH>
__global__ void __launch_bounds__(256, 1) gemm_pk(
    const float4* __restrict__ Apk, const float4* __restrict__ Bpk,
    const float* __restrict__ bias, float* __restrict__ C,
    float* __restrict__ V32, int N, int K)
{
    extern __shared__ float4 s4[];
    const int tid  = threadIdx.x;
    const int lane = tid & 31;
    const int warp = tid >> 5;
    const int g    = lane >> 2;
    const int tg   = lane & 3;
    const int wm   = (warp & 3) * 64;
    const int wn   = (warp >> 2) * 64;
    const int mt   = blockIdx.y;
    const int nt   = blockIdx.x;
    const int sgc  = (g + 2 * tg) & 7;
    const int NKt  = K >> 5;
    const uint32_t sbase = smem_u32(s4);

    float acc[4][8][4];
#pragma unroll
    for (int i = 0; i < 4; i++)
#pragma unroll
        for (int j = 0; j < 8; j++)
#pragma unroll
            for (int q = 0; q < 4; q++) acc[i][j][q] = 0.f;

#define FILLP(s, c) do { \
    const float4* As_ = Apk + ((size_t)mt * NKt + (c)) * 1024 + tid * 4; \
    const float4* Bs_ = Bpk + ((size_t)nt * NKt + (c)) * 512 + tid * 2; \
    uint32_t da_ = sbase + (s) * STGB + tid * 64; \
    uint32_t db_ = sbase + (s) * STGB + 16384 + tid * 32; \
    cp16(da_,      As_);     cp16(da_ + 16, As_ + 1); \
    cp16(da_ + 32, As_ + 2); cp16(da_ + 48, As_ + 3); \
    cp16(db_,      Bs_);     cp16(db_ + 16, Bs_ + 1); \
} while (0)

    FILLP(0, 0); asm volatile("cp.async.commit_group;" ::: "memory");
    FILLP(1, 1); asm volatile("cp.async.commit_group;" ::: "memory");
    FILLP(2, 2); asm volatile("cp.async.commit_group;" ::: "memory");

    for (int c = 0; c < NKt; c++) {
        asm volatile("cp.async.wait_group 2;" ::: "memory");
        __syncthreads();

        const float4* sa = s4 + (c & 3) * 1536;
        const float4* sb = sa + 1024;
#pragma unroll
        for (int ks = 0; ks < 2; ks++) {
            unsigned af[4][4], bf[8][2];
#pragma unroll
            for (int mi = 0; mi < 4; mi++) {
                float4 a4 = sa[ks * 512 + tg * 128 + ((wm >> 4) + mi) * 8 + sgc];
                af[mi][0] = __float_as_uint(a4.x);
                af[mi][1] = __float_as_uint(a4.y);
                af[mi][2] = __float_as_uint(a4.z);
                af[mi][3] = __float_as_uint(a4.w);
            }
#pragma unroll
            for (int j = 0; j < 4; j++) {
                float4 b4 = sb[ks * 256 + tg * 64 + ((wn >> 4) + j) * 8 + sgc];
                bf[2 * j][0]     = __float_as_uint(b4.x);
                bf[2 * j][1]     = __float_as_uint(b4.y);
                bf[2 * j + 1][0] = __float_as_uint(b4.z);
                bf[2 * j + 1][1] = __float_as_uint(b4.w);
            }
#pragma unroll
            for (int mi = 0; mi < 4; mi++)
#pragma unroll
                for (int ni = 0; ni < 8; ni++)
                    mma16(acc[mi][ni], af[mi], bf[ni]);
        }

        if (c + 3 < NKt) FILLP((c + 3) & 3, c + 3);
        asm volatile("cp.async.commit_group;" ::: "memory");
    }
#undef FILLP

    const int bm = mt * 256, bn = nt * 128;

    if (OUTH) {
        __half* Ch = (__half*)C;
#pragma unroll
        for (int ni = 0; ni < 8; ni++) {
            int n = bn + wn + ni * 8 + tg * 2;
            float b0 = bias[n], b1 = bias[n + 1];
            const bool isv = (n >= 2048);
#pragma unroll
            for (int mi = 0; mi < 4; mi++) {
                int m = bm + wm + mi * 16 + g;
                float v00 = acc[mi][ni][0] + b0;
                float v01 = acc[mi][ni][1] + b1;
                float v10 = acc[mi][ni][2] + b0;
                float v11 = acc[mi][ni][3] + b1;
                __half2 lo = __floats2half2_rn(v00, v01);
                __half2 hi = __floats2half2_rn(v10, v11);
                *(__half2*)&Ch[(size_t)m * N + n] = lo;
                *(__half2*)&Ch[(size_t)(m + 8) * N + n] = hi;
                if (isv) {
                    *(float2*)&V32[(size_t)m * DIM + n - 2048] = make_float2(v00, v01);
                    *(float2*)&V32[(size_t)(m + 8) * DIM + n - 2048] = make_float2(v10, v11);
                }
            }
        }
    } else if (!PACKOUT) {
#pragma unroll
        for (int ni = 0; ni < 8; ni++) {
            int n = bn + wn + ni * 8 + tg * 2;
            float b0 = bias[n], b1 = bias[n + 1];
#pragma unroll
            for (int mi = 0; mi < 4; mi++) {
                int m = bm + wm + mi * 16 + g;
                float v00 = acc[mi][ni][0] + b0;
                float v01 = acc[mi][ni][1] + b1;
                float v10 = acc[mi][ni][2] + b0;
                float v11 = acc[mi][ni][3] + b1;
                if (GELU) {
                    v00 = 0.5f * v00 * (1.f + erff(v00 * 0.7071067811865476f));
                    v01 = 0.5f * v01 * (1.f + erff(v01 * 0.7071067811865476f));
                    v10 = 0.5f * v10 * (1.f + erff(v10 * 0.7071067811865476f));
                    v11 = 0.5f * v11 * (1.f + erff(v11 * 0.7071067811865476f));
                }
                *(float2*)&C[(size_t)m * N + n] = make_float2(v00, v01);
                *(float2*)&C[(size_t)(m + 8) * N + n] = make_float2(v10, v11);
            }
        }
    } else {
        asm volatile("cp.async.wait_group 0;" ::: "memory");
        float* Cs = (float*)s4;
        const int NKo = N >> 5;
        float4* d4 = (float4*)C;
        for (int hf = 0; hf < 2; hf++) {
            __syncthreads();
            if ((warp >> 2) == hf) {
#pragma unroll
                for (int ni = 0; ni < 8; ni++) {
                    int ncol = ni * 8 + tg * 2;
                    int n = bn + hf * 64 + ncol;
                    float b0 = bias[n], b1 = bias[n + 1];
#pragma unroll
                    for (int mi = 0; mi < 4; mi++) {
                        int mr = wm + mi * 16 + g;
                        float v00 = acc[mi][ni][0] + b0;
                        float v01 = acc[mi][ni][1] + b1;
                        float v10 = acc[mi][ni][2] + b0;
                        float v11 = acc[mi][ni][3] + b1;
                        if (GELU) {
                            v00 = 0.5f * v00 * (1.f + erff(v00 * 0.7071067811865476f));
                            v01 = 0.5f * v01 * (1.f + erff(v01 * 0.7071067811865476f));
                            v10 = 0.5f * v10 * (1.f + erff(v10 * 0.7071067811865476f));
                            v11 = 0.5f * v11 * (1.f + erff(v11 * 0.7071067811865476f));
                        }
                        Cs[mr * 65 + ncol] = v00;
                        Cs[mr * 65 + ncol + 1] = v01;
                        Cs[(mr + 8) * 65 + ncol] = v10;
                        Cs[(mr + 8) * 65 + ncol + 1] = v11;
                    }
                }
            }
            __syncthreads();
#pragma unroll
            for (int t = 0; t < 8; t++) {
                int e = tid + 256 * t;
                int ktl = e >> 10, d = e & 1023;
                int slot = d & 7, mblk = (d >> 3) & 15, tgg = (d >> 7) & 3, ks = d >> 9;
                int gp = (slot - 2 * tgg) & 7;
                int m = mblk * 16 + gp;
                int col = ktl * 32 + ks * 16 + 2 * tgg;
                int ktg = ((bn + hf * 64) >> 5) + ktl;
                float4 o;
                o.x = h2f(Cs[m * 65 + col],           Cs[m * 65 + col + 1]);
                o.y = h2f(Cs[(m + 8) * 65 + col],     Cs[(m + 8) * 65 + col + 1]);
                o.z = h2f(Cs[m * 65 + col + 8],       Cs[m * 65 + col + 9]);
                o.w = h2f(Cs[(m + 8) * 65 + col + 8], Cs[(m + 8) * 65 + col + 9]);
                d4[((size_t)mt * NKo + ktg) * 1024 + d] = o;
            }
        }
    }
}

// ---------------- attention: fp16 mma flash, causal, no scale ----------------
// Reads fp16 QKV (row stride 3072 halves). 64 q-rows/block, 4 warps, m16n8k16.
#define PS2 36
#define SMEM_ATTN (24576 + 64 * PS2 * 4)

__global__ void __launch_bounds__(128, 3) attn_mma(
    const __half* __restrict__ QKV, float* __restrict__ AO)
{
    extern __shared__ char smc[];
    float4*   Ks4 = (float4*)smc;
    __half*   Vh  = (__half*)(smc + 8192);
    float4*   Vs4 = (float4*)(smc + 8192);
    unsigned* Qu  = (unsigned*)(smc + 16384);
    float4*   Qs4 = (float4*)(smc + 16384);
    unsigned* Ku  = (unsigned*)smc;
    unsigned* Pu  = (unsigned*)(smc + 24576);

    const int qb = blockIdx.x, h = blockIdx.y, b = blockIdx.z;
    const int tid = threadIdx.x;
    const int warp = tid >> 5, lane = tid & 31;
    const int g = lane >> 2, tg = lane & 3;
    const int sgc = (g + 2 * tg) & 7;
    const int qw0 = warp * 16;
    const size_t ib = ((size_t)b * TT) * QKVSTR + (size_t)h * HDIM;
    const size_t ob = ((size_t)b * TT) * DIM + (size_t)h * HDIM;
    const int q0 = qb * 64;

    // Q producer: A-quads from fp16 source (no conversion)
    for (int t = tid; t < 512; t += 128) {
        int row = t & 63, ch = t >> 6;
        const __half* src = QKV + 1024 + ib + (size_t)(q0 + row) * QKVSTR + ch * 8;
        uint4 u = *(const uint4*)src;
        unsigned p[4] = {u.x, u.y, u.z, u.w};
        int ks = ch >> 1, d8 = ch & 1;
        int mblk = row >> 4, gp = row & 7, hsel = (row >> 3) & 1;
#pragma unroll
        for (int t2 = 0; t2 < 4; t2++) {
            int quad = ks * 128 + t2 * 32 + mblk * 8 + ((gp + 2 * t2) & 7);
            Qu[quad * 4 + hsel + 2 * d8] = p[t2];
        }
    }
    __syncthreads();

    unsigned qf[4][4];
#pragma unroll
    for (int ks = 0; ks < 4; ks++) {
        float4 a4 = Qs4[ks * 128 + tg * 32 + warp * 8 + sgc];
        qf[ks][0] = __float_as_uint(a4.x);
        qf[ks][1] = __float_as_uint(a4.y);
        qf[ks][2] = __float_as_uint(a4.z);
        qf[ks][3] = __float_as_uint(a4.w);
    }

    float o[8][4];
#pragma unroll
    for (int ni = 0; ni < 8; ni++)
#pragma unroll
        for (int q = 0; q < 4; q++) o[ni][q] = 0.f;
    float m0 = -INFINITY, m1 = -INFINITY, l0 = 0.f, l1 = 0.f;

    for (int jb = 0; jb <= qb; jb++) {
        __syncthreads();
        const int k0 = jb * 64;
        // K producer
        for (int t = tid; t < 512; t += 128) {
            int row = t & 63, ch = t >> 6;
            const __half* src = QKV + ib + (size_t)(k0 + row) * QKVSTR + ch * 8;
            uint4 u = *(const uint4*)src;
            unsigned p[4] = {u.x, u.y, u.z, u.w};
            int ks = ch >> 1, d8 = ch & 1;
            int nblk = row >> 4, gp = row & 7, hsel = (row >> 3) & 1;
#pragma unroll
            for (int t2 = 0; t2 < 4; t2++) {
                int quad = ks * 128 + t2 * 32 + nblk * 8 + ((gp + 2 * t2) & 7);
                Ku[quad * 4 + d8 + 2 * hsel] = p[t2];
            }
        }
        // V producer (half scatter, no conversion)
        for (int t = tid; t < 512; t += 128) {
            int row = t & 63, ch = t >> 6;
            const __half* src = QKV + 2048 + ib + (size_t)(k0 + row) * QKVSTR + ch * 8;
            uint4 u = *(const uint4*)src;
            const __half* ah = (const __half*)&u;
            int ks = row >> 4, rr = row & 15;
            int tgv = (rr & 7) >> 1, d1 = row & 1, d8 = (rr >> 3) & 1;
            int nblk = ch >> 1, hsel = ch & 1;
            int he = d1 + 2 * d8 + 4 * hsel;
#pragma unroll
            for (int e = 0; e < 8; e++) {
                int quad = ks * 128 + tgv * 32 + nblk * 8 + ((e + 2 * tgv) & 7);
                Vh[quad * 8 + he] = ah[e];
            }
        }
        __syncthreads();

        float s[8][4];
#pragma unroll
        for (int ni = 0; ni < 8; ni++)
#pragma unroll
            for (int q = 0; q < 4; q++) s[ni][q] = 0.f;
#pragma unroll
        for (int ks = 0; ks < 4; ks++) {
#pragma unroll
            for (int j = 0; j < 4; j++) {
                float4 b4 = Ks4[ks * 128 + tg * 32 + j * 8 + sgc];
                unsigned blo[2] = {__float_as_uint(b4.x), __float_as_uint(b4.y)};
                unsigned bhi[2] = {__float_as_uint(b4.z), __float_as_uint(b4.w)};
                mma16(s[2 * j],     qf[ks], blo);
                mma16(s[2 * j + 1], qf[ks], bhi);
            }
        }

        if (jb == qb) {
#pragma unroll
            for (int ni = 0; ni < 8; ni++) {
                int c = ni * 8 + 2 * tg;
                if (c     > qw0 + g)     s[ni][0] = -INFINITY;
                if (c + 1 > qw0 + g)     s[ni][1] = -INFINITY;
                if (c     > qw0 + g + 8) s[ni][2] = -INFINITY;
                if (c + 1 > qw0 + g + 8) s[ni][3] = -INFINITY;
            }
        }

        float rx0 = -INFINITY, rx1 = -INFINITY;
#pragma unroll
        for (int ni = 0; ni < 8; ni++) {
            rx0 = fmaxf(rx0, fmaxf(s[ni][0], s[ni][1]));
            rx1 = fmaxf(rx1, fmaxf(s[ni][2], s[ni][3]));
        }
        rx0 = fmaxf(rx0, __shfl_xor_sync(0xffffffffu, rx0, 1));
        rx0 = fmaxf(rx0, __shfl_xor_sync(0xffffffffu, rx0, 2));
        rx1 = fmaxf(rx1, __shfl_xor_sync(0xffffffffu, rx1, 1));
        rx1 = fmaxf(rx1, __shfl_xor_sync(0xffffffffu, rx1, 2));

        float mn0 = fmaxf(m0, rx0), mn1 = fmaxf(m1, rx1);
        float al0 = __expf(m0 - mn0), al1 = __expf(m1 - mn1);
        float ps0 = 0.f, ps1 = 0.f;
#pragma unroll
        for (int ni = 0; ni < 8; ni++) {
            unsigned plo = h2u(__expf(s[ni][0] - mn0), __expf(s[ni][1] - mn0));
            unsigned phi = h2u(__expf(s[ni][2] - mn1), __expf(s[ni][3] - mn1));
            Pu[(qw0 + g) * PS2 + 4 * ni + tg]     = plo;
            Pu[(qw0 + g + 8) * PS2 + 4 * ni + tg] = phi;
            __half2 hl = *(__half2*)&plo;
            __half2 hh = *(__half2*)&phi;
            ps0 += __half2float(__low2half(hl)) + __half2float(__high2half(hl));
            ps1 += __half2float(__low2half(hh)) + __half2float(__high2half(hh));
        }
        ps0 += __shfl_xor_sync(0xffffffffu, ps0, 1);
        ps0 += __shfl_xor_sync(0xffffffffu, ps0, 2);
        ps1 += __shfl_xor_sync(0xffffffffu, ps1, 1);
        ps1 += __shfl_xor_sync(0xffffffffu, ps1, 2);
        l0 = l0 * al0 + ps0;
        l1 = l1 * al1 + ps1;
        m0 = mn0; m1 = mn1;
#pragma unroll
        for (int ni = 0; ni < 8; ni++) {
            o[ni][0] *= al0; o[ni][1] *= al0;
            o[ni][2] *= al1; o[ni][3] *= al1;
        }
        __syncwarp();

#pragma unroll
        for (int ks = 0; ks < 4; ks++) {
            unsigned pf[4];
            pf[0] = Pu[(qw0 + g) * PS2 + 8 * ks + tg];
            pf[1] = Pu[(qw0 + g + 8) * PS2 + 8 * ks + tg];
            pf[2] = Pu[(qw0 + g) * PS2 + 8 * ks + tg + 4];
            pf[3] = Pu[(qw0 + g + 8) * PS2 + 8 * ks + tg + 4];
#pragma unroll
            for (int j = 0; j < 4; j++) {
                float4 b4 = Vs4[ks * 128 + tg * 32 + j * 8 + sgc];
                unsigned blo[2] = {__float_as_uint(b4.x), __float_as_uint(b4.y)};
                unsigned bhi[2] = {__float_as_uint(b4.z), __float_as_uint(b4.w)};
                mma16(o[2 * j],     pf, blo);
                mma16(o[2 * j + 1], pf, bhi);
            }
        }
    }

    float i0 = 1.f / l0, i1 = 1.f / l1;
#pragma unroll
    for (int ni = 0; ni < 8; ni++) {
        size_t r0 = ob + (size_t)(q0 + qw0 + g) * DIM + ni * 8 + 2 * tg;
        size_t r1 = ob + (size_t)(q0 + qw0 + g + 8) * DIM + ni * 8 + 2 * tg;
        *(float2*)&AO[r0] = make_float2(o[ni][0] * i0, o[ni][1] * i0);
        *(float2*)&AO[r1] = make_float2(o[ni][2] * i1, o[ni][3] * i1);
    }
}

// ---------------- fused add + LayerNorm ----------------
__global__ void __launch_bounds__(256) add_ln_kernel(
    const float* __restrict__ A, int strideA, const float* __restrict__ B,
    const float* __restrict__ g, const float* __restrict__ beta,
    float* __restrict__ out)
{
    const int row = blockIdx.x;
    const float* a = A + (size_t)row * strideA;
    const float* b = B + (size_t)row * DIM;
    const int tid = threadIdx.x;

    float x[4];
    float s = 0.f, s2 = 0.f;
#pragma unroll
    for (int i = 0; i < 4; i++) {
        int c = tid + i * 256;
        x[i] = a[c] + b[c];
        s += x[i];
        s2 += x[i] * x[i];
    }
#pragma unroll
    for (int off = 16; off; off >>= 1) {
        s  += __shfl_down_sync(0xffffffffu, s,  off);
        s2 += __shfl_down_sync(0xffffffffu, s2, off);
    }
    __shared__ float ss[8], ss2[8];
    __shared__ float s_mean, s_inv;
    int w = tid >> 5;
    if ((tid & 31) == 0) { ss[w] = s; ss2[w] = s2; }
    __syncthreads();
    if (tid == 0) {
        float S = 0.f, S2 = 0.f;
#pragma unroll
        for (int i = 0; i < 8; i++) { S += ss[i]; S2 += ss2[i]; }
        float mu = S * (1.f / DIM);
        float var = S2 * (1.f / DIM) - mu * mu;
        s_mean = mu;
        s_inv = rsqrtf(var + 1e-5f);
    }
    __syncthreads();
    float mu = s_mean, iv = s_inv;
#pragma unroll
    for (int i = 0; i < 4; i++) {
        int c = tid + i * 256;
        out[(size_t)row * DIM + c] = (x[i] - mu) * iv * g[c] + beta[c];
    }
}

// ---------------- host ----------------
extern "C" void kernel_launch(void* const* d_in, const int* in_sizes, int n_in,
                              void* d_out, int out_size)
{
    const float* kq  = (const float*)d_in[0];
    const float* v   = (const float*)d_in[1];
    const float* Wk  = (const float*)d_in[2];
    const float* bk  = (const float*)d_in[3];
    const float* Wq  = (const float*)d_in[4];
    const float* bq  = (const float*)d_in[5];
    const float* Wv  = (const float*)d_in[6];
    const float* bv  = (const float*)d_in[7];
    const float* W1  = (const float*)d_in[8];
    const float* b1  = (const float*)d_in[9];
    const float* W2  = (const float*)d_in[10];
    const float* b2  = (const float*)d_in[11];
    const float* g1  = (const float*)d_in[12];
    const float* be1 = (const float*)d_in[13];
    const float* g2  = (const float*)d_in[14];
    const float* be2 = (const float*)d_in[15];
    float* out = (float*)d_out;

    __half *Xp, *QKVh, *Hp, *Gp, *Wp;
    float *Vres, *AO, *Hh, *F, *bqkv;
    cudaGetSymbolAddress((void**)&Xp,   g_Xp);
    cudaGetSymbolAddress((void**)&QKVh, g_QKVh);
    cudaGetSymbolAddress((void**)&Vres, g_Vres);
    cudaGetSymbolAddress((void**)&AO,   g_AO);
    cudaGetSymbolAddress((void**)&Hh,   g_H);
    cudaGetSymbolAddress((void**)&Hp,   g_Hp);
    cudaGetSymbolAddress((void**)&Gp,   g_Gp);
    cudaGetSymbolAddress((void**)&F,    g_F);
    cudaGetSymbolAddress((void**)&Wp,   g_Wp);
    cudaGetSymbolAddress((void**)&bqkv, g_bqkv);

    __half* pW1 = Wp + 3 * DIM * DIM;
    __half* pW2 = Wp + 3 * DIM * DIM + (size_t)FFD * DIM;

    cudaFuncSetAttribute(gemm_pk<0, 0, 0>, cudaFuncAttributeMaxDynamicSharedMemorySize, GPSMEM);
    cudaFuncSetAttribute(gemm_pk<1, 1, 0>, cudaFuncAttributeMaxDynamicSharedMemorySize, GPSMEM);
    cudaFuncSetAttribute(gemm_pk<0, 0, 1>, cudaFuncAttributeMaxDynamicSharedMemorySize, GPSMEM);
    cudaFuncSetAttribute(attn_mma, cudaFuncAttributeMaxDynamicSharedMemorySize, SMEM_ATTN);

    // pack inputs (fp16)
    packA_concat_h<<<dim3(DIM / 32, MTOT / 256), 256>>>(kq, v, Xp);
    packB_h<<<dim3(DIM / 32, DIM / 128), 256>>>(Wk, Wp, DIM);
    packB_h<<<dim3(DIM / 32, DIM / 128), 256>>>(Wq, Wp + DIM * DIM, DIM);
    packB_h<<<dim3(DIM / 32, DIM / 128), 256>>>(Wv, Wp + 2 * DIM * DIM, DIM);
    packB_h<<<dim3(DIM / 32, FFD / 128), 256>>>(W1, pW1, DIM);
    packB_h<<<dim3(FFD / 32, DIM / 128), 256>>>(W2, pW2, FFD);
    biascat<<<QKVSTR / 256, 256>>>(bk, bq, bv, bqkv);

    // fused QKV GEMM -> fp16 QKV + fp32 V slice
    gemm_pk<0, 0, 1><<<dim3(QKVSTR / 128, MTOT / 256), 256, GPSMEM>>>(
        (const float4*)Xp, (const float4*)Wp, bqkv, (float*)QKVh, Vres, QKVSTR, DIM);

    attn_mma<<<dim3(TT / 64, NHEAD, NBATCH), 128, SMEM_ATTN>>>(QKVh, AO);

    add_ln_kernel<<<MTOT, 256>>>(Vres, DIM, AO, g1, be1, Hh);
    packA_h<<<dim3(DIM / 32, MTOT / 256), 256>>>(Hh, Hp, DIM);

    gemm_pk<1, 1, 0><<<dim3(FFD / 128, MTOT / 256), 256, GPSMEM>>>(
        (const float4*)Hp, (const float4*)pW1, b1, (float*)Gp, nullptr, FFD, DIM);
    gemm_pk<0, 0, 0><<<dim3(DIM / 128, MTOT / 256), 256, GPSMEM>>>(
        (const float4*)Gp, (const float4*)pW2, b2, F, nullptr, DIM, FFD);

    add_ln_kernel<<<MTOT, 256>>>(Hh, DIM, F, g2, be2, out);
}